// round 2
// baseline (speedup 1.0000x reference)
#include <cuda_runtime.h>
#include <math.h>

#define NN 50000
#define NE 800000
#define NL 4
#define NG 64
#define EPS 1e-5f

// ---------------- static device scratch ----------------
__device__ __align__(16) float g_h[NN * 64];
__device__ __align__(16) float g_u[NN * 128];      // [h | aggr_h]
__device__ __align__(16) float g_un[NN * 64];
__device__ __align__(16) float g_pos[NN * 3];
__device__ __align__(16) float g_aggr_p[NN * 3];
__device__ __align__(16) float g_Hpre[(size_t)NN * 256];
__device__ __align__(16) float g_wpack[64 * 256];  // k-major [k][op]
__device__ __align__(16) float g_t1[(size_t)NE * 64];
__device__ __align__(16) float g_t2[(size_t)NE * 64];
__device__ __align__(16) float g_mlin[(size_t)NE * 64];
__device__ double g_sum[256];
__device__ double g_sumsq[256];
__device__ __align__(16) float g_bnA[256];
__device__ __align__(16) float g_bnB[256];
__device__ __align__(16) float g_pool[NG * 64];
__device__ float g_cnt[NG];

__device__ __forceinline__ float silu_f(float y) {
    return y * (1.0f / (1.0f + __expf(-y)));
}

__device__ __forceinline__ void red_add_v4(float* p, float a, float b, float c, float d) {
    asm volatile("red.global.add.v4.f32 [%0], {%1,%2,%3,%4};"
                 :: "l"(p), "f"(a), "f"(b), "f"(c), "f"(d) : "memory");
}

// ---------------- init: h = [node_s,node_type] @ W^T + b; copy pos; zero pool ----------------
__global__ void k_init(const float* __restrict__ ns, const float* __restrict__ nt,
                       const float* __restrict__ pos, const float* __restrict__ w,
                       const float* __restrict__ b)
{
    int idx = blockIdx.x * blockDim.x + threadIdx.x;
    if (idx < NG * 64) g_pool[idx] = 0.f;
    if (idx < NG) g_cnt[idx] = 0.f;
    if (idx >= NN * 64) return;
    int n = idx >> 6, o = idx & 63;
    const float* wr = w + o * 8;
    const float* s = ns + n * 6;
    float acc = b[o];
#pragma unroll
    for (int i = 0; i < 6; i++) acc = fmaf(s[i], wr[i], acc);
    acc = fmaf(nt[n * 2 + 0], wr[6], acc);
    acc = fmaf(nt[n * 2 + 1], wr[7], acc);
    g_h[idx] = acc;
    g_u[(size_t)n * 128 + o] = acc;
    if (o < 3) g_pos[n * 3 + o] = pos[n * 3 + o];
}

// ---------------- per-layer zero: aggr_h half of u, aggr_p, stats ----------------
__global__ void k_zero()
{
    int idx = blockIdx.x * blockDim.x + threadIdx.x;
    if (idx < 256) { g_sum[idx] = 0.0; g_sumsq[idx] = 0.0; }
    if (idx < NN * 3) g_aggr_p[idx] = 0.f;
    if (idx >= NN * 64) return;
    g_u[(size_t)(idx >> 6) * 128 + 64 + (idx & 63)] = 0.f;
}

// ---------------- pack h-columns of msg_w1/updc_w1, k-major [k][256] ----------------
// op: 0-63 msg-dst, 64-127 msg-src, 128-191 updc-dst, 192-255 updc-src
__global__ void k_wpack(const float* __restrict__ mw1, const float* __restrict__ cw1)
{
    int idx = blockIdx.x * blockDim.x + threadIdx.x;
    if (idx >= 64 * 256) return;
    int k = idx >> 8, op = idx & 255, o = op & 63;
    float v;
    if (op < 64)       v = mw1[o * 161 + k];
    else if (op < 128) v = mw1[o * 161 + 64 + k];
    else if (op < 192) v = cw1[o * 161 + k];
    else               v = cw1[o * 161 + 64 + k];
    g_wpack[k * 256 + op] = v;
}

// ---------------- Hpre(n, 256) = h(n,64) @ wpack^T, warp per node, 2 phases ----------------
__global__ void k_hpre()
{
    __shared__ __align__(16) float sW[64 * 128];   // 32KB
    int tid = threadIdx.x, lane = tid & 31, warp = tid >> 5;
    int node = blockIdx.x * 8 + warp;
    float h0 = 0.f, h1 = 0.f;
    if (node < NN) {
        h0 = g_h[node * 64 + lane];
        h1 = g_h[node * 64 + 32 + lane];
    }
    for (int p = 0; p < 2; p++) {
        __syncthreads();
        for (int i = tid; i < 64 * 128; i += 256)
            sW[i] = g_wpack[(i >> 7) * 256 + p * 128 + (i & 127)];
        __syncthreads();
        if (node < NN) {
            float a0 = 0.f, a1 = 0.f, a2 = 0.f, a3 = 0.f;
#pragma unroll
            for (int k = 0; k < 32; k++) {
                float hk = __shfl_sync(0xffffffffu, h0, k);
                const float* wr = &sW[k * 128];
                a0 = fmaf(hk, wr[lane], a0);      a1 = fmaf(hk, wr[32 + lane], a1);
                a2 = fmaf(hk, wr[64 + lane], a2); a3 = fmaf(hk, wr[96 + lane], a3);
            }
#pragma unroll
            for (int k = 0; k < 32; k++) {
                float hk = __shfl_sync(0xffffffffu, h1, k);
                const float* wr = &sW[(32 + k) * 128];
                a0 = fmaf(hk, wr[lane], a0);      a1 = fmaf(hk, wr[32 + lane], a1);
                a2 = fmaf(hk, wr[64 + lane], a2); a3 = fmaf(hk, wr[96 + lane], a3);
            }
            float* out = &g_Hpre[(size_t)node * 256 + p * 128];
            out[lane] = a0; out[32 + lane] = a1; out[64 + lane] = a2; out[96 + lane] = a3;
        }
    }
}

// ---------------- edge A: t1/t2 = Hpre[dst]+Hpre[src]+r*wr + edge_s@Wes + b; stats ----------------
__global__ void k_edgeA(const int* __restrict__ ei, const float* __restrict__ es,
                        const float* __restrict__ mw1, const float* __restrict__ mb1,
                        const float* __restrict__ cw1, const float* __restrict__ cb1)
{
    __shared__ __align__(16) float sWes[32 * 128]; // 16KB, [k][ch], ch<64 msg, >=64 updc
    __shared__ float sWr[128], sB[128];
    __shared__ float sS[8 * 128], sQ[8 * 128];
    int tid = threadIdx.x;
    for (int i = tid; i < 32 * 128; i += 256) {
        int k = i >> 7, ch = i & 127;
        sWes[i] = (ch < 64) ? mw1[ch * 161 + 129 + k] : cw1[(ch - 64) * 161 + 129 + k];
    }
    if (tid < 128) {
        sWr[tid] = (tid < 64) ? mw1[tid * 161 + 128] : cw1[(tid - 64) * 161 + 128];
        sB[tid]  = (tid < 64) ? mb1[tid]             : cb1[tid - 64];
    }
    __syncthreads();
    int lane = tid & 31, warp = tid >> 5;
    int ch0 = 4 * lane;                          // channels ch0..ch0+3 in [0,128)
    int dstoff = (lane < 16) ? ch0 : 64 + ch0;   // Hpre offset (dst part)
    int srcoff = (lane < 16) ? 64 + ch0 : 128 + ch0;
    float wr0 = sWr[ch0], wr1 = sWr[ch0 + 1], wr2 = sWr[ch0 + 2], wr3 = sWr[ch0 + 3];
    float bb0 = sB[ch0], bb1 = sB[ch0 + 1], bb2 = sB[ch0 + 2], bb3 = sB[ch0 + 3];
    float s0 = 0, s1 = 0, s2 = 0, s3 = 0, q0 = 0, q1 = 0, q2 = 0, q3 = 0;
    int nwarp = gridDim.x * 8;
    for (int e = blockIdx.x * 8 + warp; e < NE; e += nwarp) {
        int src = ei[e], dst = ei[NE + e];
        float dx = g_pos[dst * 3] - g_pos[src * 3];
        float dy = g_pos[dst * 3 + 1] - g_pos[src * 3 + 1];
        float dz = g_pos[dst * 3 + 2] - g_pos[src * 3 + 2];
        float r = sqrtf(dx * dx + dy * dy + dz * dz);
        float esv = es[(size_t)e * 32 + lane];
        float4 hd = *(const float4*)&g_Hpre[(size_t)dst * 256 + dstoff];
        float4 hs = *(const float4*)&g_Hpre[(size_t)src * 256 + srcoff];
        float a0 = hd.x + hs.x + r * wr0 + bb0;
        float a1 = hd.y + hs.y + r * wr1 + bb1;
        float a2 = hd.z + hs.z + r * wr2 + bb2;
        float a3 = hd.w + hs.w + r * wr3 + bb3;
#pragma unroll
        for (int k = 0; k < 32; k++) {
            float ek = __shfl_sync(0xffffffffu, esv, k);
            float4 w = *(const float4*)&sWes[k * 128 + ch0];
            a0 = fmaf(ek, w.x, a0); a1 = fmaf(ek, w.y, a1);
            a2 = fmaf(ek, w.z, a2); a3 = fmaf(ek, w.w, a3);
        }
        float* outp = (lane < 16) ? &g_t1[(size_t)e * 64 + ch0] : &g_t2[(size_t)e * 64 + ch0 - 64];
        *(float4*)outp = make_float4(a0, a1, a2, a3);
        s0 += a0; q0 += a0 * a0; s1 += a1; q1 += a1 * a1;
        s2 += a2; q2 += a2 * a2; s3 += a3; q3 += a3 * a3;
    }
    sS[warp * 128 + ch0] = s0; sS[warp * 128 + ch0 + 1] = s1;
    sS[warp * 128 + ch0 + 2] = s2; sS[warp * 128 + ch0 + 3] = s3;
    sQ[warp * 128 + ch0] = q0; sQ[warp * 128 + ch0 + 1] = q1;
    sQ[warp * 128 + ch0 + 2] = q2; sQ[warp * 128 + ch0 + 3] = q3;
    __syncthreads();
    if (tid < 128) {
        float ts = 0, tq = 0;
        for (int w = 0; w < 8; w++) { ts += sS[w * 128 + tid]; tq += sQ[w * 128 + tid]; }
        atomicAdd(&g_sum[tid], (double)ts);
        atomicAdd(&g_sumsq[tid], (double)tq);
    }
}

// ---------------- BN finalize: bnA/bnB from sums ----------------
__global__ void k_bnfin(int off, int n, double inv,
                        const float* __restrict__ g0, const float* __restrict__ b0,
                        const float* __restrict__ g1, const float* __restrict__ b1)
{
    int c = threadIdx.x;
    if (c >= n) return;
    double m = g_sum[off + c] * inv;
    double v = g_sumsq[off + c] * inv - m * m;
    float gg = (c < 64) ? g0[c] : g1[c - 64];
    float bb = (c < 64) ? b0[c] : b1[c - 64];
    float A = gg * rsqrtf((float)v + EPS);
    g_bnA[off + c] = A;
    g_bnB[off + c] = bb - (float)m * A;
}

// ---------------- edge B: mlin = silu(bn(t1)) @ msg_w2^T + b; coord head; stats ----------------
__global__ void k_edgeB(const int* __restrict__ ei,
                        const float* __restrict__ mw2, const float* __restrict__ mb2,
                        const float* __restrict__ cw2, const float* __restrict__ cb2)
{
    __shared__ __align__(16) float sW2[64 * 64];   // 16KB, k-major
    __shared__ float sWc[64];
    __shared__ float sS[8 * 64], sQ[8 * 64];
    int tid = threadIdx.x, lane = tid & 31, warp = tid >> 5;
    for (int i = tid; i < 64 * 64; i += 256) { int k = i >> 6, o = i & 63; sW2[i] = mw2[o * 64 + k]; }
    if (tid < 64) sWc[tid] = cw2[tid];
    __syncthreads();
    float A1a = g_bnA[lane], B1a = g_bnB[lane], A1b = g_bnA[32 + lane], B1b = g_bnB[32 + lane];
    float A2a = g_bnA[64 + lane], B2a = g_bnB[64 + lane], A2b = g_bnA[96 + lane], B2b = g_bnB[96 + lane];
    float wca = sWc[lane], wcb = sWc[32 + lane];
    float b2a = mb2[lane], b2b = mb2[32 + lane];
    float cbias = cb2[0];
    float s0 = 0, s1 = 0, q0 = 0, q1 = 0;
    int nwarp = gridDim.x * 8;
    for (int e = blockIdx.x * 8 + warp; e < NE; e += nwarp) {
        float xa = silu_f(fmaf(g_t1[(size_t)e * 64 + lane], A1a, B1a));
        float xb = silu_f(fmaf(g_t1[(size_t)e * 64 + 32 + lane], A1b, B1b));
        float y0 = b2a, y1 = b2b;
#pragma unroll
        for (int k = 0; k < 32; k++) {
            float xk = __shfl_sync(0xffffffffu, xa, k);
            y0 = fmaf(xk, sW2[k * 64 + lane], y0);
            y1 = fmaf(xk, sW2[k * 64 + 32 + lane], y1);
        }
#pragma unroll
        for (int k = 0; k < 32; k++) {
            float xk = __shfl_sync(0xffffffffu, xb, k);
            y0 = fmaf(xk, sW2[(32 + k) * 64 + lane], y0);
            y1 = fmaf(xk, sW2[(32 + k) * 64 + 32 + lane], y1);
        }
        g_mlin[(size_t)e * 64 + lane] = y0;
        g_mlin[(size_t)e * 64 + 32 + lane] = y1;
        s0 += y0; q0 += y0 * y0; s1 += y1; q1 += y1 * y1;
        // coord head
        float ca = silu_f(fmaf(g_t2[(size_t)e * 64 + lane], A2a, B2a));
        float cb = silu_f(fmaf(g_t2[(size_t)e * 64 + 32 + lane], A2b, B2b));
        float part = ca * wca + cb * wcb;
#pragma unroll
        for (int o = 16; o > 0; o >>= 1) part += __shfl_xor_sync(0xffffffffu, part, o);
        float sc = part + cbias;
        int src = ei[e], dst = ei[NE + e];
        if (lane < 3) {
            float dl = g_pos[dst * 3 + lane] - g_pos[src * 3 + lane];
            atomicAdd(&g_aggr_p[dst * 3 + lane], sc * dl);
        }
    }
    sS[warp * 64 + lane] = s0; sS[warp * 64 + 32 + lane] = s1;
    sQ[warp * 64 + lane] = q0; sQ[warp * 64 + 32 + lane] = q1;
    __syncthreads();
    if (tid < 64) {
        float ts = 0, tq = 0;
        for (int w = 0; w < 8; w++) { ts += sS[w * 64 + tid]; tq += sQ[w * 64 + tid]; }
        atomicAdd(&g_sum[128 + tid], (double)ts);
        atomicAdd(&g_sumsq[128 + tid], (double)tq);
    }
}

// ---------------- edge C: msg = silu(bn(mlin)); scatter-add to aggr_h half of u ----------------
__global__ void k_edgeC(const int* __restrict__ ei)
{
    int idx = blockIdx.x * blockDim.x + threadIdx.x;
    if (idx >= NE * 16) return;
    int e = idx >> 4, c4 = (idx & 15) * 4;
    int dst = ei[NE + e];
    float4 m = *(const float4*)&g_mlin[(size_t)e * 64 + c4];
    float4 A = *(const float4*)&g_bnA[128 + c4];
    float4 B = *(const float4*)&g_bnB[128 + c4];
    red_add_v4(&g_u[(size_t)dst * 128 + 64 + c4],
               silu_f(fmaf(m.x, A.x, B.x)), silu_f(fmaf(m.y, A.y, B.y)),
               silu_f(fmaf(m.z, A.z, B.z)), silu_f(fmaf(m.w, A.w, B.w)));
}

// ---------------- node 1: un = u(128) @ updf_w1^T + b; stats ----------------
__global__ void k_node1(const float* __restrict__ uw1, const float* __restrict__ ub1)
{
    __shared__ __align__(16) float sW[128 * 64];   // 32KB
    __shared__ float sS[8 * 64], sQ[8 * 64];
    int tid = threadIdx.x, lane = tid & 31, warp = tid >> 5;
    for (int i = tid; i < 128 * 64; i += 256) { int k = i >> 6, o = i & 63; sW[i] = uw1[o * 128 + k]; }
    __syncthreads();
    float bb0 = ub1[lane], bb1 = ub1[32 + lane];
    float s0 = 0, s1 = 0, q0 = 0, q1 = 0;
    int nwarp = gridDim.x * 8;
    for (int n = blockIdx.x * 8 + warp; n < NN; n += nwarp) {
        const float* up = &g_u[(size_t)n * 128];
        float u0 = up[lane], u1 = up[32 + lane], u2 = up[64 + lane], u3 = up[96 + lane];
        float y0 = bb0, y1 = bb1;
#pragma unroll
        for (int k = 0; k < 32; k++) {
            float xk = __shfl_sync(0xffffffffu, u0, k);
            y0 = fmaf(xk, sW[k * 64 + lane], y0); y1 = fmaf(xk, sW[k * 64 + 32 + lane], y1);
        }
#pragma unroll
        for (int k = 0; k < 32; k++) {
            float xk = __shfl_sync(0xffffffffu, u1, k);
            y0 = fmaf(xk, sW[(32 + k) * 64 + lane], y0); y1 = fmaf(xk, sW[(32 + k) * 64 + 32 + lane], y1);
        }
#pragma unroll
        for (int k = 0; k < 32; k++) {
            float xk = __shfl_sync(0xffffffffu, u2, k);
            y0 = fmaf(xk, sW[(64 + k) * 64 + lane], y0); y1 = fmaf(xk, sW[(64 + k) * 64 + 32 + lane], y1);
        }
#pragma unroll
        for (int k = 0; k < 32; k++) {
            float xk = __shfl_sync(0xffffffffu, u3, k);
            y0 = fmaf(xk, sW[(96 + k) * 64 + lane], y0); y1 = fmaf(xk, sW[(96 + k) * 64 + 32 + lane], y1);
        }
        g_un[n * 64 + lane] = y0;
        g_un[n * 64 + 32 + lane] = y1;
        s0 += y0; q0 += y0 * y0; s1 += y1; q1 += y1 * y1;
    }
    sS[warp * 64 + lane] = s0; sS[warp * 64 + 32 + lane] = s1;
    sQ[warp * 64 + lane] = q0; sQ[warp * 64 + 32 + lane] = q1;
    __syncthreads();
    if (tid < 64) {
        float ts = 0, tq = 0;
        for (int w = 0; w < 8; w++) { ts += sS[w * 64 + tid]; tq += sQ[w * 64 + tid]; }
        atomicAdd(&g_sum[192 + tid], (double)ts);
        atomicAdd(&g_sumsq[192 + tid], (double)tq);
    }
}

// ---------------- node 2: h += silu(bn(un)) @ updf_w2^T + b; pos += aggr_p ----------------
__global__ void k_node2(const float* __restrict__ uw2, const float* __restrict__ ub2)
{
    __shared__ __align__(16) float sW[64 * 64];
    int tid = threadIdx.x, lane = tid & 31, warp = tid >> 5;
    for (int i = tid; i < 64 * 64; i += 256) { int k = i >> 6, o = i & 63; sW[i] = uw2[o * 64 + k]; }
    __syncthreads();
    float A0 = g_bnA[192 + lane], B0 = g_bnB[192 + lane];
    float A1 = g_bnA[224 + lane], B1 = g_bnB[224 + lane];
    float bb0 = ub2[lane], bb1 = ub2[32 + lane];
    int nwarp = gridDim.x * 8;
    for (int n = blockIdx.x * 8 + warp; n < NN; n += nwarp) {
        float v0 = silu_f(fmaf(g_un[n * 64 + lane], A0, B0));
        float v1 = silu_f(fmaf(g_un[n * 64 + 32 + lane], A1, B1));
        float y0 = bb0, y1 = bb1;
#pragma unroll
        for (int k = 0; k < 32; k++) {
            float xk = __shfl_sync(0xffffffffu, v0, k);
            y0 = fmaf(xk, sW[k * 64 + lane], y0); y1 = fmaf(xk, sW[k * 64 + 32 + lane], y1);
        }
#pragma unroll
        for (int k = 0; k < 32; k++) {
            float xk = __shfl_sync(0xffffffffu, v1, k);
            y0 = fmaf(xk, sW[(32 + k) * 64 + lane], y0); y1 = fmaf(xk, sW[(32 + k) * 64 + 32 + lane], y1);
        }
        float h0 = g_h[n * 64 + lane] + y0;
        float h1 = g_h[n * 64 + 32 + lane] + y1;
        g_h[n * 64 + lane] = h0;
        g_h[n * 64 + 32 + lane] = h1;
        g_u[(size_t)n * 128 + lane] = h0;
        g_u[(size_t)n * 128 + 32 + lane] = h1;
        if (lane < 3) g_pos[n * 3 + lane] += g_aggr_p[n * 3 + lane];
    }
}

// ---------------- pooling ----------------
__global__ void k_pool(const int* __restrict__ batch)
{
    int idx = blockIdx.x * blockDim.x + threadIdx.x;
    if (idx >= NN * 16) return;
    int n = idx >> 4, c4 = (idx & 15) * 4;
    int b = batch[n];
    float4 h = *(const float4*)&g_h[n * 64 + c4];
    red_add_v4(&g_pool[b * 64 + c4], h.x, h.y, h.z, h.w);
    if (c4 == 0) atomicAdd(&g_cnt[b], 1.0f);
}

__global__ void k_pred(const float* __restrict__ w, const float* __restrict__ b,
                       float* __restrict__ out)
{
    int g = blockIdx.x, lane = threadIdx.x;
    float p = g_pool[g * 64 + lane] * w[lane] + g_pool[g * 64 + 32 + lane] * w[32 + lane];
#pragma unroll
    for (int o = 16; o > 0; o >>= 1) p += __shfl_xor_sync(0xffffffffu, p, o);
    if (lane == 0) out[g] = p / fmaxf(g_cnt[g], 1.0f) + b[0];
}

// ---------------- launch ----------------
extern "C" void kernel_launch(void* const* d_in, const int* in_sizes, int n_in,
                              void* d_out, int out_size)
{
    const float* node_s    = (const float*)d_in[0];
    const float* node_type = (const float*)d_in[1];
    const float* pos       = (const float*)d_in[2];
    const int*   ei        = (const int*)d_in[3];
    const float* edge_s    = (const float*)d_in[4];
    const int*   batch     = (const int*)d_in[5];
    const float* lin_in_w  = (const float*)d_in[6];
    const float* lin_in_b  = (const float*)d_in[7];
    const float* msg_w1    = (const float*)d_in[8];
    const float* msg_b1    = (const float*)d_in[9];
    const float* msg_g1    = (const float*)d_in[10];
    const float* msg_be1   = (const float*)d_in[11];
    const float* msg_w2    = (const float*)d_in[12];
    const float* msg_b2    = (const float*)d_in[13];
    const float* msg_g2    = (const float*)d_in[14];
    const float* msg_be2   = (const float*)d_in[15];
    const float* updf_w1   = (const float*)d_in[16];
    const float* updf_b1   = (const float*)d_in[17];
    const float* updf_g1   = (const float*)d_in[18];
    const float* updf_be1  = (const float*)d_in[19];
    const float* updf_w2   = (const float*)d_in[20];
    const float* updf_b2   = (const float*)d_in[21];
    const float* updc_w1   = (const float*)d_in[22];
    const float* updc_b1   = (const float*)d_in[23];
    const float* updc_g1   = (const float*)d_in[24];
    const float* updc_be1  = (const float*)d_in[25];
    const float* updc_w2   = (const float*)d_in[26];
    const float* updc_b2   = (const float*)d_in[27];
    const float* lin_pred_w = (const float*)d_in[28];
    const float* lin_pred_b = (const float*)d_in[29];

    k_init<<<(NN * 64 + 255) / 256, 256>>>(node_s, node_type, pos, lin_in_w, lin_in_b);

    for (int l = 0; l < NL; l++) {
        const float* mw1 = msg_w1 + (size_t)l * 64 * 161;
        const float* mb1 = msg_b1 + l * 64;
        const float* mw2 = msg_w2 + (size_t)l * 64 * 64;
        const float* mb2 = msg_b2 + l * 64;
        const float* cw1 = updc_w1 + (size_t)l * 64 * 161;
        const float* cb1 = updc_b1 + l * 64;
        const float* cw2 = updc_w2 + (size_t)l * 64;
        const float* cb2 = updc_b2 + l;
        const float* uw1 = updf_w1 + (size_t)l * 64 * 128;
        const float* ub1 = updf_b1 + l * 64;
        const float* uw2 = updf_w2 + (size_t)l * 64 * 64;
        const float* ub2 = updf_b2 + l * 64;

        k_zero<<<(NN * 64 + 255) / 256, 256>>>();
        k_wpack<<<(64 * 256 + 255) / 256, 256>>>(mw1, cw1);
        k_hpre<<<(NN + 7) / 8, 256>>>();
        k_edgeA<<<2048, 256>>>(ei, edge_s, mw1, mb1, cw1, cb1);
        k_bnfin<<<1, 128>>>(0, 128, 1.0 / NE,
                            msg_g1 + l * 64, msg_be1 + l * 64,
                            updc_g1 + l * 64, updc_be1 + l * 64);
        k_edgeB<<<2048, 256>>>(ei, mw2, mb2, cw2, cb2);
        k_bnfin<<<1, 64>>>(128, 64, 1.0 / NE,
                           msg_g2 + l * 64, msg_be2 + l * 64,
                           msg_g2 + l * 64, msg_be2 + l * 64);
        k_edgeC<<<(NE * 16 + 255) / 256, 256>>>(ei);
        k_node1<<<(NN + 7) / 8, 256>>>(uw1, ub1);
        k_bnfin<<<1, 64>>>(192, 64, 1.0 / NN,
                           updf_g1 + l * 64, updf_be1 + l * 64,
                           updf_g1 + l * 64, updf_be1 + l * 64);
        k_node2<<<(NN + 7) / 8, 256>>>(uw2, ub2);
    }

    k_pool<<<(NN * 16 + 255) / 256, 256>>>(batch);
    k_pred<<<NG, 32>>>(lin_pred_w, lin_pred_b, (float*)d_out);
}

// round 3
// speedup vs baseline: 1.3889x; 1.3889x over previous
#include <cuda_runtime.h>
#include <math.h>

#define NN 50000
#define NE 800000
#define NL 4
#define NG 64
#define EPS 1e-5f

// ---------------- static device scratch ----------------
__device__ __align__(16) float g_h[NN * 64];
__device__ __align__(16) float g_u[NN * 128];      // [h | aggr_h]
__device__ __align__(16) float g_un[NN * 64];
__device__ __align__(16) float g_pos[NN * 3];
__device__ __align__(16) float g_aggr_p[NN * 3];
__device__ __align__(16) float g_Hpre[(size_t)NN * 256];
__device__ __align__(16) float g_wpack[64 * 256];  // k-major [k][op]
__device__ __align__(16) float g_t1[(size_t)NE * 64];
__device__ __align__(16) float g_t2[(size_t)NE * 64];
__device__ __align__(16) float g_mlin[(size_t)NE * 64];
__device__ double g_sum[256];
__device__ double g_sumsq[256];
__device__ __align__(16) float g_bnA[256];
__device__ __align__(16) float g_bnB[256];
__device__ __align__(16) float g_pool[NG * 64];
__device__ float g_cnt[NG];

__device__ __forceinline__ float silu_f(float y) {
    return y * (1.0f / (1.0f + __expf(-y)));
}

__device__ __forceinline__ void red_add_v4(float* p, float a, float b, float c, float d) {
    asm volatile("red.global.add.v4.f32 [%0], {%1,%2,%3,%4};"
                 :: "l"(p), "f"(a), "f"(b), "f"(c), "f"(d) : "memory");
}

// ---------------- init ----------------
__global__ void k_init(const float* __restrict__ ns, const float* __restrict__ nt,
                       const float* __restrict__ pos, const float* __restrict__ w,
                       const float* __restrict__ b)
{
    int idx = blockIdx.x * blockDim.x + threadIdx.x;
    if (idx < NG * 64) g_pool[idx] = 0.f;
    if (idx < NG) g_cnt[idx] = 0.f;
    if (idx >= NN * 64) return;
    int n = idx >> 6, o = idx & 63;
    const float* wr = w + o * 8;
    const float* s = ns + n * 6;
    float acc = b[o];
#pragma unroll
    for (int i = 0; i < 6; i++) acc = fmaf(s[i], wr[i], acc);
    acc = fmaf(nt[n * 2 + 0], wr[6], acc);
    acc = fmaf(nt[n * 2 + 1], wr[7], acc);
    g_h[idx] = acc;
    g_u[(size_t)n * 128 + o] = acc;
    if (o < 3) g_pos[n * 3 + o] = pos[n * 3 + o];
}

// ---------------- per-layer zero ----------------
__global__ void k_zero()
{
    int idx = blockIdx.x * blockDim.x + threadIdx.x;
    if (idx < 256) { g_sum[idx] = 0.0; g_sumsq[idx] = 0.0; }
    if (idx < NN * 3) g_aggr_p[idx] = 0.f;
    if (idx >= NN * 64) return;
    g_u[(size_t)(idx >> 6) * 128 + 64 + (idx & 63)] = 0.f;
}

// ---------------- pack h-columns of msg_w1/updc_w1, k-major [k][256] ----------------
__global__ void k_wpack(const float* __restrict__ mw1, const float* __restrict__ cw1)
{
    int idx = blockIdx.x * blockDim.x + threadIdx.x;
    if (idx >= 64 * 256) return;
    int k = idx >> 8, op = idx & 255, o = op & 63;
    float v;
    if (op < 64)       v = mw1[o * 161 + k];
    else if (op < 128) v = mw1[o * 161 + 64 + k];
    else if (op < 192) v = cw1[o * 161 + k];
    else               v = cw1[o * 161 + 64 + k];
    g_wpack[k * 256 + op] = v;
}

// ---------------- Hpre: tiled GEMM 64n x 128o (2 phases), K=64 ----------------
__global__ __launch_bounds__(256) void k_hpre()
{
    __shared__ __align__(16) float sA[64][64];
    __shared__ __align__(16) float sB[64][128];
    int tid = threadIdx.x, tx = tid & 15, ty = tid >> 4;
    int ntiles = (NN + 63) >> 6;
    for (int t = blockIdx.x; t < ntiles; t += gridDim.x) {
        int n0 = t << 6;
        __syncthreads();
        {
            int nn = tid >> 2, k0 = (tid & 3) << 4;
            int n = n0 + nn;
#pragma unroll
            for (int m = 0; m < 4; m++) {
                float4 v = (n < NN) ? *(const float4*)&g_h[n * 64 + k0 + 4 * m]
                                    : make_float4(0.f, 0.f, 0.f, 0.f);
                sA[k0 + 4 * m + 0][nn] = v.x;
                sA[k0 + 4 * m + 1][nn] = v.y;
                sA[k0 + 4 * m + 2][nn] = v.z;
                sA[k0 + 4 * m + 3][nn] = v.w;
            }
        }
        for (int ph = 0; ph < 2; ph++) {
            __syncthreads();
#pragma unroll
            for (int r = 0; r < 8; r++) {
                int i = tid + r * 256;
                int k = i >> 5, o4 = (i & 31) << 2;
                *(float4*)&sB[k][o4] = *(const float4*)&g_wpack[k * 256 + ph * 128 + o4];
            }
            __syncthreads();
            float acc[4][8];
#pragma unroll
            for (int i = 0; i < 4; i++)
#pragma unroll
                for (int j = 0; j < 8; j++) acc[i][j] = 0.f;
#pragma unroll 4
            for (int k = 0; k < 64; k++) {
                float4 a = *(const float4*)&sA[k][tx << 2];
                float4 b0 = *(const float4*)&sB[k][ty << 3];
                float4 b1 = *(const float4*)&sB[k][(ty << 3) + 4];
                float av[4] = {a.x, a.y, a.z, a.w};
                float bv[8] = {b0.x, b0.y, b0.z, b0.w, b1.x, b1.y, b1.z, b1.w};
#pragma unroll
                for (int i = 0; i < 4; i++)
#pragma unroll
                    for (int j = 0; j < 8; j++) acc[i][j] = fmaf(av[i], bv[j], acc[i][j]);
            }
#pragma unroll
            for (int i = 0; i < 4; i++) {
                int n = n0 + (tx << 2) + i;
                if (n < NN) {
                    float* out = &g_Hpre[(size_t)n * 256 + ph * 128 + (ty << 3)];
                    *(float4*)out = make_float4(acc[i][0], acc[i][1], acc[i][2], acc[i][3]);
                    *(float4*)(out + 4) = make_float4(acc[i][4], acc[i][5], acc[i][6], acc[i][7]);
                }
            }
        }
    }
}

// ---------------- edge A: tiled, 64 edges x 128 ch, K=32 (edge_s) + gather init ----------------
__global__ __launch_bounds__(256) void k_edgeA(const int* __restrict__ ei, const float* __restrict__ es,
                                               const float* __restrict__ mw1, const float* __restrict__ mb1,
                                               const float* __restrict__ cw1, const float* __restrict__ cb1)
{
    __shared__ __align__(16) float sWes[32][128];
    __shared__ float sWr[128], sBias[128];
    __shared__ __align__(16) float sEs[32][68];
    __shared__ float sR[64];
    __shared__ int sSrc[64], sDst[64];
    __shared__ float sS[128], sQ[128];
    int tid = threadIdx.x, tx = tid & 15, ty = tid >> 4;
    for (int i = tid; i < 32 * 128; i += 256) {
        int k = i >> 7, ch = i & 127;
        sWes[k][ch] = (ch < 64) ? mw1[ch * 161 + 129 + k] : cw1[(ch - 64) * 161 + 129 + k];
    }
    if (tid < 128) {
        sWr[tid]  = (tid < 64) ? mw1[tid * 161 + 128] : cw1[(tid - 64) * 161 + 128];
        sBias[tid] = (tid < 64) ? mb1[tid] : cb1[tid - 64];
        sS[tid] = 0.f; sQ[tid] = 0.f;
    }
    __syncthreads();
    int ch0 = ty << 3;
    int dstoff = (ch0 < 64) ? ch0 : 64 + ch0;
    float wr[8], bb[8];
#pragma unroll
    for (int j = 0; j < 8; j++) { wr[j] = sWr[ch0 + j]; bb[j] = sBias[ch0 + j]; }
    float st[8], sq[8];
#pragma unroll
    for (int j = 0; j < 8; j++) { st[j] = 0.f; sq[j] = 0.f; }

    for (int t = blockIdx.x; t < NE / 64; t += gridDim.x) {
        int e0 = t << 6;
        __syncthreads();
        if (tid < 64) {
            int e = e0 + tid;
            int s = ei[e], d = ei[NE + e];
            sSrc[tid] = s; sDst[tid] = d;
            float dx = g_pos[d * 3] - g_pos[s * 3];
            float dy = g_pos[d * 3 + 1] - g_pos[s * 3 + 1];
            float dz = g_pos[d * 3 + 2] - g_pos[s * 3 + 2];
            sR[tid] = sqrtf(dx * dx + dy * dy + dz * dz);
        }
        {
            int el = tid >> 2, k0 = (tid & 3) << 3;
            const float* ep = &es[(size_t)(e0 + el) * 32 + k0];
            float4 v0 = *(const float4*)ep;
            float4 v1 = *(const float4*)(ep + 4);
            sEs[k0 + 0][el] = v0.x; sEs[k0 + 1][el] = v0.y;
            sEs[k0 + 2][el] = v0.z; sEs[k0 + 3][el] = v0.w;
            sEs[k0 + 4][el] = v1.x; sEs[k0 + 5][el] = v1.y;
            sEs[k0 + 6][el] = v1.z; sEs[k0 + 7][el] = v1.w;
        }
        __syncthreads();
        float acc[4][8];
#pragma unroll
        for (int i = 0; i < 4; i++) {
            int el = (tx << 2) + i;
            int d = sDst[el], s = sSrc[el];
            float r = sR[el];
            const float* hdp = &g_Hpre[(size_t)d * 256 + dstoff];
            const float* hsp = &g_Hpre[(size_t)s * 256 + dstoff + 64];
            float4 hd0 = *(const float4*)hdp;
            float4 hd1 = *(const float4*)(hdp + 4);
            float4 hs0 = *(const float4*)hsp;
            float4 hs1 = *(const float4*)(hsp + 4);
            acc[i][0] = hd0.x + hs0.x + fmaf(r, wr[0], bb[0]);
            acc[i][1] = hd0.y + hs0.y + fmaf(r, wr[1], bb[1]);
            acc[i][2] = hd0.z + hs0.z + fmaf(r, wr[2], bb[2]);
            acc[i][3] = hd0.w + hs0.w + fmaf(r, wr[3], bb[3]);
            acc[i][4] = hd1.x + hs1.x + fmaf(r, wr[4], bb[4]);
            acc[i][5] = hd1.y + hs1.y + fmaf(r, wr[5], bb[5]);
            acc[i][6] = hd1.z + hs1.z + fmaf(r, wr[6], bb[6]);
            acc[i][7] = hd1.w + hs1.w + fmaf(r, wr[7], bb[7]);
        }
#pragma unroll 4
        for (int k = 0; k < 32; k++) {
            float4 a = *(const float4*)&sEs[k][tx << 2];
            float4 b0 = *(const float4*)&sWes[k][ch0];
            float4 b1 = *(const float4*)&sWes[k][ch0 + 4];
            float av[4] = {a.x, a.y, a.z, a.w};
            float bv[8] = {b0.x, b0.y, b0.z, b0.w, b1.x, b1.y, b1.z, b1.w};
#pragma unroll
            for (int i = 0; i < 4; i++)
#pragma unroll
                for (int j = 0; j < 8; j++) acc[i][j] = fmaf(av[i], bv[j], acc[i][j]);
        }
#pragma unroll
        for (int i = 0; i < 4; i++) {
            int e = e0 + (tx << 2) + i;
            float4 c0 = make_float4(acc[i][0], acc[i][1], acc[i][2], acc[i][3]);
            float4 c1 = make_float4(acc[i][4], acc[i][5], acc[i][6], acc[i][7]);
            float* out = (ch0 < 64) ? &g_t1[(size_t)e * 64 + ch0]
                                    : &g_t2[(size_t)e * 64 + ch0 - 64];
            *(float4*)out = c0;
            *(float4*)(out + 4) = c1;
#pragma unroll
            for (int j = 0; j < 8; j++) { st[j] += acc[i][j]; sq[j] += acc[i][j] * acc[i][j]; }
        }
    }
    __syncthreads();
#pragma unroll
    for (int j = 0; j < 8; j++) { atomicAdd(&sS[ch0 + j], st[j]); atomicAdd(&sQ[ch0 + j], sq[j]); }
    __syncthreads();
    if (tid < 128) {
        atomicAdd(&g_sum[tid], (double)sS[tid]);
        atomicAdd(&g_sumsq[tid], (double)sQ[tid]);
    }
}

// ---------------- BN finalize ----------------
__global__ void k_bnfin(int off, int n, double inv,
                        const float* __restrict__ g0, const float* __restrict__ b0,
                        const float* __restrict__ g1, const float* __restrict__ b1)
{
    int c = threadIdx.x;
    if (c >= n) return;
    double m = g_sum[off + c] * inv;
    double v = g_sumsq[off + c] * inv - m * m;
    float gg = (c < 64) ? g0[c] : g1[c - 64];
    float bb = (c < 64) ? b0[c] : b1[c - 64];
    float A = gg * rsqrtf((float)v + EPS);
    g_bnA[off + c] = A;
    g_bnB[off + c] = bb - (float)m * A;
}

// ---------------- edge B: tiled 64 edges x 64 ch, K=64; + coord head ----------------
__global__ __launch_bounds__(256) void k_edgeB(const int* __restrict__ ei,
                                               const float* __restrict__ mw2, const float* __restrict__ mb2,
                                               const float* __restrict__ cw2, const float* __restrict__ cb2)
{
    __shared__ __align__(16) float sW2[64][64];
    __shared__ __align__(16) float sX[64][68];
    __shared__ float sWc[64];
    __shared__ float sCoord[64];
    __shared__ float sS[64], sQ[64];
    int tid = threadIdx.x, tx = tid & 15, ty = tid >> 4;
    for (int i = tid; i < 1024; i += 256) {
        int o = i & 63, k0 = (i >> 6) << 2;
        float4 v = *(const float4*)&mw2[o * 64 + k0];
        sW2[k0 + 0][o] = v.x; sW2[k0 + 1][o] = v.y;
        sW2[k0 + 2][o] = v.z; sW2[k0 + 3][o] = v.w;
    }
    if (tid < 64) { sWc[tid] = cw2[tid]; sS[tid] = 0.f; sQ[tid] = 0.f; }
    int k0s = (tid & 3) << 4;
    float4 cA[4], cB[4], dA[4], dB[4];
#pragma unroll
    for (int m = 0; m < 4; m++) {
        cA[m] = *(const float4*)&g_bnA[k0s + 4 * m];
        cB[m] = *(const float4*)&g_bnB[k0s + 4 * m];
        dA[m] = *(const float4*)&g_bnA[64 + k0s + 4 * m];
        dB[m] = *(const float4*)&g_bnB[64 + k0s + 4 * m];
    }
    float b2[4];
#pragma unroll
    for (int j = 0; j < 4; j++) b2[j] = mb2[(ty << 2) + j];
    float cbias = cb2[0];
    float st[4] = {0.f, 0.f, 0.f, 0.f}, sq[4] = {0.f, 0.f, 0.f, 0.f};
    __syncthreads();

    for (int t = blockIdx.x; t < NE / 64; t += gridDim.x) {
        int e0 = t << 6;
        __syncthreads();
        {
            int el = tid >> 2;
            const float* base = &g_t1[(size_t)(e0 + el) * 64 + k0s];
#pragma unroll
            for (int m = 0; m < 4; m++) {
                float4 v = *(const float4*)(base + 4 * m);
                sX[k0s + 4 * m + 0][el] = silu_f(fmaf(v.x, cA[m].x, cB[m].x));
                sX[k0s + 4 * m + 1][el] = silu_f(fmaf(v.y, cA[m].y, cB[m].y));
                sX[k0s + 4 * m + 2][el] = silu_f(fmaf(v.z, cA[m].z, cB[m].z));
                sX[k0s + 4 * m + 3][el] = silu_f(fmaf(v.w, cA[m].w, cB[m].w));
            }
        }
        __syncthreads();
        float acc[4][4];
#pragma unroll
        for (int i = 0; i < 4; i++)
#pragma unroll
            for (int j = 0; j < 4; j++) acc[i][j] = 0.f;
#pragma unroll 4
        for (int k = 0; k < 64; k++) {
            float4 a = *(const float4*)&sX[k][tx << 2];
            float4 b = *(const float4*)&sW2[k][ty << 2];
            float av[4] = {a.x, a.y, a.z, a.w};
            float bv[4] = {b.x, b.y, b.z, b.w};
#pragma unroll
            for (int i = 0; i < 4; i++)
#pragma unroll
                for (int j = 0; j < 4; j++) acc[i][j] = fmaf(av[i], bv[j], acc[i][j]);
        }
#pragma unroll
        for (int i = 0; i < 4; i++) {
            int e = e0 + (tx << 2) + i;
            float y0 = acc[i][0] + b2[0], y1 = acc[i][1] + b2[1];
            float y2 = acc[i][2] + b2[2], y3 = acc[i][3] + b2[3];
            *(float4*)&g_mlin[(size_t)e * 64 + (ty << 2)] = make_float4(y0, y1, y2, y3);
            st[0] += y0; sq[0] += y0 * y0; st[1] += y1; sq[1] += y1 * y1;
            st[2] += y2; sq[2] += y2 * y2; st[3] += y3; sq[3] += y3 * y3;
        }
        // coord head partial (each group of 4 threads handles one edge, 16 ch each)
        {
            int el = tid >> 2;
            const float* base = &g_t2[(size_t)(e0 + el) * 64 + k0s];
            float part = 0.f;
#pragma unroll
            for (int m = 0; m < 4; m++) {
                float4 v = *(const float4*)(base + 4 * m);
                part += silu_f(fmaf(v.x, dA[m].x, dB[m].x)) * sWc[k0s + 4 * m + 0];
                part += silu_f(fmaf(v.y, dA[m].y, dB[m].y)) * sWc[k0s + 4 * m + 1];
                part += silu_f(fmaf(v.z, dA[m].z, dB[m].z)) * sWc[k0s + 4 * m + 2];
                part += silu_f(fmaf(v.w, dA[m].w, dB[m].w)) * sWc[k0s + 4 * m + 3];
            }
            part += __shfl_xor_sync(0xffffffffu, part, 1);
            part += __shfl_xor_sync(0xffffffffu, part, 2);
            if ((tid & 3) == 0) sCoord[el] = part + cbias;
        }
        __syncthreads();
        if (tid < 64) {
            int e = e0 + tid;
            int s = ei[e], d = ei[NE + e];
            float sc = sCoord[tid];
            atomicAdd(&g_aggr_p[d * 3 + 0], sc * (g_pos[d * 3 + 0] - g_pos[s * 3 + 0]));
            atomicAdd(&g_aggr_p[d * 3 + 1], sc * (g_pos[d * 3 + 1] - g_pos[s * 3 + 1]));
            atomicAdd(&g_aggr_p[d * 3 + 2], sc * (g_pos[d * 3 + 2] - g_pos[s * 3 + 2]));
        }
    }
    __syncthreads();
#pragma unroll
    for (int j = 0; j < 4; j++) {
        atomicAdd(&sS[(ty << 2) + j], st[j]);
        atomicAdd(&sQ[(ty << 2) + j], sq[j]);
    }
    __syncthreads();
    if (tid < 64) {
        atomicAdd(&g_sum[128 + tid], (double)sS[tid]);
        atomicAdd(&g_sumsq[128 + tid], (double)sQ[tid]);
    }
}

// ---------------- edge C: msg = silu(bn(mlin)); scatter-add ----------------
__global__ void k_edgeC(const int* __restrict__ ei)
{
    int idx = blockIdx.x * blockDim.x + threadIdx.x;
    if (idx >= NE * 16) return;
    int e = idx >> 4, c4 = (idx & 15) * 4;
    int dst = ei[NE + e];
    float4 m = *(const float4*)&g_mlin[(size_t)e * 64 + c4];
    float4 A = *(const float4*)&g_bnA[128 + c4];
    float4 B = *(const float4*)&g_bnB[128 + c4];
    red_add_v4(&g_u[(size_t)dst * 128 + 64 + c4],
               silu_f(fmaf(m.x, A.x, B.x)), silu_f(fmaf(m.y, A.y, B.y)),
               silu_f(fmaf(m.z, A.z, B.z)), silu_f(fmaf(m.w, A.w, B.w)));
}

// ---------------- node 1: tiled 64n x 64o, K=128 (two halves) ----------------
__global__ __launch_bounds__(256) void k_node1(const float* __restrict__ uw1, const float* __restrict__ ub1)
{
    __shared__ __align__(16) float sW[64][64];
    __shared__ __align__(16) float sA[64][64];
    __shared__ float sS[64], sQ[64];
    int tid = threadIdx.x, tx = tid & 15, ty = tid >> 4;
    if (tid < 64) { sS[tid] = 0.f; sQ[tid] = 0.f; }
    float bb[4];
#pragma unroll
    for (int j = 0; j < 4; j++) bb[j] = ub1[(ty << 2) + j];
    float st[4] = {0.f, 0.f, 0.f, 0.f}, sq[4] = {0.f, 0.f, 0.f, 0.f};
    int ntiles = (NN + 63) >> 6;
    for (int t = blockIdx.x; t < ntiles; t += gridDim.x) {
        int n0 = t << 6;
        float acc[4][4];
#pragma unroll
        for (int i = 0; i < 4; i++)
#pragma unroll
            for (int j = 0; j < 4; j++) acc[i][j] = 0.f;
        for (int half = 0; half < 2; half++) {
            __syncthreads();
            for (int i = tid; i < 1024; i += 256) {
                int o = i & 63, k0 = (i >> 6) << 2;
                float4 v = *(const float4*)&uw1[o * 128 + half * 64 + k0];
                sW[k0 + 0][o] = v.x; sW[k0 + 1][o] = v.y;
                sW[k0 + 2][o] = v.z; sW[k0 + 3][o] = v.w;
            }
            {
                int nn = tid >> 2, k0 = (tid & 3) << 4;
                int n = n0 + nn;
#pragma unroll
                for (int m = 0; m < 4; m++) {
                    float4 v = (n < NN) ? *(const float4*)&g_u[(size_t)n * 128 + half * 64 + k0 + 4 * m]
                                        : make_float4(0.f, 0.f, 0.f, 0.f);
                    sA[k0 + 4 * m + 0][nn] = v.x;
                    sA[k0 + 4 * m + 1][nn] = v.y;
                    sA[k0 + 4 * m + 2][nn] = v.z;
                    sA[k0 + 4 * m + 3][nn] = v.w;
                }
            }
            __syncthreads();
#pragma unroll 4
            for (int k = 0; k < 64; k++) {
                float4 a = *(const float4*)&sA[k][tx << 2];
                float4 b = *(const float4*)&sW[k][ty << 2];
                float av[4] = {a.x, a.y, a.z, a.w};
                float bv[4] = {b.x, b.y, b.z, b.w};
#pragma unroll
                for (int i = 0; i < 4; i++)
#pragma unroll
                    for (int j = 0; j < 4; j++) acc[i][j] = fmaf(av[i], bv[j], acc[i][j]);
            }
        }
#pragma unroll
        for (int i = 0; i < 4; i++) {
            int n = n0 + (tx << 2) + i;
            if (n < NN) {
                float y0 = acc[i][0] + bb[0], y1 = acc[i][1] + bb[1];
                float y2 = acc[i][2] + bb[2], y3 = acc[i][3] + bb[3];
                *(float4*)&g_un[n * 64 + (ty << 2)] = make_float4(y0, y1, y2, y3);
                st[0] += y0; sq[0] += y0 * y0; st[1] += y1; sq[1] += y1 * y1;
                st[2] += y2; sq[2] += y2 * y2; st[3] += y3; sq[3] += y3 * y3;
            }
        }
    }
    __syncthreads();
#pragma unroll
    for (int j = 0; j < 4; j++) {
        atomicAdd(&sS[(ty << 2) + j], st[j]);
        atomicAdd(&sQ[(ty << 2) + j], sq[j]);
    }
    __syncthreads();
    if (tid < 64) {
        atomicAdd(&g_sum[192 + tid], (double)sS[tid]);
        atomicAdd(&g_sumsq[192 + tid], (double)sQ[tid]);
    }
}

// ---------------- node 2: tiled 64n x 64o, K=64; residual + pos update ----------------
__global__ __launch_bounds__(256) void k_node2(const float* __restrict__ uw2, const float* __restrict__ ub2)
{
    __shared__ __align__(16) float sW[64][64];
    __shared__ __align__(16) float sA[64][64];
    int tid = threadIdx.x, tx = tid & 15, ty = tid >> 4;
    for (int i = tid; i < 1024; i += 256) {
        int o = i & 63, k0 = (i >> 6) << 2;
        float4 v = *(const float4*)&uw2[o * 64 + k0];
        sW[k0 + 0][o] = v.x; sW[k0 + 1][o] = v.y;
        sW[k0 + 2][o] = v.z; sW[k0 + 3][o] = v.w;
    }
    int k0s = (tid & 3) << 4;
    float4 cA[4], cB[4];
#pragma unroll
    for (int m = 0; m < 4; m++) {
        cA[m] = *(const float4*)&g_bnA[192 + k0s + 4 * m];
        cB[m] = *(const float4*)&g_bnB[192 + k0s + 4 * m];
    }
    float bb[4];
#pragma unroll
    for (int j = 0; j < 4; j++) bb[j] = ub2[(ty << 2) + j];
    int ntiles = (NN + 63) >> 6;
    for (int t = blockIdx.x; t < ntiles; t += gridDim.x) {
        int n0 = t << 6;
        __syncthreads();
        {
            int nn = tid >> 2;
            int n = n0 + nn;
#pragma unroll
            for (int m = 0; m < 4; m++) {
                float4 v = (n < NN) ? *(const float4*)&g_un[(size_t)n * 64 + k0s + 4 * m]
                                    : make_float4(0.f, 0.f, 0.f, 0.f);
                sA[k0s + 4 * m + 0][nn] = silu_f(fmaf(v.x, cA[m].x, cB[m].x));
                sA[k0s + 4 * m + 1][nn] = silu_f(fmaf(v.y, cA[m].y, cB[m].y));
                sA[k0s + 4 * m + 2][nn] = silu_f(fmaf(v.z, cA[m].z, cB[m].z));
                sA[k0s + 4 * m + 3][nn] = silu_f(fmaf(v.w, cA[m].w, cB[m].w));
            }
        }
        __syncthreads();
        float acc[4][4];
#pragma unroll
        for (int i = 0; i < 4; i++)
#pragma unroll
            for (int j = 0; j < 4; j++) acc[i][j] = 0.f;
#pragma unroll 4
        for (int k = 0; k < 64; k++) {
            float4 a = *(const float4*)&sA[k][tx << 2];
            float4 b = *(const float4*)&sW[k][ty << 2];
            float av[4] = {a.x, a.y, a.z, a.w};
            float bv[4] = {b.x, b.y, b.z, b.w};
#pragma unroll
            for (int i = 0; i < 4; i++)
#pragma unroll
                for (int j = 0; j < 4; j++) acc[i][j] = fmaf(av[i], bv[j], acc[i][j]);
        }
#pragma unroll
        for (int i = 0; i < 4; i++) {
            int n = n0 + (tx << 2) + i;
            if (n < NN) {
                float4 hold = *(const float4*)&g_h[n * 64 + (ty << 2)];
                float h0 = hold.x + acc[i][0] + bb[0];
                float h1 = hold.y + acc[i][1] + bb[1];
                float h2 = hold.z + acc[i][2] + bb[2];
                float h3 = hold.w + acc[i][3] + bb[3];
                float4 hv = make_float4(h0, h1, h2, h3);
                *(float4*)&g_h[n * 64 + (ty << 2)] = hv;
                *(float4*)&g_u[(size_t)n * 128 + (ty << 2)] = hv;
            }
        }
        if (tid < 64) {
            int n = n0 + tid;
            if (n < NN) {
                g_pos[n * 3 + 0] += g_aggr_p[n * 3 + 0];
                g_pos[n * 3 + 1] += g_aggr_p[n * 3 + 1];
                g_pos[n * 3 + 2] += g_aggr_p[n * 3 + 2];
            }
        }
    }
}

// ---------------- pooling ----------------
__global__ void k_pool(const int* __restrict__ batch)
{
    int idx = blockIdx.x * blockDim.x + threadIdx.x;
    if (idx >= NN * 16) return;
    int n = idx >> 4, c4 = (idx & 15) * 4;
    int b = batch[n];
    float4 h = *(const float4*)&g_h[n * 64 + c4];
    red_add_v4(&g_pool[b * 64 + c4], h.x, h.y, h.z, h.w);
    if (c4 == 0) atomicAdd(&g_cnt[b], 1.0f);
}

__global__ void k_pred(const float* __restrict__ w, const float* __restrict__ b,
                       float* __restrict__ out)
{
    int g = blockIdx.x, lane = threadIdx.x;
    float p = g_pool[g * 64 + lane] * w[lane] + g_pool[g * 64 + 32 + lane] * w[32 + lane];
#pragma unroll
    for (int o = 16; o > 0; o >>= 1) p += __shfl_xor_sync(0xffffffffu, p, o);
    if (lane == 0) out[g] = p / fmaxf(g_cnt[g], 1.0f) + b[0];
}

// ---------------- launch ----------------
extern "C" void kernel_launch(void* const* d_in, const int* in_sizes, int n_in,
                              void* d_out, int out_size)
{
    const float* node_s    = (const float*)d_in[0];
    const float* node_type = (const float*)d_in[1];
    const float* pos       = (const float*)d_in[2];
    const int*   ei        = (const int*)d_in[3];
    const float* edge_s    = (const float*)d_in[4];
    const int*   batch     = (const int*)d_in[5];
    const float* lin_in_w  = (const float*)d_in[6];
    const float* lin_in_b  = (const float*)d_in[7];
    const float* msg_w1    = (const float*)d_in[8];
    const float* msg_b1    = (const float*)d_in[9];
    const float* msg_g1    = (const float*)d_in[10];
    const float* msg_be1   = (const float*)d_in[11];
    const float* msg_w2    = (const float*)d_in[12];
    const float* msg_b2    = (const float*)d_in[13];
    const float* msg_g2    = (const float*)d_in[14];
    const float* msg_be2   = (const float*)d_in[15];
    const float* updf_w1   = (const float*)d_in[16];
    const float* updf_b1   = (const float*)d_in[17];
    const float* updf_g1   = (const float*)d_in[18];
    const float* updf_be1  = (const float*)d_in[19];
    const float* updf_w2   = (const float*)d_in[20];
    const float* updf_b2   = (const float*)d_in[21];
    const float* updc_w1   = (const float*)d_in[22];
    const float* updc_b1   = (const float*)d_in[23];
    const float* updc_g1   = (const float*)d_in[24];
    const float* updc_be1  = (const float*)d_in[25];
    const float* updc_w2   = (const float*)d_in[26];
    const float* updc_b2   = (const float*)d_in[27];
    const float* lin_pred_w = (const float*)d_in[28];
    const float* lin_pred_b = (const float*)d_in[29];

    k_init<<<(NN * 64 + 255) / 256, 256>>>(node_s, node_type, pos, lin_in_w, lin_in_b);

    for (int l = 0; l < NL; l++) {
        const float* mw1 = msg_w1 + (size_t)l * 64 * 161;
        const float* mb1 = msg_b1 + l * 64;
        const float* mw2 = msg_w2 + (size_t)l * 64 * 64;
        const float* mb2 = msg_b2 + l * 64;
        const float* cw1 = updc_w1 + (size_t)l * 64 * 161;
        const float* cb1 = updc_b1 + l * 64;
        const float* cw2 = updc_w2 + (size_t)l * 64;
        const float* cb2 = updc_b2 + l;
        const float* uw1 = updf_w1 + (size_t)l * 64 * 128;
        const float* ub1 = updf_b1 + l * 64;
        const float* uw2 = updf_w2 + (size_t)l * 64 * 64;
        const float* ub2 = updf_b2 + l * 64;

        k_zero<<<(NN * 64 + 255) / 256, 256>>>();
        k_wpack<<<(64 * 256 + 255) / 256, 256>>>(mw1, cw1);
        k_hpre<<<512, 256>>>();
        k_edgeA<<<1024, 256>>>(ei, edge_s, mw1, mb1, cw1, cb1);
        k_bnfin<<<1, 128>>>(0, 128, 1.0 / NE,
                            msg_g1 + l * 64, msg_be1 + l * 64,
                            updc_g1 + l * 64, updc_be1 + l * 64);
        k_edgeB<<<1024, 256>>>(ei, mw2, mb2, cw2, cb2);
        k_bnfin<<<1, 64>>>(128, 64, 1.0 / NE,
                           msg_g2 + l * 64, msg_be2 + l * 64,
                           msg_g2 + l * 64, msg_be2 + l * 64);
        k_edgeC<<<(NE * 16 + 255) / 256, 256>>>(ei);
        k_node1<<<512, 256>>>(uw1, ub1);
        k_bnfin<<<1, 64>>>(192, 64, 1.0 / NN,
                           updf_g1 + l * 64, updf_be1 + l * 64,
                           updf_g1 + l * 64, updf_be1 + l * 64);
        k_node2<<<512, 256>>>(uw2, ub2);
    }

    k_pool<<<(NN * 16 + 255) / 256, 256>>>(batch);
    k_pred<<<NG, 32>>>(lin_pred_w, lin_pred_b, (float*)d_out);
}

// round 6
// speedup vs baseline: 1.4381x; 1.0354x over previous
#include <cuda_runtime.h>
#include <math.h>

#define NN 50000
#define NE 800000
#define NL 4
#define NG 64
#define EPS 1e-5f

// ---------------- static device scratch ----------------
__device__ __align__(16) float g_h[NN * 64];
__device__ __align__(16) float g_u[NN * 128];      // [h | aggr_h]
__device__ __align__(16) float g_un[NN * 64];
__device__ __align__(16) float g_pos[NN * 3];
__device__ __align__(16) float g_aggr_p[NN * 3];
__device__ __align__(16) float g_Hpre[(size_t)NN * 256];
__device__ __align__(16) float g_wpack4[NL][64 * 256];  // k-major [k][op]
__device__ __align__(16) float g_t1[(size_t)NE * 64];
__device__ __align__(16) float g_t2[(size_t)NE * 64];
__device__ __align__(16) float g_mlin[(size_t)NE * 64];
__device__ __align__(16) float g_sc[NE];
__device__ int g_deg[NN];
__device__ int g_rowstart[NN + 1];
__device__ int g_cursor[NN];
__device__ int g_csr[NE];
__device__ double g_sum[256];
__device__ double g_sumsq[256];
__device__ __align__(16) float g_bnA[256];
__device__ __align__(16) float g_bnB[256];
__device__ __align__(16) float g_pool[NG * 64];
__device__ float g_cnt[NG];

__device__ __forceinline__ float silu_f(float y) {
    return y * (1.0f / (1.0f + __expf(-y)));
}

__device__ __forceinline__ void red_add_v4(float* p, float a, float b, float c, float d) {
    asm volatile("red.global.add.v4.f32 [%0], {%1,%2,%3,%4};"
                 :: "l"(p), "f"(a), "f"(b), "f"(c), "f"(d) : "memory");
}

// ---------------- init: h = [node_s,node_type]@W^T+b; zero stats/deg/pool ----------------
__global__ void k_init(const float* __restrict__ ns, const float* __restrict__ nt,
                       const float* __restrict__ pos, const float* __restrict__ w,
                       const float* __restrict__ b)
{
    int idx = blockIdx.x * blockDim.x + threadIdx.x;
    if (idx < NG * 64) g_pool[idx] = 0.f;
    if (idx < NG) g_cnt[idx] = 0.f;
    if (idx < 256) { g_sum[idx] = 0.0; g_sumsq[idx] = 0.0; }
    if (idx < NN) g_deg[idx] = 0;
    if (idx >= NN * 64) return;
    int n = idx >> 6, o = idx & 63;
    const float* wr = w + o * 8;
    const float* s = ns + n * 6;
    float acc = b[o];
#pragma unroll
    for (int i = 0; i < 6; i++) acc = fmaf(s[i], wr[i], acc);
    acc = fmaf(nt[n * 2 + 0], wr[6], acc);
    acc = fmaf(nt[n * 2 + 1], wr[7], acc);
    g_h[idx] = acc;
    g_u[(size_t)n * 128 + o] = acc;
    if (o < 3) g_pos[n * 3 + o] = pos[n * 3 + o];
}

// ---------------- CSR build ----------------
__global__ void k_hist(const int* __restrict__ ei)
{
    int e = blockIdx.x * blockDim.x + threadIdx.x;
    if (e < NE) atomicAdd(&g_deg[ei[NE + e]], 1);
}

__global__ __launch_bounds__(1024) void k_scan()
{
    __shared__ int ssum[1024];
    int t = threadIdx.x;
    const int C = 49;  // 1024*49 = 50176 >= NN
    int begin = t * C;
    int end = begin + C; if (end > NN) end = NN;
    if (begin > NN) begin = NN;
    int s = 0;
    for (int i = begin; i < end; i++) s += g_deg[i];
    ssum[t] = s;
    __syncthreads();
    for (int off = 1; off < 1024; off <<= 1) {
        int v = (t >= off) ? ssum[t - off] : 0;
        __syncthreads();
        ssum[t] += v;
        __syncthreads();
    }
    int run = ssum[t] - s;  // exclusive prefix
    for (int i = begin; i < end; i++) {
        g_rowstart[i] = run;
        g_cursor[i] = run;
        run += g_deg[i];
    }
    if (t == 1023) g_rowstart[NN] = ssum[1023];
}

__global__ void k_fill(const int* __restrict__ ei)
{
    int e = blockIdx.x * blockDim.x + threadIdx.x;
    if (e >= NE) return;
    int d = ei[NE + e];
    int p = atomicAdd(&g_cursor[d], 1);
    g_csr[p] = e;
}

// ---------------- pack h-columns of msg_w1/updc_w1 for ALL layers, k-major ----------------
__global__ void k_wpack_all(const float* __restrict__ mw1a, const float* __restrict__ cw1a)
{
    int idx = blockIdx.x * blockDim.x + threadIdx.x;
    if (idx >= NL * 64 * 256) return;
    int l = idx >> 14;
    int r = idx & 16383;
    int k = r >> 8, op = r & 255, o = op & 63;
    const float* mw1 = mw1a + (size_t)l * 64 * 161;
    const float* cw1 = cw1a + (size_t)l * 64 * 161;
    float v;
    if (op < 64)       v = mw1[o * 161 + k];
    else if (op < 128) v = mw1[o * 161 + 64 + k];
    else if (op < 192) v = cw1[o * 161 + k];
    else               v = cw1[o * 161 + 64 + k];
    g_wpack4[l][k * 256 + op] = v;
}

// ---------------- Hpre: tiled GEMM 64n x 128o (2 phases), K=64 ----------------
__global__ __launch_bounds__(256) void k_hpre(int layer)
{
    const float* wpack = g_wpack4[layer];
    __shared__ __align__(16) float sA[64][64];
    __shared__ __align__(16) float sB[64][128];
    int tid = threadIdx.x, tx = tid & 15, ty = tid >> 4;
    int ntiles = (NN + 63) >> 6;
    for (int t = blockIdx.x; t < ntiles; t += gridDim.x) {
        int n0 = t << 6;
        __syncthreads();
        {
            int nn = tid >> 2, k0 = (tid & 3) << 4;
            int n = n0 + nn;
#pragma unroll
            for (int m = 0; m < 4; m++) {
                float4 v = (n < NN) ? *(const float4*)&g_h[n * 64 + k0 + 4 * m]
                                    : make_float4(0.f, 0.f, 0.f, 0.f);
                sA[k0 + 4 * m + 0][nn] = v.x;
                sA[k0 + 4 * m + 1][nn] = v.y;
                sA[k0 + 4 * m + 2][nn] = v.z;
                sA[k0 + 4 * m + 3][nn] = v.w;
            }
        }
        for (int ph = 0; ph < 2; ph++) {
            __syncthreads();
#pragma unroll
            for (int r = 0; r < 8; r++) {
                int i = tid + r * 256;
                int k = i >> 5, o4 = (i & 31) << 2;
                *(float4*)&sB[k][o4] = *(const float4*)&wpack[k * 256 + ph * 128 + o4];
            }
            __syncthreads();
            float acc[4][8];
#pragma unroll
            for (int i = 0; i < 4; i++)
#pragma unroll
                for (int j = 0; j < 8; j++) acc[i][j] = 0.f;
#pragma unroll 4
            for (int k = 0; k < 64; k++) {
                float4 a = *(const float4*)&sA[k][tx << 2];
                float4 b0 = *(const float4*)&sB[k][ty << 3];
                float4 b1 = *(const float4*)&sB[k][(ty << 3) + 4];
                float av[4] = {a.x, a.y, a.z, a.w};
                float bv[8] = {b0.x, b0.y, b0.z, b0.w, b1.x, b1.y, b1.z, b1.w};
#pragma unroll
                for (int i = 0; i < 4; i++)
#pragma unroll
                    for (int j = 0; j < 8; j++) acc[i][j] = fmaf(av[i], bv[j], acc[i][j]);
            }
#pragma unroll
            for (int i = 0; i < 4; i++) {
                int n = n0 + (tx << 2) + i;
                if (n < NN) {
                    float* out = &g_Hpre[(size_t)n * 256 + ph * 128 + (ty << 3)];
                    *(float4*)out = make_float4(acc[i][0], acc[i][1], acc[i][2], acc[i][3]);
                    *(float4*)(out + 4) = make_float4(acc[i][4], acc[i][5], acc[i][6], acc[i][7]);
                }
            }
        }
    }
}

// ---------------- edge A: tiled, 64 edges x 128 ch, K=32 (edge_s) + gather init ----------------
__global__ __launch_bounds__(256) void k_edgeA(const int* __restrict__ ei, const float* __restrict__ es,
                                               const float* __restrict__ mw1, const float* __restrict__ mb1,
                                               const float* __restrict__ cw1, const float* __restrict__ cb1)
{
    __shared__ __align__(16) float sWes[32][128];
    __shared__ float sWr[128], sBias[128];
    __shared__ __align__(16) float sEs[32][68];
    __shared__ float sR[64];
    __shared__ int sSrc[64], sDst[64];
    __shared__ float sS[128], sQ[128];
    int tid = threadIdx.x, tx = tid & 15, ty = tid >> 4;
    for (int i = tid; i < 32 * 128; i += 256) {
        int k = i >> 7, ch = i & 127;
        sWes[k][ch] = (ch < 64) ? mw1[ch * 161 + 129 + k] : cw1[(ch - 64) * 161 + 129 + k];
    }
    if (tid < 128) {
        sWr[tid]  = (tid < 64) ? mw1[tid * 161 + 128] : cw1[(tid - 64) * 161 + 128];
        sBias[tid] = (tid < 64) ? mb1[tid] : cb1[tid - 64];
        sS[tid] = 0.f; sQ[tid] = 0.f;
    }
    __syncthreads();
    int ch0 = ty << 3;
    int dstoff = (ch0 < 64) ? ch0 : 64 + ch0;
    float wr[8], bb[8];
#pragma unroll
    for (int j = 0; j < 8; j++) { wr[j] = sWr[ch0 + j]; bb[j] = sBias[ch0 + j]; }
    float st[8], sq[8];
#pragma unroll
    for (int j = 0; j < 8; j++) { st[j] = 0.f; sq[j] = 0.f; }

    for (int t = blockIdx.x; t < NE / 64; t += gridDim.x) {
        int e0 = t << 6;
        __syncthreads();
        if (tid < 64) {
            int e = e0 + tid;
            int s = ei[e], d = ei[NE + e];
            sSrc[tid] = s; sDst[tid] = d;
            float dx = g_pos[d * 3] - g_pos[s * 3];
            float dy = g_pos[d * 3 + 1] - g_pos[s * 3 + 1];
            float dz = g_pos[d * 3 + 2] - g_pos[s * 3 + 2];
            sR[tid] = sqrtf(dx * dx + dy * dy + dz * dz);
        }
        {
            int el = tid >> 2, k0 = (tid & 3) << 3;
            const float* ep = &es[(size_t)(e0 + el) * 32 + k0];
            float4 v0 = *(const float4*)ep;
            float4 v1 = *(const float4*)(ep + 4);
            sEs[k0 + 0][el] = v0.x; sEs[k0 + 1][el] = v0.y;
            sEs[k0 + 2][el] = v0.z; sEs[k0 + 3][el] = v0.w;
            sEs[k0 + 4][el] = v1.x; sEs[k0 + 5][el] = v1.y;
            sEs[k0 + 6][el] = v1.z; sEs[k0 + 7][el] = v1.w;
        }
        __syncthreads();
        float acc[4][8];
#pragma unroll
        for (int i = 0; i < 4; i++) {
            int el = (tx << 2) + i;
            int d = sDst[el], s = sSrc[el];
            float r = sR[el];
            const float* hdp = &g_Hpre[(size_t)d * 256 + dstoff];
            const float* hsp = &g_Hpre[(size_t)s * 256 + dstoff + 64];
            float4 hd0 = *(const float4*)hdp;
            float4 hd1 = *(const float4*)(hdp + 4);
            float4 hs0 = *(const float4*)hsp;
            float4 hs1 = *(const float4*)(hsp + 4);
            acc[i][0] = hd0.x + hs0.x + fmaf(r, wr[0], bb[0]);
            acc[i][1] = hd0.y + hs0.y + fmaf(r, wr[1], bb[1]);
            acc[i][2] = hd0.z + hs0.z + fmaf(r, wr[2], bb[2]);
            acc[i][3] = hd0.w + hs0.w + fmaf(r, wr[3], bb[3]);
            acc[i][4] = hd1.x + hs1.x + fmaf(r, wr[4], bb[4]);
            acc[i][5] = hd1.y + hs1.y + fmaf(r, wr[5], bb[5]);
            acc[i][6] = hd1.z + hs1.z + fmaf(r, wr[6], bb[6]);
            acc[i][7] = hd1.w + hs1.w + fmaf(r, wr[7], bb[7]);
        }
#pragma unroll 4
        for (int k = 0; k < 32; k++) {
            float4 a = *(const float4*)&sEs[k][tx << 2];
            float4 b0 = *(const float4*)&sWes[k][ch0];
            float4 b1 = *(const float4*)&sWes[k][ch0 + 4];
            float av[4] = {a.x, a.y, a.z, a.w};
            float bv[8] = {b0.x, b0.y, b0.z, b0.w, b1.x, b1.y, b1.z, b1.w};
#pragma unroll
            for (int i = 0; i < 4; i++)
#pragma unroll
                for (int j = 0; j < 8; j++) acc[i][j] = fmaf(av[i], bv[j], acc[i][j]);
        }
#pragma unroll
        for (int i = 0; i < 4; i++) {
            int e = e0 + (tx << 2) + i;
            float4 c0 = make_float4(acc[i][0], acc[i][1], acc[i][2], acc[i][3]);
            float4 c1 = make_float4(acc[i][4], acc[i][5], acc[i][6], acc[i][7]);
            float* out = (ch0 < 64) ? &g_t1[(size_t)e * 64 + ch0]
                                    : &g_t2[(size_t)e * 64 + ch0 - 64];
            *(float4*)out = c0;
            *(float4*)(out + 4) = c1;
#pragma unroll
            for (int j = 0; j < 8; j++) { st[j] += acc[i][j]; sq[j] += acc[i][j] * acc[i][j]; }
        }
    }
    __syncthreads();
#pragma unroll
    for (int j = 0; j < 8; j++) { atomicAdd(&sS[ch0 + j], st[j]); atomicAdd(&sQ[ch0 + j], sq[j]); }
    __syncthreads();
    if (tid < 128) {
        atomicAdd(&g_sum[tid], (double)sS[tid]);
        atomicAdd(&g_sumsq[tid], (double)sQ[tid]);
    }
}

// ---------------- BN finalize (self-resetting stats) ----------------
__global__ void k_bnfin(int off, int n, double inv,
                        const float* __restrict__ g0, const float* __restrict__ b0,
                        const float* __restrict__ g1, const float* __restrict__ b1)
{
    int c = threadIdx.x;
    if (c >= n) return;
    double m = g_sum[off + c] * inv;
    double v = g_sumsq[off + c] * inv - m * m;
    g_sum[off + c] = 0.0;
    g_sumsq[off + c] = 0.0;
    float gg = (c < 64) ? g0[c] : g1[c - 64];
    float bb = (c < 64) ? b0[c] : b1[c - 64];
    float A = gg * rsqrtf((float)v + EPS);
    g_bnA[off + c] = A;
    g_bnB[off + c] = bb - (float)m * A;
}

// ---------------- edge B: tiled 64 edges x 64 ch, K=64; coord head -> g_sc ----------------
__global__ __launch_bounds__(256) void k_edgeB(const float* __restrict__ mw2, const float* __restrict__ mb2,
                                               const float* __restrict__ cw2, const float* __restrict__ cb2)
{
    __shared__ __align__(16) float sW2[64][64];
    __shared__ __align__(16) float sX[64][68];
    __shared__ float sWc[64];
    __shared__ float sS[64], sQ[64];
    int tid = threadIdx.x, tx = tid & 15, ty = tid >> 4;
    for (int i = tid; i < 1024; i += 256) {
        int o = i & 63, k0 = (i >> 6) << 2;
        float4 v = *(const float4*)&mw2[o * 64 + k0];
        sW2[k0 + 0][o] = v.x; sW2[k0 + 1][o] = v.y;
        sW2[k0 + 2][o] = v.z; sW2[k0 + 3][o] = v.w;
    }
    if (tid < 64) { sWc[tid] = cw2[tid]; sS[tid] = 0.f; sQ[tid] = 0.f; }
    int k0s = (tid & 3) << 4;
    float4 cA[4], cB[4], dA[4], dB[4];
#pragma unroll
    for (int m = 0; m < 4; m++) {
        cA[m] = *(const float4*)&g_bnA[k0s + 4 * m];
        cB[m] = *(const float4*)&g_bnB[k0s + 4 * m];
        dA[m] = *(const float4*)&g_bnA[64 + k0s + 4 * m];
        dB[m] = *(const float4*)&g_bnB[64 + k0s + 4 * m];
    }
    float b2[4];
#pragma unroll
    for (int j = 0; j < 4; j++) b2[j] = mb2[(ty << 2) + j];
    float cbias = cb2[0];
    float st[4] = {0.f, 0.f, 0.f, 0.f}, sq[4] = {0.f, 0.f, 0.f, 0.f};
    __syncthreads();

    for (int t = blockIdx.x; t < NE / 64; t += gridDim.x) {
        int e0 = t << 6;
        __syncthreads();
        {
            int el = tid >> 2;
            const float* base = &g_t1[(size_t)(e0 + el) * 64 + k0s];
#pragma unroll
            for (int m = 0; m < 4; m++) {
                float4 v = *(const float4*)(base + 4 * m);
                sX[k0s + 4 * m + 0][el] = silu_f(fmaf(v.x, cA[m].x, cB[m].x));
                sX[k0s + 4 * m + 1][el] = silu_f(fmaf(v.y, cA[m].y, cB[m].y));
                sX[k0s + 4 * m + 2][el] = silu_f(fmaf(v.z, cA[m].z, cB[m].z));
                sX[k0s + 4 * m + 3][el] = silu_f(fmaf(v.w, cA[m].w, cB[m].w));
            }
        }
        // coord head: group of 4 threads handles edge el, 16 ch each -> g_sc
        {
            int el = tid >> 2;
            const float* base = &g_t2[(size_t)(e0 + el) * 64 + k0s];
            float part = 0.f;
#pragma unroll
            for (int m = 0; m < 4; m++) {
                float4 v = *(const float4*)(base + 4 * m);
                part += silu_f(fmaf(v.x, dA[m].x, dB[m].x)) * sWc[k0s + 4 * m + 0];
                part += silu_f(fmaf(v.y, dA[m].y, dB[m].y)) * sWc[k0s + 4 * m + 1];
                part += silu_f(fmaf(v.z, dA[m].z, dB[m].z)) * sWc[k0s + 4 * m + 2];
                part += silu_f(fmaf(v.w, dA[m].w, dB[m].w)) * sWc[k0s + 4 * m + 3];
            }
            part += __shfl_xor_sync(0xffffffffu, part, 1);
            part += __shfl_xor_sync(0xffffffffu, part, 2);
            if ((tid & 3) == 0) g_sc[e0 + el] = part + cbias;
        }
        __syncthreads();
        float acc[4][4];
#pragma unroll
        for (int i = 0; i < 4; i++)
#pragma unroll
            for (int j = 0; j < 4; j++) acc[i][j] = 0.f;
#pragma unroll 4
        for (int k = 0; k < 64; k++) {
            float4 a = *(const float4*)&sX[k][tx << 2];
            float4 b = *(const float4*)&sW2[k][ty << 2];
            float av[4] = {a.x, a.y, a.z, a.w};
            float bv[4] = {b.x, b.y, b.z, b.w};
#pragma unroll
            for (int i = 0; i < 4; i++)
#pragma unroll
                for (int j = 0; j < 4; j++) acc[i][j] = fmaf(av[i], bv[j], acc[i][j]);
        }
#pragma unroll
        for (int i = 0; i < 4; i++) {
            int e = e0 + (tx << 2) + i;
            float y0 = acc[i][0] + b2[0], y1 = acc[i][1] + b2[1];
            float y2 = acc[i][2] + b2[2], y3 = acc[i][3] + b2[3];
            *(float4*)&g_mlin[(size_t)e * 64 + (ty << 2)] = make_float4(y0, y1, y2, y3);
            st[0] += y0; sq[0] += y0 * y0; st[1] += y1; sq[1] += y1 * y1;
            st[2] += y2; sq[2] += y2 * y2; st[3] += y3; sq[3] += y3 * y3;
        }
    }
    __syncthreads();
#pragma unroll
    for (int j = 0; j < 4; j++) {
        atomicAdd(&sS[(ty << 2) + j], st[j]);
        atomicAdd(&sQ[(ty << 2) + j], sq[j]);
    }
    __syncthreads();
    if (tid < 64) {
        atomicAdd(&g_sum[128 + tid], (double)sS[tid]);
        atomicAdd(&g_sumsq[128 + tid], (double)sQ[tid]);
    }
}

// ---------------- aggregation: warp per node, CSR gather ----------------
__global__ __launch_bounds__(256) void k_aggr(const int* __restrict__ ei)
{
    int gwarp = (blockIdx.x * blockDim.x + threadIdx.x) >> 5;
    int lane = threadIdx.x & 31;
    if (gwarp >= NN) return;
    int n = gwarp;
    int s0 = g_rowstart[n], s1 = g_rowstart[n + 1];
    float A0 = g_bnA[128 + lane], B0 = g_bnB[128 + lane];
    float A1 = g_bnA[160 + lane], B1 = g_bnB[160 + lane];
    float acc0 = 0.f, acc1 = 0.f;
    for (int i = s0; i < s1; i++) {
        int e = g_csr[i];
        float m0 = g_mlin[(size_t)e * 64 + lane];
        float m1 = g_mlin[(size_t)e * 64 + 32 + lane];
        acc0 += silu_f(fmaf(m0, A0, B0));
        acc1 += silu_f(fmaf(m1, A1, B1));
    }
    g_u[(size_t)n * 128 + 64 + lane] = acc0;
    g_u[(size_t)n * 128 + 96 + lane] = acc1;
    // coord aggregation
    float px = g_pos[n * 3], py = g_pos[n * 3 + 1], pz = g_pos[n * 3 + 2];
    float cx = 0.f, cy = 0.f, cz = 0.f;
    for (int i = s0 + lane; i < s1; i += 32) {
        int e = g_csr[i];
        int src = ei[e];
        float sc = g_sc[e];
        cx += sc * (px - g_pos[src * 3]);
        cy += sc * (py - g_pos[src * 3 + 1]);
        cz += sc * (pz - g_pos[src * 3 + 2]);
    }
#pragma unroll
    for (int o = 16; o > 0; o >>= 1) {
        cx += __shfl_xor_sync(0xffffffffu, cx, o);
        cy += __shfl_xor_sync(0xffffffffu, cy, o);
        cz += __shfl_xor_sync(0xffffffffu, cz, o);
    }
    if (lane == 0) {
        g_aggr_p[n * 3 + 0] = cx;
        g_aggr_p[n * 3 + 1] = cy;
        g_aggr_p[n * 3 + 2] = cz;
    }
}

// ---------------- node 1: tiled 64n x 64o, K=128 (two halves) ----------------
__global__ __launch_bounds__(256) void k_node1(const float* __restrict__ uw1, const float* __restrict__ ub1)
{
    __shared__ __align__(16) float sW[64][64];
    __shared__ __align__(16) float sA[64][64];
    __shared__ float sS[64], sQ[64];
    int tid = threadIdx.x, tx = tid & 15, ty = tid >> 4;
    if (tid < 64) { sS[tid] = 0.f; sQ[tid] = 0.f; }
    float bb[4];
#pragma unroll
    for (int j = 0; j < 4; j++) bb[j] = ub1[(ty << 2) + j];
    float st[4] = {0.f, 0.f, 0.f, 0.f}, sq[4] = {0.f, 0.f, 0.f, 0.f};
    int ntiles = (NN + 63) >> 6;
    for (int t = blockIdx.x; t < ntiles; t += gridDim.x) {
        int n0 = t << 6;
        float acc[4][4];
#pragma unroll
        for (int i = 0; i < 4; i++)
#pragma unroll
            for (int j = 0; j < 4; j++) acc[i][j] = 0.f;
        for (int half = 0; half < 2; half++) {
            __syncthreads();
            for (int i = tid; i < 1024; i += 256) {
                int o = i & 63, k0 = (i >> 6) << 2;
                float4 v = *(const float4*)&uw1[o * 128 + half * 64 + k0];
                sW[k0 + 0][o] = v.x; sW[k0 + 1][o] = v.y;
                sW[k0 + 2][o] = v.z; sW[k0 + 3][o] = v.w;
            }
            {
                int nn = tid >> 2, k0 = (tid & 3) << 4;
                int n = n0 + nn;
#pragma unroll
                for (int m = 0; m < 4; m++) {
                    float4 v = (n < NN) ? *(const float4*)&g_u[(size_t)n * 128 + half * 64 + k0 + 4 * m]
                                        : make_float4(0.f, 0.f, 0.f, 0.f);
                    sA[k0 + 4 * m + 0][nn] = v.x;
                    sA[k0 + 4 * m + 1][nn] = v.y;
                    sA[k0 + 4 * m + 2][nn] = v.z;
                    sA[k0 + 4 * m + 3][nn] = v.w;
                }
            }
            __syncthreads();
#pragma unroll 4
            for (int k = 0; k < 64; k++) {
                float4 a = *(const float4*)&sA[k][tx << 2];
                float4 b = *(const float4*)&sW[k][ty << 2];
                float av[4] = {a.x, a.y, a.z, a.w};
                float bv[4] = {b.x, b.y, b.z, b.w};
#pragma unroll
                for (int i = 0; i < 4; i++)
#pragma unroll
                    for (int j = 0; j < 4; j++) acc[i][j] = fmaf(av[i], bv[j], acc[i][j]);
            }
        }
#pragma unroll
        for (int i = 0; i < 4; i++) {
            int n = n0 + (tx << 2) + i;
            if (n < NN) {
                float y0 = acc[i][0] + bb[0], y1 = acc[i][1] + bb[1];
                float y2 = acc[i][2] + bb[2], y3 = acc[i][3] + bb[3];
                *(float4*)&g_un[n * 64 + (ty << 2)] = make_float4(y0, y1, y2, y3);
                st[0] += y0; sq[0] += y0 * y0; st[1] += y1; sq[1] += y1 * y1;
                st[2] += y2; sq[2] += y2 * y2; st[3] += y3; sq[3] += y3 * y3;
            }
        }
    }
    __syncthreads();
#pragma unroll
    for (int j = 0; j < 4; j++) {
        atomicAdd(&sS[(ty << 2) + j], st[j]);
        atomicAdd(&sQ[(ty << 2) + j], sq[j]);
    }
    __syncthreads();
    if (tid < 64) {
        atomicAdd(&g_sum[192 + tid], (double)sS[tid]);
        atomicAdd(&g_sumsq[192 + tid], (double)sQ[tid]);
    }
}

// ---------------- node 2: tiled 64n x 64o, K=64; residual + pos update ----------------
__global__ __launch_bounds__(256) void k_node2(const float* __restrict__ uw2, const float* __restrict__ ub2)
{
    __shared__ __align__(16) float sW[64][64];
    __shared__ __align__(16) float sA[64][64];
    int tid = threadIdx.x, tx = tid & 15, ty = tid >> 4;
    for (int i = tid; i < 1024; i += 256) {
        int o = i & 63, k0 = (i >> 6) << 2;
        float4 v = *(const float4*)&uw2[o * 64 + k0];
        sW[k0 + 0][o] = v.x; sW[k0 + 1][o] = v.y;
        sW[k0 + 2][o] = v.z; sW[k0 + 3][o] = v.w;
    }
    int k0s = (tid & 3) << 4;
    float4 cA[4], cB[4];
#pragma unroll
    for (int m = 0; m < 4; m++) {
        cA[m] = *(const float4*)&g_bnA[192 + k0s + 4 * m];
        cB[m] = *(const float4*)&g_bnB[192 + k0s + 4 * m];
    }
    float bb[4];
#pragma unroll
    for (int j = 0; j < 4; j++) bb[j] = ub2[(ty << 2) + j];
    int ntiles = (NN + 63) >> 6;
    for (int t = blockIdx.x; t < ntiles; t += gridDim.x) {
        int n0 = t << 6;
        __syncthreads();
        {
            int nn = tid >> 2;
            int n = n0 + nn;
#pragma unroll
            for (int m = 0; m < 4; m++) {
                float4 v = (n < NN) ? *(const float4*)&g_un[(size_t)n * 64 + k0s + 4 * m]
                                    : make_float4(0.f, 0.f, 0.f, 0.f);
                sA[k0s + 4 * m + 0][nn] = silu_f(fmaf(v.x, cA[m].x, cB[m].x));
                sA[k0s + 4 * m + 1][nn] = silu_f(fmaf(v.y, cA[m].y, cB[m].y));
                sA[k0s + 4 * m + 2][nn] = silu_f(fmaf(v.z, cA[m].z, cB[m].z));
                sA[k0s + 4 * m + 3][nn] = silu_f(fmaf(v.w, cA[m].w, cB[m].w));
            }
        }
        __syncthreads();
        float acc[4][4];
#pragma unroll
        for (int i = 0; i < 4; i++)
#pragma unroll
            for (int j = 0; j < 4; j++) acc[i][j] = 0.f;
#pragma unroll 4
        for (int k = 0; k < 64; k++) {
            float4 a = *(const float4*)&sA[k][tx << 2];
            float4 b = *(const float4*)&sW[k][ty << 2];
            float av[4] = {a.x, a.y, a.z, a.w};
            float bv[4] = {b.x, b.y, b.z, b.w};
#pragma unroll
            for (int i = 0; i < 4; i++)
#pragma unroll
                for (int j = 0; j < 4; j++) acc[i][j] = fmaf(av[i], bv[j], acc[i][j]);
        }
#pragma unroll
        for (int i = 0; i < 4; i++) {
            int n = n0 + (tx << 2) + i;
            if (n < NN) {
                float4 hold = *(const float4*)&g_h[n * 64 + (ty << 2)];
                float h0 = hold.x + acc[i][0] + bb[0];
                float h1 = hold.y + acc[i][1] + bb[1];
                float h2 = hold.z + acc[i][2] + bb[2];
                float h3 = hold.w + acc[i][3] + bb[3];
                float4 hv = make_float4(h0, h1, h2, h3);
                *(float4*)&g_h[n * 64 + (ty << 2)] = hv;
                *(float4*)&g_u[(size_t)n * 128 + (ty << 2)] = hv;
            }
        }
        if (tid < 64) {
            int n = n0 + tid;
            if (n < NN) {
                g_pos[n * 3 + 0] += g_aggr_p[n * 3 + 0];
                g_pos[n * 3 + 1] += g_aggr_p[n * 3 + 1];
                g_pos[n * 3 + 2] += g_aggr_p[n * 3 + 2];
            }
        }
    }
}

// ---------------- pooling ----------------
__global__ void k_pool(const int* __restrict__ batch)
{
    int idx = blockIdx.x * blockDim.x + threadIdx.x;
    if (idx >= NN * 16) return;
    int n = idx >> 4, c4 = (idx & 15) * 4;
    int b = batch[n];
    float4 h = *(const float4*)&g_h[n * 64 + c4];
    red_add_v4(&g_pool[b * 64 + c4], h.x, h.y, h.z, h.w);
    if (c4 == 0) atomicAdd(&g_cnt[b], 1.0f);
}

__global__ void k_pred(const float* __restrict__ w, const float* __restrict__ b,
                       float* __restrict__ out)
{
    int g = blockIdx.x, lane = threadIdx.x;
    float p = g_pool[g * 64 + lane] * w[lane] + g_pool[g * 64 + 32 + lane] * w[32 + lane];
#pragma unroll
    for (int o = 16; o > 0; o >>= 1) p += __shfl_xor_sync(0xffffffffu, p, o);
    if (lane == 0) out[g] = p / fmaxf(g_cnt[g], 1.0f) + b[0];
}

// ---------------- launch ----------------
extern "C" void kernel_launch(void* const* d_in, const int* in_sizes, int n_in,
                              void* d_out, int out_size)
{
    const float* node_s    = (const float*)d_in[0];
    const float* node_type = (const float*)d_in[1];
    const float* pos       = (const float*)d_in[2];
    const int*   ei        = (const int*)d_in[3];
    const float* edge_s    = (const float*)d_in[4];
    const int*   batch     = (const int*)d_in[5];
    const float* lin_in_w  = (const float*)d_in[6];
    const float* lin_in_b  = (const float*)d_in[7];
    const float* msg_w1    = (const float*)d_in[8];
    const float* msg_b1    = (const float*)d_in[9];
    const float* msg_g1    = (const float*)d_in[10];
    const float* msg_be1   = (const float*)d_in[11];
    const float* msg_w2    = (const float*)d_in[12];
    const float* msg_b2    = (const float*)d_in[13];
    const float* msg_g2    = (const float*)d_in[14];
    const float* msg_be2   = (const float*)d_in[15];
    const float* updf_w1   = (const float*)d_in[16];
    const float* updf_b1   = (const float*)d_in[17];
    const float* updf_g1   = (const float*)d_in[18];
    const float* updf_be1  = (const float*)d_in[19];
    const float* updf_w2   = (const float*)d_in[20];
    const float* updf_b2   = (const float*)d_in[21];
    const float* updc_w1   = (const float*)d_in[22];
    const float* updc_b1   = (const float*)d_in[23];
    const float* updc_g1   = (const float*)d_in[24];
    const float* updc_be1  = (const float*)d_in[25];
    const float* updc_w2   = (const float*)d_in[26];
    const float* updc_b2   = (const float*)d_in[27];
    const float* lin_pred_w = (const float*)d_in[28];
    const float* lin_pred_b = (const float*)d_in[29];

    k_init<<<(NN * 64 + 255) / 256, 256>>>(node_s, node_type, pos, lin_in_w, lin_in_b);
    k_hist<<<(NE + 255) / 256, 256>>>(ei);
    k_scan<<<1, 1024>>>();
    k_fill<<<(NE + 255) / 256, 256>>>(ei);
    k_wpack_all<<<(NL * 64 * 256 + 255) / 256, 256>>>(msg_w1, updc_w1);

    for (int l = 0; l < NL; l++) {
        const float* mw1 = msg_w1 + (size_t)l * 64 * 161;
        const float* mb1 = msg_b1 + l * 64;
        const float* mw2 = msg_w2 + (size_t)l * 64 * 64;
        const float* mb2 = msg_b2 + l * 64;
        const float* cw1 = updc_w1 + (size_t)l * 64 * 161;
        const float* cb1 = updc_b1 + l * 64;
        const float* cw2 = updc_w2 + (size_t)l * 64;
        const float* cb2 = updc_b2 + l;
        const float* uw1 = updf_w1 + (size_t)l * 64 * 128;
        const float* ub1 = updf_b1 + l * 64;
        const float* uw2 = updf_w2 + (size_t)l * 64 * 64;
        const float* ub2 = updf_b2 + l * 64;

        k_hpre<<<592, 256>>>(l);
        k_edgeA<<<1036, 256>>>(ei, edge_s, mw1, mb1, cw1, cb1);
        k_bnfin<<<1, 128>>>(0, 128, 1.0 / NE,
                            msg_g1 + l * 64, msg_be1 + l * 64,
                            updc_g1 + l * 64, updc_be1 + l * 64);
        k_edgeB<<<1036, 256>>>(mw2, mb2, cw2, cb2);
        k_bnfin<<<1, 64>>>(128, 64, 1.0 / NE,
                           msg_g2 + l * 64, msg_be2 + l * 64,
                           msg_g2 + l * 64, msg_be2 + l * 64);
        k_aggr<<<(NN * 32 + 255) / 256, 256>>>(ei);
        k_node1<<<592, 256>>>(uw1, ub1);
        k_bnfin<<<1, 64>>>(192, 64, 1.0 / NN,
                           updf_g1 + l * 64, updf_be1 + l * 64,
                           updf_g1 + l * 64, updf_be1 + l * 64);
        k_node2<<<592, 256>>>(uw2, ub2);
    }

    k_pool<<<(NN * 16 + 255) / 256, 256>>>(batch);
    k_pred<<<NG, 32>>>(lin_pred_w, lin_pred_b, (float*)d_out);
}

// round 7
// speedup vs baseline: 1.4852x; 1.0328x over previous
#include <cuda_runtime.h>
#include <math.h>
#include <stdint.h>

#define NN 50000
#define NE 800000
#define NL 4
#define NG 64
#define EPS 1e-5f

// ---------------- static device scratch ----------------
__device__ __align__(16) float g_h[NN * 64];
__device__ __align__(16) float g_u[NN * 128];      // [h | aggr_h]
__device__ __align__(16) float g_un[NN * 64];
__device__ __align__(16) float g_pos[NN * 3];
__device__ __align__(16) float g_aggr_p[NN * 3];
__device__ __align__(16) float g_Hpre[(size_t)NN * 256];
__device__ __align__(16) float g_wpack4[NL][64 * 256];  // k-major [k][op]
__device__ __align__(16) float g_t1[(size_t)NE * 64];
__device__ __align__(16) float g_t2[(size_t)NE * 64];
__device__ __align__(16) float g_mlin[(size_t)NE * 64];  // CSR-ordered rows
__device__ __align__(16) float g_sc[NE];                 // CSR-ordered
__device__ int g_deg[NN];
__device__ int g_rowstart[NN + 1];
__device__ int g_cursor[NN];
__device__ int g_epos[NE];     // edge -> CSR position
__device__ int g_csrsrc[NE];   // CSR position -> src node
__device__ double g_sum[256];
__device__ double g_sumsq[256];
__device__ __align__(16) float g_bnA[256];
__device__ __align__(16) float g_bnB[256];
__device__ __align__(16) float g_pool[NG * 64];
__device__ float g_cnt[NG];

__device__ __forceinline__ float silu_f(float y) {
    return y * (1.0f / (1.0f + __expf(-y)));
}

__device__ __forceinline__ void red_add_v4(float* p, float a, float b, float c, float d) {
    asm volatile("red.global.add.v4.f32 [%0], {%1,%2,%3,%4};"
                 :: "l"(p), "f"(a), "f"(b), "f"(c), "f"(d) : "memory");
}

__device__ __forceinline__ uint32_t f2tf32(float f) {
    uint32_t u;
    asm("cvt.rna.tf32.f32 %0, %1;" : "=r"(u) : "f"(f));
    return u;
}

__device__ __forceinline__ void mma_tf32(float* c, uint32_t a0, uint32_t a1, uint32_t a2, uint32_t a3,
                                         uint32_t b0, uint32_t b1) {
    asm volatile("mma.sync.aligned.m16n8k8.row.col.f32.tf32.tf32.f32 "
                 "{%0,%1,%2,%3}, {%4,%5,%6,%7}, {%8,%9}, {%0,%1,%2,%3};"
                 : "+f"(c[0]), "+f"(c[1]), "+f"(c[2]), "+f"(c[3])
                 : "r"(a0), "r"(a1), "r"(a2), "r"(a3), "r"(b0), "r"(b1));
}

// ---------------- init ----------------
__global__ void k_init(const float* __restrict__ ns, const float* __restrict__ nt,
                       const float* __restrict__ pos, const float* __restrict__ w,
                       const float* __restrict__ b)
{
    int idx = blockIdx.x * blockDim.x + threadIdx.x;
    if (idx < NG * 64) g_pool[idx] = 0.f;
    if (idx < NG) g_cnt[idx] = 0.f;
    if (idx < 256) { g_sum[idx] = 0.0; g_sumsq[idx] = 0.0; }
    if (idx < NN) g_deg[idx] = 0;
    if (idx >= NN * 64) return;
    int n = idx >> 6, o = idx & 63;
    const float* wr = w + o * 8;
    const float* s = ns + n * 6;
    float acc = b[o];
#pragma unroll
    for (int i = 0; i < 6; i++) acc = fmaf(s[i], wr[i], acc);
    acc = fmaf(nt[n * 2 + 0], wr[6], acc);
    acc = fmaf(nt[n * 2 + 1], wr[7], acc);
    g_h[idx] = acc;
    g_u[(size_t)n * 128 + o] = acc;
    if (o < 3) g_pos[n * 3 + o] = pos[n * 3 + o];
}

// ---------------- CSR build ----------------
__global__ void k_hist(const int* __restrict__ ei)
{
    int e = blockIdx.x * blockDim.x + threadIdx.x;
    if (e < NE) atomicAdd(&g_deg[ei[NE + e]], 1);
}

__global__ __launch_bounds__(1024) void k_scan()
{
    __shared__ int ssum[1024];
    int t = threadIdx.x;
    const int C = 49;
    int begin = t * C;
    int end = begin + C; if (end > NN) end = NN;
    if (begin > NN) begin = NN;
    int s = 0;
    for (int i = begin; i < end; i++) s += g_deg[i];
    ssum[t] = s;
    __syncthreads();
    for (int off = 1; off < 1024; off <<= 1) {
        int v = (t >= off) ? ssum[t - off] : 0;
        __syncthreads();
        ssum[t] += v;
        __syncthreads();
    }
    int run = ssum[t] - s;
    for (int i = begin; i < end; i++) {
        g_rowstart[i] = run;
        g_cursor[i] = run;
        run += g_deg[i];
    }
    if (t == 1023) g_rowstart[NN] = ssum[1023];
}

__global__ void k_fill(const int* __restrict__ ei)
{
    int e = blockIdx.x * blockDim.x + threadIdx.x;
    if (e >= NE) return;
    int d = ei[NE + e];
    int p = atomicAdd(&g_cursor[d], 1);
    g_epos[e] = p;
    g_csrsrc[p] = ei[e];
}

// ---------------- pack h-columns of msg_w1/updc_w1 for ALL layers ----------------
__global__ void k_wpack_all(const float* __restrict__ mw1a, const float* __restrict__ cw1a)
{
    int idx = blockIdx.x * blockDim.x + threadIdx.x;
    if (idx >= NL * 64 * 256) return;
    int l = idx >> 14;
    int r = idx & 16383;
    int k = r >> 8, op = r & 255, o = op & 63;
    const float* mw1 = mw1a + (size_t)l * 64 * 161;
    const float* cw1 = cw1a + (size_t)l * 64 * 161;
    float v;
    if (op < 64)       v = mw1[o * 161 + k];
    else if (op < 128) v = mw1[o * 161 + 64 + k];
    else if (op < 192) v = cw1[o * 161 + k];
    else               v = cw1[o * 161 + 64 + k];
    g_wpack4[l][k * 256 + op] = v;
}

// ---------------- Hpre: tiled GEMM 64n x 128o (2 phases), K=64 ----------------
__global__ __launch_bounds__(256) void k_hpre(int layer)
{
    const float* wpack = g_wpack4[layer];
    __shared__ __align__(16) float sA[64][64];
    __shared__ __align__(16) float sB[64][128];
    int tid = threadIdx.x, tx = tid & 15, ty = tid >> 4;
    int ntiles = (NN + 63) >> 6;
    for (int t = blockIdx.x; t < ntiles; t += gridDim.x) {
        int n0 = t << 6;
        __syncthreads();
        {
            int nn = tid >> 2, k0 = (tid & 3) << 4;
            int n = n0 + nn;
#pragma unroll
            for (int m = 0; m < 4; m++) {
                float4 v = (n < NN) ? *(const float4*)&g_h[n * 64 + k0 + 4 * m]
                                    : make_float4(0.f, 0.f, 0.f, 0.f);
                sA[k0 + 4 * m + 0][nn] = v.x;
                sA[k0 + 4 * m + 1][nn] = v.y;
                sA[k0 + 4 * m + 2][nn] = v.z;
                sA[k0 + 4 * m + 3][nn] = v.w;
            }
        }
        for (int ph = 0; ph < 2; ph++) {
            __syncthreads();
#pragma unroll
            for (int r = 0; r < 8; r++) {
                int i = tid + r * 256;
                int k = i >> 5, o4 = (i & 31) << 2;
                *(float4*)&sB[k][o4] = *(const float4*)&wpack[k * 256 + ph * 128 + o4];
            }
            __syncthreads();
            float acc[4][8];
#pragma unroll
            for (int i = 0; i < 4; i++)
#pragma unroll
                for (int j = 0; j < 8; j++) acc[i][j] = 0.f;
#pragma unroll 4
            for (int k = 0; k < 64; k++) {
                float4 a = *(const float4*)&sA[k][tx << 2];
                float4 b0 = *(const float4*)&sB[k][ty << 3];
                float4 b1 = *(const float4*)&sB[k][(ty << 3) + 4];
                float av[4] = {a.x, a.y, a.z, a.w};
                float bv[8] = {b0.x, b0.y, b0.z, b0.w, b1.x, b1.y, b1.z, b1.w};
#pragma unroll
                for (int i = 0; i < 4; i++)
#pragma unroll
                    for (int j = 0; j < 8; j++) acc[i][j] = fmaf(av[i], bv[j], acc[i][j]);
            }
#pragma unroll
            for (int i = 0; i < 4; i++) {
                int n = n0 + (tx << 2) + i;
                if (n < NN) {
                    float* out = &g_Hpre[(size_t)n * 256 + ph * 128 + (ty << 3)];
                    *(float4*)out = make_float4(acc[i][0], acc[i][1], acc[i][2], acc[i][3]);
                    *(float4*)(out + 4) = make_float4(acc[i][4], acc[i][5], acc[i][6], acc[i][7]);
                }
            }
        }
    }
}

// ---------------- edge A: tiled, 64 edges x 128 ch, K=32 + gather init ----------------
__global__ __launch_bounds__(256) void k_edgeA(const int* __restrict__ ei, const float* __restrict__ es,
                                               const float* __restrict__ mw1, const float* __restrict__ mb1,
                                               const float* __restrict__ cw1, const float* __restrict__ cb1)
{
    __shared__ __align__(16) float sWes[32][128];
    __shared__ float sWr[128], sBias[128];
    __shared__ __align__(16) float sEs[32][68];
    __shared__ float sR[64];
    __shared__ int sSrc[64], sDst[64];
    __shared__ float sS[128], sQ[128];
    int tid = threadIdx.x, tx = tid & 15, ty = tid >> 4;
    for (int i = tid; i < 32 * 128; i += 256) {
        int k = i >> 7, ch = i & 127;
        sWes[k][ch] = (ch < 64) ? mw1[ch * 161 + 129 + k] : cw1[(ch - 64) * 161 + 129 + k];
    }
    if (tid < 128) {
        sWr[tid]  = (tid < 64) ? mw1[tid * 161 + 128] : cw1[(tid - 64) * 161 + 128];
        sBias[tid] = (tid < 64) ? mb1[tid] : cb1[tid - 64];
        sS[tid] = 0.f; sQ[tid] = 0.f;
    }
    __syncthreads();
    int ch0 = ty << 3;
    int dstoff = (ch0 < 64) ? ch0 : 64 + ch0;
    float wr[8], bb[8];
#pragma unroll
    for (int j = 0; j < 8; j++) { wr[j] = sWr[ch0 + j]; bb[j] = sBias[ch0 + j]; }
    float st[8], sq[8];
#pragma unroll
    for (int j = 0; j < 8; j++) { st[j] = 0.f; sq[j] = 0.f; }

    for (int t = blockIdx.x; t < NE / 64; t += gridDim.x) {
        int e0 = t << 6;
        __syncthreads();
        if (tid < 64) {
            int e = e0 + tid;
            int s = ei[e], d = ei[NE + e];
            sSrc[tid] = s; sDst[tid] = d;
            float dx = g_pos[d * 3] - g_pos[s * 3];
            float dy = g_pos[d * 3 + 1] - g_pos[s * 3 + 1];
            float dz = g_pos[d * 3 + 2] - g_pos[s * 3 + 2];
            sR[tid] = sqrtf(dx * dx + dy * dy + dz * dz);
        }
        {
            int el = tid >> 2, k0 = (tid & 3) << 3;
            const float* ep = &es[(size_t)(e0 + el) * 32 + k0];
            float4 v0 = *(const float4*)ep;
            float4 v1 = *(const float4*)(ep + 4);
            sEs[k0 + 0][el] = v0.x; sEs[k0 + 1][el] = v0.y;
            sEs[k0 + 2][el] = v0.z; sEs[k0 + 3][el] = v0.w;
            sEs[k0 + 4][el] = v1.x; sEs[k0 + 5][el] = v1.y;
            sEs[k0 + 6][el] = v1.z; sEs[k0 + 7][el] = v1.w;
        }
        __syncthreads();
        float acc[4][8];
#pragma unroll
        for (int i = 0; i < 4; i++) {
            int el = (tx << 2) + i;
            int d = sDst[el], s = sSrc[el];
            float r = sR[el];
            const float* hdp = &g_Hpre[(size_t)d * 256 + dstoff];
            const float* hsp = &g_Hpre[(size_t)s * 256 + dstoff + 64];
            float4 hd0 = *(const float4*)hdp;
            float4 hd1 = *(const float4*)(hdp + 4);
            float4 hs0 = *(const float4*)hsp;
            float4 hs1 = *(const float4*)(hsp + 4);
            acc[i][0] = hd0.x + hs0.x + fmaf(r, wr[0], bb[0]);
            acc[i][1] = hd0.y + hs0.y + fmaf(r, wr[1], bb[1]);
            acc[i][2] = hd0.z + hs0.z + fmaf(r, wr[2], bb[2]);
            acc[i][3] = hd0.w + hs0.w + fmaf(r, wr[3], bb[3]);
            acc[i][4] = hd1.x + hs1.x + fmaf(r, wr[4], bb[4]);
            acc[i][5] = hd1.y + hs1.y + fmaf(r, wr[5], bb[5]);
            acc[i][6] = hd1.z + hs1.z + fmaf(r, wr[6], bb[6]);
            acc[i][7] = hd1.w + hs1.w + fmaf(r, wr[7], bb[7]);
        }
#pragma unroll 4
        for (int k = 0; k < 32; k++) {
            float4 a = *(const float4*)&sEs[k][tx << 2];
            float4 b0 = *(const float4*)&sWes[k][ch0];
            float4 b1 = *(const float4*)&sWes[k][ch0 + 4];
            float av[4] = {a.x, a.y, a.z, a.w};
            float bv[8] = {b0.x, b0.y, b0.z, b0.w, b1.x, b1.y, b1.z, b1.w};
#pragma unroll
            for (int i = 0; i < 4; i++)
#pragma unroll
                for (int j = 0; j < 8; j++) acc[i][j] = fmaf(av[i], bv[j], acc[i][j]);
        }
#pragma unroll
        for (int i = 0; i < 4; i++) {
            int e = e0 + (tx << 2) + i;
            float4 c0 = make_float4(acc[i][0], acc[i][1], acc[i][2], acc[i][3]);
            float4 c1 = make_float4(acc[i][4], acc[i][5], acc[i][6], acc[i][7]);
            float* out = (ch0 < 64) ? &g_t1[(size_t)e * 64 + ch0]
                                    : &g_t2[(size_t)e * 64 + ch0 - 64];
            *(float4*)out = c0;
            *(float4*)(out + 4) = c1;
#pragma unroll
            for (int j = 0; j < 8; j++) { st[j] += acc[i][j]; sq[j] += acc[i][j] * acc[i][j]; }
        }
    }
    __syncthreads();
#pragma unroll
    for (int j = 0; j < 8; j++) { atomicAdd(&sS[ch0 + j], st[j]); atomicAdd(&sQ[ch0 + j], sq[j]); }
    __syncthreads();
    if (tid < 128) {
        atomicAdd(&g_sum[tid], (double)sS[tid]);
        atomicAdd(&g_sumsq[tid], (double)sQ[tid]);
    }
}

// ---------------- BN finalize (self-resetting stats) ----------------
__global__ void k_bnfin(int off, int n, double inv,
                        const float* __restrict__ g0, const float* __restrict__ b0,
                        const float* __restrict__ g1, const float* __restrict__ b1)
{
    int c = threadIdx.x;
    if (c >= n) return;
    double m = g_sum[off + c] * inv;
    double v = g_sumsq[off + c] * inv - m * m;
    g_sum[off + c] = 0.0;
    g_sumsq[off + c] = 0.0;
    float gg = (c < 64) ? g0[c] : g1[c - 64];
    float bb = (c < 64) ? b0[c] : b1[c - 64];
    float A = gg * rsqrtf((float)v + EPS);
    g_bnA[off + c] = A;
    g_bnB[off + c] = bb - (float)m * A;
}

// ---------------- edge B (tf32 MMA, 3xTF32): mlin = silu(bn(t1)) @ msg_w2^T + b ----------------
// 128 threads, 4 warps; tile = 64 edges x 64 out. Warp w covers out rows [16w,16w+16).
// W fragments pre-split in registers; X staged hi/lo tf32 in smem; mlin/sc written CSR-ordered.
__global__ __launch_bounds__(128) void k_edgeBmma(const float* __restrict__ mw2, const float* __restrict__ mb2,
                                                  const float* __restrict__ cw2, const float* __restrict__ cb2)
{
    __shared__ uint32_t sXh[64][68];
    __shared__ uint32_t sXl[64][68];
    __shared__ int sEp[64];
    __shared__ float sS[64], sQ[64];
    __shared__ float sCA[64], sCB[64], sDA[64], sDB[64], sWc2[64];

    int tid = threadIdx.x;
    int warp = tid >> 5, lane = tid & 31;
    int gid = lane >> 2, tig = lane & 3;
    int m0 = warp << 4;

    if (tid < 64) {
        sS[tid] = 0.f; sQ[tid] = 0.f;
        sCA[tid] = g_bnA[tid];        sCB[tid] = g_bnB[tid];
        sDA[tid] = g_bnA[64 + tid];   sDB[tid] = g_bnB[64 + tid];
        sWc2[tid] = cw2[tid];
    }

    // preload + split weight fragments: A[m][k] = mw2[m*64+k], rows m0+gid / m0+gid+8
    uint32_t ah[8][4], al[8][4];
    {
        const float* w0 = mw2 + (size_t)(m0 + gid) * 64;
        const float* w1 = mw2 + (size_t)(m0 + gid + 8) * 64;
#pragma unroll
        for (int kb = 0; kb < 8; kb++) {
            float f[4];
            f[0] = w0[kb * 8 + tig];     f[1] = w1[kb * 8 + tig];
            f[2] = w0[kb * 8 + tig + 4]; f[3] = w1[kb * 8 + tig + 4];
#pragma unroll
            for (int j = 0; j < 4; j++) {
                uint32_t h = f2tf32(f[j]);
                ah[kb][j] = h;
                al[kb][j] = f2tf32(f[j] - __uint_as_float(h));
            }
        }
    }
    float bias0 = mb2[m0 + gid], bias1 = mb2[m0 + gid + 8];
    float cbias = cb2[0];
    float s0 = 0.f, q0 = 0.f, s1 = 0.f, q1 = 0.f;

    int el = tid >> 1, half = tid & 1;

    for (int t = blockIdx.x; t < NE / 64; t += gridDim.x) {
        int e0 = t << 6;
        __syncthreads();
        if (tid < 64) sEp[tid] = g_epos[e0 + tid];
        // stage X = silu(bn1(t1)) as tf32 hi/lo
        {
            const float4* tb = (const float4*)&g_t1[(size_t)(e0 + el) * 64 + half * 32];
#pragma unroll
            for (int m = 0; m < 8; m++) {
                float4 v = tb[m];
                int c = half * 32 + 4 * m;
                float x0 = silu_f(fmaf(v.x, sCA[c], sCB[c]));
                float x1 = silu_f(fmaf(v.y, sCA[c + 1], sCB[c + 1]));
                float x2 = silu_f(fmaf(v.z, sCA[c + 2], sCB[c + 2]));
                float x3 = silu_f(fmaf(v.w, sCA[c + 3], sCB[c + 3]));
                uint32_t h0 = f2tf32(x0), h1 = f2tf32(x1), h2 = f2tf32(x2), h3 = f2tf32(x3);
                *(uint4*)&sXh[el][c] = make_uint4(h0, h1, h2, h3);
                *(uint4*)&sXl[el][c] = make_uint4(
                    f2tf32(x0 - __uint_as_float(h0)), f2tf32(x1 - __uint_as_float(h1)),
                    f2tf32(x2 - __uint_as_float(h2)), f2tf32(x3 - __uint_as_float(h3)));
            }
        }
        // coord head (scalar): 2 threads per edge, 32 ch each
        {
            const float4* tb = (const float4*)&g_t2[(size_t)(e0 + el) * 64 + half * 32];
            float part = 0.f;
#pragma unroll
            for (int m = 0; m < 8; m++) {
                float4 v = tb[m];
                int c = half * 32 + 4 * m;
                part += silu_f(fmaf(v.x, sDA[c], sDB[c])) * sWc2[c];
                part += silu_f(fmaf(v.y, sDA[c + 1], sDB[c + 1])) * sWc2[c + 1];
                part += silu_f(fmaf(v.z, sDA[c + 2], sDB[c + 2])) * sWc2[c + 2];
                part += silu_f(fmaf(v.w, sDA[c + 3], sDB[c + 3])) * sWc2[c + 3];
            }
            part += __shfl_xor_sync(0xffffffffu, part, 1);
            if (half == 0) g_sc[g_epos[e0 + el]] = part + cbias;
        }
        __syncthreads();
        // MMA: C[16 out][64 edges] per warp
        float c[8][4];
#pragma unroll
        for (int nb = 0; nb < 8; nb++)
#pragma unroll
            for (int j = 0; j < 4; j++) c[nb][j] = 0.f;
#pragma unroll
        for (int kb = 0; kb < 8; kb++) {
#pragma unroll
            for (int nb = 0; nb < 8; nb++) {
                uint32_t bh0 = sXh[nb * 8 + gid][kb * 8 + tig];
                uint32_t bh1 = sXh[nb * 8 + gid][kb * 8 + tig + 4];
                uint32_t bl0 = sXl[nb * 8 + gid][kb * 8 + tig];
                uint32_t bl1 = sXl[nb * 8 + gid][kb * 8 + tig + 4];
                mma_tf32(c[nb], ah[kb][0], ah[kb][1], ah[kb][2], ah[kb][3], bh0, bh1);
                mma_tf32(c[nb], ah[kb][0], ah[kb][1], ah[kb][2], ah[kb][3], bl0, bl1);
                mma_tf32(c[nb], al[kb][0], al[kb][1], al[kb][2], al[kb][3], bh0, bh1);
            }
        }
        __syncthreads();
        // epilogue: bias + stats, transpose through smem (reuse sXh as float buffer)
        float* sOut = (float*)&sXh[0][0];
#pragma unroll
        for (int nb = 0; nb < 8; nb++) {
            int e = nb * 8 + 2 * tig;
            float y00 = c[nb][0] + bias0;
            float y01 = c[nb][1] + bias0;
            float y10 = c[nb][2] + bias1;
            float y11 = c[nb][3] + bias1;
            sOut[e * 68 + m0 + gid] = y00;
            sOut[(e + 1) * 68 + m0 + gid] = y01;
            sOut[e * 68 + m0 + gid + 8] = y10;
            sOut[(e + 1) * 68 + m0 + gid + 8] = y11;
            s0 += y00 + y01; q0 += y00 * y00 + y01 * y01;
            s1 += y10 + y11; q1 += y10 * y10 + y11 * y11;
        }
        __syncthreads();
        // coalesced CSR-ordered write
        {
            float* dst = &g_mlin[(size_t)sEp[el] * 64 + half * 32];
            const float* src = &sOut[el * 68 + half * 32];
#pragma unroll
            for (int m = 0; m < 8; m++)
                *(float4*)(dst + 4 * m) = *(const float4*)(src + 4 * m);
        }
    }
    __syncthreads();
    atomicAdd(&sS[m0 + gid], s0); atomicAdd(&sQ[m0 + gid], q0);
    atomicAdd(&sS[m0 + gid + 8], s1); atomicAdd(&sQ[m0 + gid + 8], q1);
    __syncthreads();
    if (tid < 64) {
        atomicAdd(&g_sum[128 + tid], (double)sS[tid]);
        atomicAdd(&g_sumsq[128 + tid], (double)sQ[tid]);
    }
}

// ---------------- aggregation: warp per node, contiguous CSR rows ----------------
__global__ __launch_bounds__(256) void k_aggr()
{
    int gwarp = (blockIdx.x * blockDim.x + threadIdx.x) >> 5;
    int lane = threadIdx.x & 31;
    if (gwarp >= NN) return;
    int n = gwarp;
    int s0 = g_rowstart[n], s1 = g_rowstart[n + 1];
    float A0 = g_bnA[128 + lane], B0 = g_bnB[128 + lane];
    float A1 = g_bnA[160 + lane], B1 = g_bnB[160 + lane];
    float acc0 = 0.f, acc1 = 0.f;
    for (int i = s0; i < s1; i++) {
        float m0 = g_mlin[(size_t)i * 64 + lane];
        float m1 = g_mlin[(size_t)i * 64 + 32 + lane];
        acc0 += silu_f(fmaf(m0, A0, B0));
        acc1 += silu_f(fmaf(m1, A1, B1));
    }
    g_u[(size_t)n * 128 + 64 + lane] = acc0;
    g_u[(size_t)n * 128 + 96 + lane] = acc1;
    float px = g_pos[n * 3], py = g_pos[n * 3 + 1], pz = g_pos[n * 3 + 2];
    float cx = 0.f, cy = 0.f, cz = 0.f;
    for (int i = s0 + lane; i < s1; i += 32) {
        int src = g_csrsrc[i];
        float sc = g_sc[i];
        cx += sc * (px - g_pos[src * 3]);
        cy += sc * (py - g_pos[src * 3 + 1]);
        cz += sc * (pz - g_pos[src * 3 + 2]);
    }
#pragma unroll
    for (int o = 16; o > 0; o >>= 1) {
        cx += __shfl_xor_sync(0xffffffffu, cx, o);
        cy += __shfl_xor_sync(0xffffffffu, cy, o);
        cz += __shfl_xor_sync(0xffffffffu, cz, o);
    }
    if (lane == 0) {
        g_aggr_p[n * 3 + 0] = cx;
        g_aggr_p[n * 3 + 1] = cy;
        g_aggr_p[n * 3 + 2] = cz;
    }
}

// ---------------- node 1: tiled 64n x 64o, K=128 ----------------
__global__ __launch_bounds__(256) void k_node1(const float* __restrict__ uw1, const float* __restrict__ ub1)
{
    __shared__ __align__(16) float sW[64][64];
    __shared__ __align__(16) float sA[64][64];
    __shared__ float sS[64], sQ[64];
    int tid = threadIdx.x, tx = tid & 15, ty = tid >> 4;
    if (tid < 64) { sS[tid] = 0.f; sQ[tid] = 0.f; }
    float bb[4];
#pragma unroll
    for (int j = 0; j < 4; j++) bb[j] = ub1[(ty << 2) + j];
    float st[4] = {0.f, 0.f, 0.f, 0.f}, sq[4] = {0.f, 0.f, 0.f, 0.f};
    int ntiles = (NN + 63) >> 6;
    for (int t = blockIdx.x; t < ntiles; t += gridDim.x) {
        int n0 = t << 6;
        float acc[4][4];
#pragma unroll
        for (int i = 0; i < 4; i++)
#pragma unroll
            for (int j = 0; j < 4; j++) acc[i][j] = 0.f;
        for (int half = 0; half < 2; half++) {
            __syncthreads();
            for (int i = tid; i < 1024; i += 256) {
                int o = i & 63, k0 = (i >> 6) << 2;
                float4 v = *(const float4*)&uw1[o * 128 + half * 64 + k0];
                sW[k0 + 0][o] = v.x; sW[k0 + 1][o] = v.y;
                sW[k0 + 2][o] = v.z; sW[k0 + 3][o] = v.w;
            }
            {
                int nn = tid >> 2, k0 = (tid & 3) << 4;
                int n = n0 + nn;
#pragma unroll
                for (int m = 0; m < 4; m++) {
                    float4 v = (n < NN) ? *(const float4*)&g_u[(size_t)n * 128 + half * 64 + k0 + 4 * m]
                                        : make_float4(0.f, 0.f, 0.f, 0.f);
                    sA[k0 + 4 * m + 0][nn] = v.x;
                    sA[k0 + 4 * m + 1][nn] = v.y;
                    sA[k0 + 4 * m + 2][nn] = v.z;
                    sA[k0 + 4 * m + 3][nn] = v.w;
                }
            }
            __syncthreads();
#pragma unroll 4
            for (int k = 0; k < 64; k++) {
                float4 a = *(const float4*)&sA[k][tx << 2];
                float4 b = *(const float4*)&sW[k][ty << 2];
                float av[4] = {a.x, a.y, a.z, a.w};
                float bv[4] = {b.x, b.y, b.z, b.w};
#pragma unroll
                for (int i = 0; i < 4; i++)
#pragma unroll
                    for (int j = 0; j < 4; j++) acc[i][j] = fmaf(av[i], bv[j], acc[i][j]);
            }
        }
#pragma unroll
        for (int i = 0; i < 4; i++) {
            int n = n0 + (tx << 2) + i;
            if (n < NN) {
                float y0 = acc[i][0] + bb[0], y1 = acc[i][1] + bb[1];
                float y2 = acc[i][2] + bb[2], y3 = acc[i][3] + bb[3];
                *(float4*)&g_un[n * 64 + (ty << 2)] = make_float4(y0, y1, y2, y3);
                st[0] += y0; sq[0] += y0 * y0; st[1] += y1; sq[1] += y1 * y1;
                st[2] += y2; sq[2] += y2 * y2; st[3] += y3; sq[3] += y3 * y3;
            }
        }
    }
    __syncthreads();
#pragma unroll
    for (int j = 0; j < 4; j++) {
        atomicAdd(&sS[(ty << 2) + j], st[j]);
        atomicAdd(&sQ[(ty << 2) + j], sq[j]);
    }
    __syncthreads();
    if (tid < 64) {
        atomicAdd(&g_sum[192 + tid], (double)sS[tid]);
        atomicAdd(&g_sumsq[192 + tid], (double)sQ[tid]);
    }
}

// ---------------- node 2: tiled 64n x 64o, K=64; residual + pos update ----------------
__global__ __launch_bounds__(256) void k_node2(const float* __restrict__ uw2, const float* __restrict__ ub2)
{
    __shared__ __align__(16) float sW[64][64];
    __shared__ __align__(16) float sA[64][64];
    int tid = threadIdx.x, tx = tid & 15, ty = tid >> 4;
    for (int i = tid; i < 1024; i += 256) {
        int o = i & 63, k0 = (i >> 6) << 2;
        float4 v = *(const float4*)&uw2[o * 64 + k0];
        sW[k0 + 0][o] = v.x; sW[k0 + 1][o] = v.y;
        sW[k0 + 2][o] = v.z; sW[k0 + 3][o] = v.w;
    }
    int k0s = (tid & 3) << 4;
    float4 cA[4], cB[4];
#pragma unroll
    for (int m = 0; m < 4; m++) {
        cA[m] = *(const float4*)&g_bnA[192 + k0s + 4 * m];
        cB[m] = *(const float4*)&g_bnB[192 + k0s + 4 * m];
    }
    float bb[4];
#pragma unroll
    for (int j = 0; j < 4; j++) bb[j] = ub2[(ty << 2) + j];
    int ntiles = (NN + 63) >> 6;
    for (int t = blockIdx.x; t < ntiles; t += gridDim.x) {
        int n0 = t << 6;
        __syncthreads();
        {
            int nn = tid >> 2;
            int n = n0 + nn;
#pragma unroll
            for (int m = 0; m < 4; m++) {
                float4 v = (n < NN) ? *(const float4*)&g_un[(size_t)n * 64 + k0s + 4 * m]
                                    : make_float4(0.f, 0.f, 0.f, 0.f);
                sA[k0s + 4 * m + 0][nn] = silu_f(fmaf(v.x, cA[m].x, cB[m].x));
                sA[k0s + 4 * m + 1][nn] = silu_f(fmaf(v.y, cA[m].y, cB[m].y));
                sA[k0s + 4 * m + 2][nn] = silu_f(fmaf(v.z, cA[m].z, cB[m].z));
                sA[k0s + 4 * m + 3][nn] = silu_f(fmaf(v.w, cA[m].w, cB[m].w));
            }
        }
        __syncthreads();
        float acc[4][4];
#pragma unroll
        for (int i = 0; i < 4; i++)
#pragma unroll
            for (int j = 0; j < 4; j++) acc[i][j] = 0.f;
#pragma unroll 4
        for (int k = 0; k < 64; k++) {
            float4 a = *(const float4*)&sA[k][tx << 2];
            float4 b = *(const float4*)&sW[k][ty << 2];
            float av[4] = {a.x, a.y, a.z, a.w};
            float bv[4] = {b.x, b.y, b.z, b.w};
#pragma unroll
            for (int i = 0; i < 4; i++)
#pragma unroll
                for (int j = 0; j < 4; j++) acc[i][j] = fmaf(av[i], bv[j], acc[i][j]);
        }
#pragma unroll
        for (int i = 0; i < 4; i++) {
            int n = n0 + (tx << 2) + i;
            if (n < NN) {
                float4 hold = *(const float4*)&g_h[n * 64 + (ty << 2)];
                float h0 = hold.x + acc[i][0] + bb[0];
                float h1 = hold.y + acc[i][1] + bb[1];
                float h2 = hold.z + acc[i][2] + bb[2];
                float h3 = hold.w + acc[i][3] + bb[3];
                float4 hv = make_float4(h0, h1, h2, h3);
                *(float4*)&g_h[n * 64 + (ty << 2)] = hv;
                *(float4*)&g_u[(size_t)n * 128 + (ty << 2)] = hv;
            }
        }
        if (tid < 64) {
            int n = n0 + tid;
            if (n < NN) {
                g_pos[n * 3 + 0] += g_aggr_p[n * 3 + 0];
                g_pos[n * 3 + 1] += g_aggr_p[n * 3 + 1];
                g_pos[n * 3 + 2] += g_aggr_p[n * 3 + 2];
            }
        }
    }
}

// ---------------- pooling ----------------
__global__ void k_pool(const int* __restrict__ batch)
{
    int idx = blockIdx.x * blockDim.x + threadIdx.x;
    if (idx >= NN * 16) return;
    int n = idx >> 4, c4 = (idx & 15) * 4;
    int b = batch[n];
    float4 h = *(const float4*)&g_h[n * 64 + c4];
    red_add_v4(&g_pool[b * 64 + c4], h.x, h.y, h.z, h.w);
    if (c4 == 0) atomicAdd(&g_cnt[b], 1.0f);
}

__global__ void k_pred(const float* __restrict__ w, const float* __restrict__ b,
                       float* __restrict__ out)
{
    int g = blockIdx.x, lane = threadIdx.x;
    float p = g_pool[g * 64 + lane] * w[lane] + g_pool[g * 64 + 32 + lane] * w[32 + lane];
#pragma unroll
    for (int o = 16; o > 0; o >>= 1) p += __shfl_xor_sync(0xffffffffu, p, o);
    if (lane == 0) out[g] = p / fmaxf(g_cnt[g], 1.0f) + b[0];
}

// ---------------- launch ----------------
extern "C" void kernel_launch(void* const* d_in, const int* in_sizes, int n_in,
                              void* d_out, int out_size)
{
    const float* node_s    = (const float*)d_in[0];
    const float* node_type = (const float*)d_in[1];
    const float* pos       = (const float*)d_in[2];
    const int*   ei        = (const int*)d_in[3];
    const float* edge_s    = (const float*)d_in[4];
    const int*   batch     = (const int*)d_in[5];
    const float* lin_in_w  = (const float*)d_in[6];
    const float* lin_in_b  = (const float*)d_in[7];
    const float* msg_w1    = (const float*)d_in[8];
    const float* msg_b1    = (const float*)d_in[9];
    const float* msg_g1    = (const float*)d_in[10];
    const float* msg_be1   = (const float*)d_in[11];
    const float* msg_w2    = (const float*)d_in[12];
    const float* msg_b2    = (const float*)d_in[13];
    const float* msg_g2    = (const float*)d_in[14];
    const float* msg_be2   = (const float*)d_in[15];
    const float* updf_w1   = (const float*)d_in[16];
    const float* updf_b1   = (const float*)d_in[17];
    const float* updf_g1   = (const float*)d_in[18];
    const float* updf_be1  = (const float*)d_in[19];
    const float* updf_w2   = (const float*)d_in[20];
    const float* updf_b2   = (const float*)d_in[21];
    const float* updc_w1   = (const float*)d_in[22];
    const float* updc_b1   = (const float*)d_in[23];
    const float* updc_g1   = (const float*)d_in[24];
    const float* updc_be1  = (const float*)d_in[25];
    const float* updc_w2   = (const float*)d_in[26];
    const float* updc_b2   = (const float*)d_in[27];
    const float* lin_pred_w = (const float*)d_in[28];
    const float* lin_pred_b = (const float*)d_in[29];

    k_init<<<(NN * 64 + 255) / 256, 256>>>(node_s, node_type, pos, lin_in_w, lin_in_b);
    k_hist<<<(NE + 255) / 256, 256>>>(ei);
    k_scan<<<1, 1024>>>();
    k_fill<<<(NE + 255) / 256, 256>>>(ei);
    k_wpack_all<<<(NL * 64 * 256 + 255) / 256, 256>>>(msg_w1, updc_w1);

    for (int l = 0; l < NL; l++) {
        const float* mw1 = msg_w1 + (size_t)l * 64 * 161;
        const float* mb1 = msg_b1 + l * 64;
        const float* mw2 = msg_w2 + (size_t)l * 64 * 64;
        const float* mb2 = msg_b2 + l * 64;
        const float* cw1 = updc_w1 + (size_t)l * 64 * 161;
        const float* cb1 = updc_b1 + l * 64;
        const float* cw2 = updc_w2 + (size_t)l * 64;
        const float* cb2 = updc_b2 + l;
        const float* uw1 = updf_w1 + (size_t)l * 64 * 128;
        const float* ub1 = updf_b1 + l * 64;
        const float* uw2 = updf_w2 + (size_t)l * 64 * 64;
        const float* ub2 = updf_b2 + l * 64;

        k_hpre<<<592, 256>>>(l);
        k_edgeA<<<1036, 256>>>(ei, edge_s, mw1, mb1, cw1, cb1);
        k_bnfin<<<1, 128>>>(0, 128, 1.0 / NE,
                            msg_g1 + l * 64, msg_be1 + l * 64,
                            updc_g1 + l * 64, updc_be1 + l * 64);
        k_edgeBmma<<<592, 128>>>(mw2, mb2, cw2, cb2);
        k_bnfin<<<1, 64>>>(128, 64, 1.0 / NE,
                           msg_g2 + l * 64, msg_be2 + l * 64,
                           msg_g2 + l * 64, msg_be2 + l * 64);
        k_aggr<<<(NN * 32 + 255) / 256, 256>>>();
        k_node1<<<592, 256>>>(uw1, ub1);
        k_bnfin<<<1, 64>>>(192, 64, 1.0 / NN,
                           updf_g1 + l * 64, updf_be1 + l * 64,
                           updf_g1 + l * 64, updf_be1 + l * 64);
        k_node2<<<592, 256>>>(uw2, ub2);
    }

    k_pool<<<(NN * 16 + 255) / 256, 256>>>(batch);
    k_pred<<<NG, 32>>>(lin_pred_w, lin_pred_b, (float*)d_out);
}

// round 8
// speedup vs baseline: 1.5276x; 1.0286x over previous
#include <cuda_runtime.h>
#include <math.h>
#include <stdint.h>

#define NN 50000
#define NE 800000
#define NL 4
#define NG 64
#define EPS 1e-5f

// ---------------- static device scratch ----------------
__device__ __align__(16) float g_h[NN * 64];
__device__ __align__(16) float g_u[NN * 128];      // [h | aggr_h]
__device__ __align__(16) float g_un[NN * 64];
__device__ __align__(16) float g_pos[NN * 3];
__device__ __align__(16) float g_aggr_p[NN * 3];
__device__ __align__(16) float g_Hpre[(size_t)NN * 256];
__device__ __align__(16) float g_wpack4[NL][64 * 256];  // k-major [k][op]
__device__ __align__(16) float g_t1[(size_t)NE * 64];
__device__ __align__(16) float g_t2[(size_t)NE * 64];
__device__ __align__(16) float g_mlin[(size_t)NE * 64];  // CSR-ordered rows
__device__ __align__(16) float g_sc[NE];                 // CSR-ordered
__device__ int g_deg[NN];
__device__ int g_rowstart[NN + 1];
__device__ int g_cursor[NN];
__device__ int g_epos[NE];     // edge -> CSR position
__device__ int g_csrsrc[NE];   // CSR position -> src node
__device__ double g_sum[256];
__device__ double g_sumsq[256];
__device__ __align__(16) float g_bnA[256];
__device__ __align__(16) float g_bnB[256];
__device__ __align__(16) float g_pool[NG * 64];
__device__ float g_cnt[NG];

__device__ __forceinline__ float silu_f(float y) {
    return y * (1.0f / (1.0f + __expf(-y)));
}

__device__ __forceinline__ void red_add_v4(float* p, float a, float b, float c, float d) {
    asm volatile("red.global.add.v4.f32 [%0], {%1,%2,%3,%4};"
                 :: "l"(p), "f"(a), "f"(b), "f"(c), "f"(d) : "memory");
}

__device__ __forceinline__ uint32_t f2tf32(float f) {
    uint32_t u;
    asm("cvt.rna.tf32.f32 %0, %1;" : "=r"(u) : "f"(f));
    return u;
}

__device__ __forceinline__ void mma_tf32(float* c, uint32_t a0, uint32_t a1, uint32_t a2, uint32_t a3,
                                         uint32_t b0, uint32_t b1) {
    asm volatile("mma.sync.aligned.m16n8k8.row.col.f32.tf32.tf32.f32 "
                 "{%0,%1,%2,%3}, {%4,%5,%6,%7}, {%8,%9}, {%0,%1,%2,%3};"
                 : "+f"(c[0]), "+f"(c[1]), "+f"(c[2]), "+f"(c[3])
                 : "r"(a0), "r"(a1), "r"(a2), "r"(a3), "r"(b0), "r"(b1));
}

// ---------------- init ----------------
__global__ void k_init(const float* __restrict__ ns, const float* __restrict__ nt,
                       const float* __restrict__ pos, const float* __restrict__ w,
                       const float* __restrict__ b)
{
    int idx = blockIdx.x * blockDim.x + threadIdx.x;
    if (idx < NG * 64) g_pool[idx] = 0.f;
    if (idx < NG) g_cnt[idx] = 0.f;
    if (idx < 256) { g_sum[idx] = 0.0; g_sumsq[idx] = 0.0; }
    if (idx < NN) g_deg[idx] = 0;
    if (idx >= NN * 64) return;
    int n = idx >> 6, o = idx & 63;
    const float* wr = w + o * 8;
    const float* s = ns + n * 6;
    float acc = b[o];
#pragma unroll
    for (int i = 0; i < 6; i++) acc = fmaf(s[i], wr[i], acc);
    acc = fmaf(nt[n * 2 + 0], wr[6], acc);
    acc = fmaf(nt[n * 2 + 1], wr[7], acc);
    g_h[idx] = acc;
    g_u[(size_t)n * 128 + o] = acc;
    if (o < 3) g_pos[n * 3 + o] = pos[n * 3 + o];
}

// ---------------- CSR build ----------------
__global__ void k_hist(const int* __restrict__ ei)
{
    int e = blockIdx.x * blockDim.x + threadIdx.x;
    if (e < NE) atomicAdd(&g_deg[ei[NE + e]], 1);
}

__global__ __launch_bounds__(1024) void k_scan()
{
    __shared__ int ssum[1024];
    int t = threadIdx.x;
    const int C = 49;
    int begin = t * C;
    int end = begin + C; if (end > NN) end = NN;
    if (begin > NN) begin = NN;
    int s = 0;
    for (int i = begin; i < end; i++) s += g_deg[i];
    ssum[t] = s;
    __syncthreads();
    for (int off = 1; off < 1024; off <<= 1) {
        int v = (t >= off) ? ssum[t - off] : 0;
        __syncthreads();
        ssum[t] += v;
        __syncthreads();
    }
    int run = ssum[t] - s;
    for (int i = begin; i < end; i++) {
        g_rowstart[i] = run;
        g_cursor[i] = run;
        run += g_deg[i];
    }
    if (t == 1023) g_rowstart[NN] = ssum[1023];
}

__global__ void k_fill(const int* __restrict__ ei)
{
    int e = blockIdx.x * blockDim.x + threadIdx.x;
    if (e >= NE) return;
    int d = ei[NE + e];
    int p = atomicAdd(&g_cursor[d], 1);
    g_epos[e] = p;
    g_csrsrc[p] = ei[e];
}

// ---------------- pack h-columns of msg_w1/updc_w1 for ALL layers ----------------
__global__ void k_wpack_all(const float* __restrict__ mw1a, const float* __restrict__ cw1a)
{
    int idx = blockIdx.x * blockDim.x + threadIdx.x;
    if (idx >= NL * 64 * 256) return;
    int l = idx >> 14;
    int r = idx & 16383;
    int k = r >> 8, op = r & 255, o = op & 63;
    const float* mw1 = mw1a + (size_t)l * 64 * 161;
    const float* cw1 = cw1a + (size_t)l * 64 * 161;
    float v;
    if (op < 64)       v = mw1[o * 161 + k];
    else if (op < 128) v = mw1[o * 161 + 64 + k];
    else if (op < 192) v = cw1[o * 161 + k];
    else               v = cw1[o * 161 + 64 + k];
    g_wpack4[l][k * 256 + op] = v;
}

// ---------------- Hpre: tiled GEMM 64n x 128o (2 phases), K=64 ----------------
__global__ __launch_bounds__(256) void k_hpre(int layer)
{
    const float* wpack = g_wpack4[layer];
    __shared__ __align__(16) float sA[64][64];
    __shared__ __align__(16) float sB[64][128];
    int tid = threadIdx.x, tx = tid & 15, ty = tid >> 4;
    int ntiles = (NN + 63) >> 6;
    for (int t = blockIdx.x; t < ntiles; t += gridDim.x) {
        int n0 = t << 6;
        __syncthreads();
        {
            int nn = tid >> 2, k0 = (tid & 3) << 4;
            int n = n0 + nn;
#pragma unroll
            for (int m = 0; m < 4; m++) {
                float4 v = (n < NN) ? *(const float4*)&g_h[n * 64 + k0 + 4 * m]
                                    : make_float4(0.f, 0.f, 0.f, 0.f);
                sA[k0 + 4 * m + 0][nn] = v.x;
                sA[k0 + 4 * m + 1][nn] = v.y;
                sA[k0 + 4 * m + 2][nn] = v.z;
                sA[k0 + 4 * m + 3][nn] = v.w;
            }
        }
        for (int ph = 0; ph < 2; ph++) {
            __syncthreads();
#pragma unroll
            for (int r = 0; r < 8; r++) {
                int i = tid + r * 256;
                int k = i >> 5, o4 = (i & 31) << 2;
                *(float4*)&sB[k][o4] = *(const float4*)&wpack[k * 256 + ph * 128 + o4];
            }
            __syncthreads();
            float acc[4][8];
#pragma unroll
            for (int i = 0; i < 4; i++)
#pragma unroll
                for (int j = 0; j < 8; j++) acc[i][j] = 0.f;
#pragma unroll 4
            for (int k = 0; k < 64; k++) {
                float4 a = *(const float4*)&sA[k][tx << 2];
                float4 b0 = *(const float4*)&sB[k][ty << 3];
                float4 b1 = *(const float4*)&sB[k][(ty << 3) + 4];
                float av[4] = {a.x, a.y, a.z, a.w};
                float bv[8] = {b0.x, b0.y, b0.z, b0.w, b1.x, b1.y, b1.z, b1.w};
#pragma unroll
                for (int i = 0; i < 4; i++)
#pragma unroll
                    for (int j = 0; j < 8; j++) acc[i][j] = fmaf(av[i], bv[j], acc[i][j]);
            }
#pragma unroll
            for (int i = 0; i < 4; i++) {
                int n = n0 + (tx << 2) + i;
                if (n < NN) {
                    float* out = &g_Hpre[(size_t)n * 256 + ph * 128 + (ty << 3)];
                    *(float4*)out = make_float4(acc[i][0], acc[i][1], acc[i][2], acc[i][3]);
                    *(float4*)(out + 4) = make_float4(acc[i][4], acc[i][5], acc[i][6], acc[i][7]);
                }
            }
        }
    }
}

// ---------------- edge A (tf32 MMA): t1/t2 = Hpre gather + r*wr + es@Wes^T + b ----------------
// 128 threads, 4 warps; tile = 64 edges x 128 ch. Warp w covers ch [32w, 32w+32).
__global__ __launch_bounds__(128) void k_edgeAmma(const int* __restrict__ ei, const float* __restrict__ es,
                                                  const float* __restrict__ mw1, const float* __restrict__ mb1,
                                                  const float* __restrict__ cw1, const float* __restrict__ cb1)
{
    // union buffer: staging B (es hi/lo) while MMA runs, then output transpose
    __shared__ __align__(16) uint32_t sBuf[64 * 132];      // 33.8KB
    uint32_t (*sBh)[36] = (uint32_t(*)[36])sBuf;           // [64][36]
    uint32_t (*sBl)[36] = (uint32_t(*)[36])(sBuf + 64 * 36);
    float (*sOut)[132] = (float(*)[132])sBuf;              // [64][132]
    __shared__ float sR[64];
    __shared__ int sSrc[64], sDst[64];
    __shared__ float sS[128], sQ[128];

    int tid = threadIdx.x;
    int warp = tid >> 5, lane = tid & 31;
    int gid = lane >> 2, tig = lane & 3;

    if (tid < 128) { sS[tid] = 0.f; sQ[tid] = 0.f; }

    // weight W(ch, k): ch<64: mw1[ch*161+129+k]; else cw1[(ch-64)*161+129+k]
    // A fragments: 2 m16 tiles per warp; rows = warp*32 + mt*16 + gid (+8)
    uint32_t ah[2][4][4], al[2][4][4];
#pragma unroll
    for (int mt = 0; mt < 2; mt++) {
        int r0 = warp * 32 + mt * 16 + gid;
        int r1 = r0 + 8;
        const float* w0 = (r0 < 64) ? &mw1[r0 * 161 + 129] : &cw1[(r0 - 64) * 161 + 129];
        const float* w1 = (r1 < 64) ? &mw1[r1 * 161 + 129] : &cw1[(r1 - 64) * 161 + 129];
#pragma unroll
        for (int kb = 0; kb < 4; kb++) {
            float f[4];
            f[0] = w0[kb * 8 + tig];     f[1] = w1[kb * 8 + tig];
            f[2] = w0[kb * 8 + tig + 4]; f[3] = w1[kb * 8 + tig + 4];
#pragma unroll
            for (int j = 0; j < 4; j++) {
                uint32_t h = f2tf32(f[j]);
                ah[mt][kb][j] = h;
                al[mt][kb][j] = f2tf32(f[j] - __uint_as_float(h));
            }
        }
    }
    // per-thread fixed 4 channels for epilogue: ch0 = lane*4
    int ch0 = lane << 2;
    float wr4[4], bb4[4];
#pragma unroll
    for (int j = 0; j < 4; j++) {
        int ch = ch0 + j;
        wr4[j] = (ch < 64) ? mw1[ch * 161 + 128] : cw1[(ch - 64) * 161 + 128];
        bb4[j] = (ch < 64) ? mb1[ch] : cb1[ch - 64];
    }
    int hd_off = (ch0 < 64) ? ch0 : 64 + ch0;        // dst block offset
    int hs_off = (ch0 < 64) ? 64 + ch0 : 128 + ch0;  // src block offset
    float st[4] = {0.f, 0.f, 0.f, 0.f}, sq[4] = {0.f, 0.f, 0.f, 0.f};

    for (int t = blockIdx.x; t < NE / 64; t += gridDim.x) {
        int e0 = t << 6;
        __syncthreads();
        // stage edge meta
        if (tid < 64) {
            int e = e0 + tid;
            int s = ei[e], d = ei[NE + e];
            sSrc[tid] = s; sDst[tid] = d;
            float dx = g_pos[d * 3] - g_pos[s * 3];
            float dy = g_pos[d * 3 + 1] - g_pos[s * 3 + 1];
            float dz = g_pos[d * 3 + 2] - g_pos[s * 3 + 2];
            sR[tid] = sqrtf(dx * dx + dy * dy + dz * dz);
        }
        // stage es as tf32 hi/lo [edge][k]
        {
            int el = tid >> 1, koff = (tid & 1) * 16;
            const float4* ep = (const float4*)&es[(size_t)(e0 + el) * 32 + koff];
#pragma unroll
            for (int m = 0; m < 4; m++) {
                float4 v = ep[m];
                uint32_t h0 = f2tf32(v.x), h1 = f2tf32(v.y), h2 = f2tf32(v.z), h3 = f2tf32(v.w);
                sBh[el][koff + 4 * m + 0] = h0;
                sBh[el][koff + 4 * m + 1] = h1;
                sBh[el][koff + 4 * m + 2] = h2;
                sBh[el][koff + 4 * m + 3] = h3;
                sBl[el][koff + 4 * m + 0] = f2tf32(v.x - __uint_as_float(h0));
                sBl[el][koff + 4 * m + 1] = f2tf32(v.y - __uint_as_float(h1));
                sBl[el][koff + 4 * m + 2] = f2tf32(v.z - __uint_as_float(h2));
                sBl[el][koff + 4 * m + 3] = f2tf32(v.w - __uint_as_float(h3));
            }
        }
        __syncthreads();
        // MMA: per warp C[32 ch][64 edges]
        float c[2][8][4];
#pragma unroll
        for (int mt = 0; mt < 2; mt++)
#pragma unroll
            for (int nb = 0; nb < 8; nb++)
#pragma unroll
                for (int j = 0; j < 4; j++) c[mt][nb][j] = 0.f;
#pragma unroll
        for (int kb = 0; kb < 4; kb++) {
#pragma unroll
            for (int nb = 0; nb < 8; nb++) {
                uint32_t bh0 = sBh[nb * 8 + gid][kb * 8 + tig];
                uint32_t bh1 = sBh[nb * 8 + gid][kb * 8 + tig + 4];
                uint32_t bl0 = sBl[nb * 8 + gid][kb * 8 + tig];
                uint32_t bl1 = sBl[nb * 8 + gid][kb * 8 + tig + 4];
#pragma unroll
                for (int mt = 0; mt < 2; mt++) {
                    mma_tf32(c[mt][nb], ah[mt][kb][0], ah[mt][kb][1], ah[mt][kb][2], ah[mt][kb][3], bh0, bh1);
                    mma_tf32(c[mt][nb], ah[mt][kb][0], ah[mt][kb][1], ah[mt][kb][2], ah[mt][kb][3], bl0, bl1);
                    mma_tf32(c[mt][nb], al[mt][kb][0], al[mt][kb][1], al[mt][kb][2], al[mt][kb][3], bh0, bh1);
                }
            }
        }
        __syncthreads();
        // transpose C into sOut[edge][ch]
#pragma unroll
        for (int mt = 0; mt < 2; mt++) {
            int ch = warp * 32 + mt * 16 + gid;
#pragma unroll
            for (int nb = 0; nb < 8; nb++) {
                int e = nb * 8 + 2 * tig;
                sOut[e][ch] = c[mt][nb][0];
                sOut[e + 1][ch] = c[mt][nb][1];
                sOut[e][ch + 8] = c[mt][nb][2];
                sOut[e + 1][ch + 8] = c[mt][nb][3];
            }
        }
        __syncthreads();
        // epilogue: warp handles edges [warp*16, warp*16+16); thread = 4 fixed channels
#pragma unroll 2
        for (int ee = 0; ee < 16; ee++) {
            int e = warp * 16 + ee;
            int d = sDst[e], s = sSrc[e];
            float r = sR[e];
            float4 hd = *(const float4*)&g_Hpre[(size_t)d * 256 + hd_off];
            float4 hs = *(const float4*)&g_Hpre[(size_t)s * 256 + hs_off];
            float y0 = sOut[e][ch0 + 0] + hd.x + hs.x + fmaf(r, wr4[0], bb4[0]);
            float y1 = sOut[e][ch0 + 1] + hd.y + hs.y + fmaf(r, wr4[1], bb4[1]);
            float y2 = sOut[e][ch0 + 2] + hd.z + hs.z + fmaf(r, wr4[2], bb4[2]);
            float y3 = sOut[e][ch0 + 3] + hd.w + hs.w + fmaf(r, wr4[3], bb4[3]);
            int eg = e0 + e;
            float* out = (ch0 < 64) ? &g_t1[(size_t)eg * 64 + ch0]
                                    : &g_t2[(size_t)eg * 64 + ch0 - 64];
            *(float4*)out = make_float4(y0, y1, y2, y3);
            st[0] += y0; sq[0] += y0 * y0; st[1] += y1; sq[1] += y1 * y1;
            st[2] += y2; sq[2] += y2 * y2; st[3] += y3; sq[3] += y3 * y3;
        }
    }
    __syncthreads();
#pragma unroll
    for (int j = 0; j < 4; j++) { atomicAdd(&sS[ch0 + j], st[j]); atomicAdd(&sQ[ch0 + j], sq[j]); }
    __syncthreads();
    if (tid < 128) {
        atomicAdd(&g_sum[tid], (double)sS[tid]);
        atomicAdd(&g_sumsq[tid], (double)sQ[tid]);
    }
}

// ---------------- BN finalize (self-resetting stats) ----------------
__global__ void k_bnfin(int off, int n, double inv,
                        const float* __restrict__ g0, const float* __restrict__ b0,
                        const float* __restrict__ g1, const float* __restrict__ b1)
{
    int c = threadIdx.x;
    if (c >= n) return;
    double m = g_sum[off + c] * inv;
    double v = g_sumsq[off + c] * inv - m * m;
    g_sum[off + c] = 0.0;
    g_sumsq[off + c] = 0.0;
    float gg = (c < 64) ? g0[c] : g1[c - 64];
    float bb = (c < 64) ? b0[c] : b1[c - 64];
    float A = gg * rsqrtf((float)v + EPS);
    g_bnA[off + c] = A;
    g_bnB[off + c] = bb - (float)m * A;
}

// ---------------- edge B (tf32 MMA): mlin = silu(bn(t1)) @ msg_w2^T + b; coord -> g_sc ----------------
__global__ __launch_bounds__(128) void k_edgeBmma(const float* __restrict__ mw2, const float* __restrict__ mb2,
                                                  const float* __restrict__ cw2, const float* __restrict__ cb2)
{
    __shared__ uint32_t sXh[64][68];
    __shared__ uint32_t sXl[64][68];
    __shared__ int sEp[64];
    __shared__ float sS[64], sQ[64];
    __shared__ float sCA[64], sCB[64], sDA[64], sDB[64], sWc2[64];

    int tid = threadIdx.x;
    int warp = tid >> 5, lane = tid & 31;
    int gid = lane >> 2, tig = lane & 3;
    int m0 = warp << 4;

    if (tid < 64) {
        sS[tid] = 0.f; sQ[tid] = 0.f;
        sCA[tid] = g_bnA[tid];        sCB[tid] = g_bnB[tid];
        sDA[tid] = g_bnA[64 + tid];   sDB[tid] = g_bnB[64 + tid];
        sWc2[tid] = cw2[tid];
    }

    uint32_t ah[8][4], al[8][4];
    {
        const float* w0 = mw2 + (size_t)(m0 + gid) * 64;
        const float* w1 = mw2 + (size_t)(m0 + gid + 8) * 64;
#pragma unroll
        for (int kb = 0; kb < 8; kb++) {
            float f[4];
            f[0] = w0[kb * 8 + tig];     f[1] = w1[kb * 8 + tig];
            f[2] = w0[kb * 8 + tig + 4]; f[3] = w1[kb * 8 + tig + 4];
#pragma unroll
            for (int j = 0; j < 4; j++) {
                uint32_t h = f2tf32(f[j]);
                ah[kb][j] = h;
                al[kb][j] = f2tf32(f[j] - __uint_as_float(h));
            }
        }
    }
    float bias0 = mb2[m0 + gid], bias1 = mb2[m0 + gid + 8];
    float cbias = cb2[0];
    float s0 = 0.f, q0 = 0.f, s1 = 0.f, q1 = 0.f;

    int el = tid >> 1, half = tid & 1;

    for (int t = blockIdx.x; t < NE / 64; t += gridDim.x) {
        int e0 = t << 6;
        __syncthreads();
        if (tid < 64) sEp[tid] = g_epos[e0 + tid];
        {
            const float4* tb = (const float4*)&g_t1[(size_t)(e0 + el) * 64 + half * 32];
#pragma unroll
            for (int m = 0; m < 8; m++) {
                float4 v = tb[m];
                int c = half * 32 + 4 * m;
                float x0 = silu_f(fmaf(v.x, sCA[c], sCB[c]));
                float x1 = silu_f(fmaf(v.y, sCA[c + 1], sCB[c + 1]));
                float x2 = silu_f(fmaf(v.z, sCA[c + 2], sCB[c + 2]));
                float x3 = silu_f(fmaf(v.w, sCA[c + 3], sCB[c + 3]));
                uint32_t h0 = f2tf32(x0), h1 = f2tf32(x1), h2 = f2tf32(x2), h3 = f2tf32(x3);
                *(uint4*)&sXh[el][c] = make_uint4(h0, h1, h2, h3);
                *(uint4*)&sXl[el][c] = make_uint4(
                    f2tf32(x0 - __uint_as_float(h0)), f2tf32(x1 - __uint_as_float(h1)),
                    f2tf32(x2 - __uint_as_float(h2)), f2tf32(x3 - __uint_as_float(h3)));
            }
        }
        {
            const float4* tb = (const float4*)&g_t2[(size_t)(e0 + el) * 64 + half * 32];
            float part = 0.f;
#pragma unroll
            for (int m = 0; m < 8; m++) {
                float4 v = tb[m];
                int c = half * 32 + 4 * m;
                part += silu_f(fmaf(v.x, sDA[c], sDB[c])) * sWc2[c];
                part += silu_f(fmaf(v.y, sDA[c + 1], sDB[c + 1])) * sWc2[c + 1];
                part += silu_f(fmaf(v.z, sDA[c + 2], sDB[c + 2])) * sWc2[c + 2];
                part += silu_f(fmaf(v.w, sDA[c + 3], sDB[c + 3])) * sWc2[c + 3];
            }
            part += __shfl_xor_sync(0xffffffffu, part, 1);
            if (half == 0) g_sc[g_epos[e0 + el]] = part + cbias;
        }
        __syncthreads();
        float c[8][4];
#pragma unroll
        for (int nb = 0; nb < 8; nb++)
#pragma unroll
            for (int j = 0; j < 4; j++) c[nb][j] = 0.f;
#pragma unroll
        for (int kb = 0; kb < 8; kb++) {
#pragma unroll
            for (int nb = 0; nb < 8; nb++) {
                uint32_t bh0 = sXh[nb * 8 + gid][kb * 8 + tig];
                uint32_t bh1 = sXh[nb * 8 + gid][kb * 8 + tig + 4];
                uint32_t bl0 = sXl[nb * 8 + gid][kb * 8 + tig];
                uint32_t bl1 = sXl[nb * 8 + gid][kb * 8 + tig + 4];
                mma_tf32(c[nb], ah[kb][0], ah[kb][1], ah[kb][2], ah[kb][3], bh0, bh1);
                mma_tf32(c[nb], ah[kb][0], ah[kb][1], ah[kb][2], ah[kb][3], bl0, bl1);
                mma_tf32(c[nb], al[kb][0], al[kb][1], al[kb][2], al[kb][3], bh0, bh1);
            }
        }
        __syncthreads();
        float* sOut = (float*)&sXh[0][0];
#pragma unroll
        for (int nb = 0; nb < 8; nb++) {
            int e = nb * 8 + 2 * tig;
            float y00 = c[nb][0] + bias0;
            float y01 = c[nb][1] + bias0;
            float y10 = c[nb][2] + bias1;
            float y11 = c[nb][3] + bias1;
            sOut[e * 68 + m0 + gid] = y00;
            sOut[(e + 1) * 68 + m0 + gid] = y01;
            sOut[e * 68 + m0 + gid + 8] = y10;
            sOut[(e + 1) * 68 + m0 + gid + 8] = y11;
            s0 += y00 + y01; q0 += y00 * y00 + y01 * y01;
            s1 += y10 + y11; q1 += y10 * y10 + y11 * y11;
        }
        __syncthreads();
        {
            float* dst = &g_mlin[(size_t)sEp[el] * 64 + half * 32];
            const float* src = &sOut[el * 68 + half * 32];
#pragma unroll
            for (int m = 0; m < 8; m++)
                *(float4*)(dst + 4 * m) = *(const float4*)(src + 4 * m);
        }
    }
    __syncthreads();
    atomicAdd(&sS[m0 + gid], s0); atomicAdd(&sQ[m0 + gid], q0);
    atomicAdd(&sS[m0 + gid + 8], s1); atomicAdd(&sQ[m0 + gid + 8], q1);
    __syncthreads();
    if (tid < 64) {
        atomicAdd(&g_sum[128 + tid], (double)sS[tid]);
        atomicAdd(&g_sumsq[128 + tid], (double)sQ[tid]);
    }
}

// ---------------- aggregation: warp per node, contiguous CSR rows ----------------
__global__ __launch_bounds__(256) void k_aggr()
{
    int gwarp = (blockIdx.x * blockDim.x + threadIdx.x) >> 5;
    int lane = threadIdx.x & 31;
    if (gwarp >= NN) return;
    int n = gwarp;
    int s0 = g_rowstart[n], s1 = g_rowstart[n + 1];
    float A0 = g_bnA[128 + lane], B0 = g_bnB[128 + lane];
    float A1 = g_bnA[160 + lane], B1 = g_bnB[160 + lane];
    float acc0 = 0.f, acc1 = 0.f;
    for (int i = s0; i < s1; i++) {
        float m0 = g_mlin[(size_t)i * 64 + lane];
        float m1 = g_mlin[(size_t)i * 64 + 32 + lane];
        acc0 += silu_f(fmaf(m0, A0, B0));
        acc1 += silu_f(fmaf(m1, A1, B1));
    }
    g_u[(size_t)n * 128 + 64 + lane] = acc0;
    g_u[(size_t)n * 128 + 96 + lane] = acc1;
    float px = g_pos[n * 3], py = g_pos[n * 3 + 1], pz = g_pos[n * 3 + 2];
    float cx = 0.f, cy = 0.f, cz = 0.f;
    for (int i = s0 + lane; i < s1; i += 32) {
        int src = g_csrsrc[i];
        float sc = g_sc[i];
        cx += sc * (px - g_pos[src * 3]);
        cy += sc * (py - g_pos[src * 3 + 1]);
        cz += sc * (pz - g_pos[src * 3 + 2]);
    }
#pragma unroll
    for (int o = 16; o > 0; o >>= 1) {
        cx += __shfl_xor_sync(0xffffffffu, cx, o);
        cy += __shfl_xor_sync(0xffffffffu, cy, o);
        cz += __shfl_xor_sync(0xffffffffu, cz, o);
    }
    if (lane == 0) {
        g_aggr_p[n * 3 + 0] = cx;
        g_aggr_p[n * 3 + 1] = cy;
        g_aggr_p[n * 3 + 2] = cz;
    }
}

// ---------------- node 1: tiled 64n x 64o, K=128 ----------------
__global__ __launch_bounds__(256) void k_node1(const float* __restrict__ uw1, const float* __restrict__ ub1)
{
    __shared__ __align__(16) float sW[64][64];
    __shared__ __align__(16) float sA[64][64];
    __shared__ float sS[64], sQ[64];
    int tid = threadIdx.x, tx = tid & 15, ty = tid >> 4;
    if (tid < 64) { sS[tid] = 0.f; sQ[tid] = 0.f; }
    float bb[4];
#pragma unroll
    for (int j = 0; j < 4; j++) bb[j] = ub1[(ty << 2) + j];
    float st[4] = {0.f, 0.f, 0.f, 0.f}, sq[4] = {0.f, 0.f, 0.f, 0.f};
    int ntiles = (NN + 63) >> 6;
    for (int t = blockIdx.x; t < ntiles; t += gridDim.x) {
        int n0 = t << 6;
        float acc[4][4];
#pragma unroll
        for (int i = 0; i < 4; i++)
#pragma unroll
            for (int j = 0; j < 4; j++) acc[i][j] = 0.f;
        for (int half = 0; half < 2; half++) {
            __syncthreads();
            for (int i = tid; i < 1024; i += 256) {
                int o = i & 63, k0 = (i >> 6) << 2;
                float4 v = *(const float4*)&uw1[o * 128 + half * 64 + k0];
                sW[k0 + 0][o] = v.x; sW[k0 + 1][o] = v.y;
                sW[k0 + 2][o] = v.z; sW[k0 + 3][o] = v.w;
            }
            {
                int nn = tid >> 2, k0 = (tid & 3) << 4;
                int n = n0 + nn;
#pragma unroll
                for (int m = 0; m < 4; m++) {
                    float4 v = (n < NN) ? *(const float4*)&g_u[(size_t)n * 128 + half * 64 + k0 + 4 * m]
                                        : make_float4(0.f, 0.f, 0.f, 0.f);
                    sA[k0 + 4 * m + 0][nn] = v.x;
                    sA[k0 + 4 * m + 1][nn] = v.y;
                    sA[k0 + 4 * m + 2][nn] = v.z;
                    sA[k0 + 4 * m + 3][nn] = v.w;
                }
            }
            __syncthreads();
#pragma unroll 4
            for (int k = 0; k < 64; k++) {
                float4 a = *(const float4*)&sA[k][tx << 2];
                float4 b = *(const float4*)&sW[k][ty << 2];
                float av[4] = {a.x, a.y, a.z, a.w};
                float bv[4] = {b.x, b.y, b.z, b.w};
#pragma unroll
                for (int i = 0; i < 4; i++)
#pragma unroll
                    for (int j = 0; j < 4; j++) acc[i][j] = fmaf(av[i], bv[j], acc[i][j]);
            }
        }
#pragma unroll
        for (int i = 0; i < 4; i++) {
            int n = n0 + (tx << 2) + i;
            if (n < NN) {
                float y0 = acc[i][0] + bb[0], y1 = acc[i][1] + bb[1];
                float y2 = acc[i][2] + bb[2], y3 = acc[i][3] + bb[3];
                *(float4*)&g_un[n * 64 + (ty << 2)] = make_float4(y0, y1, y2, y3);
                st[0] += y0; sq[0] += y0 * y0; st[1] += y1; sq[1] += y1 * y1;
                st[2] += y2; sq[2] += y2 * y2; st[3] += y3; sq[3] += y3 * y3;
            }
        }
    }
    __syncthreads();
#pragma unroll
    for (int j = 0; j < 4; j++) {
        atomicAdd(&sS[(ty << 2) + j], st[j]);
        atomicAdd(&sQ[(ty << 2) + j], sq[j]);
    }
    __syncthreads();
    if (tid < 64) {
        atomicAdd(&g_sum[192 + tid], (double)sS[tid]);
        atomicAdd(&g_sumsq[192 + tid], (double)sQ[tid]);
    }
}

// ---------------- node 2: tiled 64n x 64o, K=64; residual + pos update ----------------
__global__ __launch_bounds__(256) void k_node2(const float* __restrict__ uw2, const float* __restrict__ ub2)
{
    __shared__ __align__(16) float sW[64][64];
    __shared__ __align__(16) float sA[64][64];
    int tid = threadIdx.x, tx = tid & 15, ty = tid >> 4;
    for (int i = tid; i < 1024; i += 256) {
        int o = i & 63, k0 = (i >> 6) << 2;
        float4 v = *(const float4*)&uw2[o * 64 + k0];
        sW[k0 + 0][o] = v.x; sW[k0 + 1][o] = v.y;
        sW[k0 + 2][o] = v.z; sW[k0 + 3][o] = v.w;
    }
    int k0s = (tid & 3) << 4;
    float4 cA[4], cB[4];
#pragma unroll
    for (int m = 0; m < 4; m++) {
        cA[m] = *(const float4*)&g_bnA[192 + k0s + 4 * m];
        cB[m] = *(const float4*)&g_bnB[192 + k0s + 4 * m];
    }
    float bb[4];
#pragma unroll
    for (int j = 0; j < 4; j++) bb[j] = ub2[(ty << 2) + j];
    int ntiles = (NN + 63) >> 6;
    for (int t = blockIdx.x; t < ntiles; t += gridDim.x) {
        int n0 = t << 6;
        __syncthreads();
        {
            int nn = tid >> 2;
            int n = n0 + nn;
#pragma unroll
            for (int m = 0; m < 4; m++) {
                float4 v = (n < NN) ? *(const float4*)&g_un[(size_t)n * 64 + k0s + 4 * m]
                                    : make_float4(0.f, 0.f, 0.f, 0.f);
                sA[k0s + 4 * m + 0][nn] = silu_f(fmaf(v.x, cA[m].x, cB[m].x));
                sA[k0s + 4 * m + 1][nn] = silu_f(fmaf(v.y, cA[m].y, cB[m].y));
                sA[k0s + 4 * m + 2][nn] = silu_f(fmaf(v.z, cA[m].z, cB[m].z));
                sA[k0s + 4 * m + 3][nn] = silu_f(fmaf(v.w, cA[m].w, cB[m].w));
            }
        }
        __syncthreads();
        float acc[4][4];
#pragma unroll
        for (int i = 0; i < 4; i++)
#pragma unroll
            for (int j = 0; j < 4; j++) acc[i][j] = 0.f;
#pragma unroll 4
        for (int k = 0; k < 64; k++) {
            float4 a = *(const float4*)&sA[k][tx << 2];
            float4 b = *(const float4*)&sW[k][ty << 2];
            float av[4] = {a.x, a.y, a.z, a.w};
            float bv[4] = {b.x, b.y, b.z, b.w};
#pragma unroll
            for (int i = 0; i < 4; i++)
#pragma unroll
                for (int j = 0; j < 4; j++) acc[i][j] = fmaf(av[i], bv[j], acc[i][j]);
        }
#pragma unroll
        for (int i = 0; i < 4; i++) {
            int n = n0 + (tx << 2) + i;
            if (n < NN) {
                float4 hold = *(const float4*)&g_h[n * 64 + (ty << 2)];
                float h0 = hold.x + acc[i][0] + bb[0];
                float h1 = hold.y + acc[i][1] + bb[1];
                float h2 = hold.z + acc[i][2] + bb[2];
                float h3 = hold.w + acc[i][3] + bb[3];
                float4 hv = make_float4(h0, h1, h2, h3);
                *(float4*)&g_h[n * 64 + (ty << 2)] = hv;
                *(float4*)&g_u[(size_t)n * 128 + (ty << 2)] = hv;
            }
        }
        if (tid < 64) {
            int n = n0 + tid;
            if (n < NN) {
                g_pos[n * 3 + 0] += g_aggr_p[n * 3 + 0];
                g_pos[n * 3 + 1] += g_aggr_p[n * 3 + 1];
                g_pos[n * 3 + 2] += g_aggr_p[n * 3 + 2];
            }
        }
    }
}

// ---------------- pooling ----------------
__global__ void k_pool(const int* __restrict__ batch)
{
    int idx = blockIdx.x * blockDim.x + threadIdx.x;
    if (idx >= NN * 16) return;
    int n = idx >> 4, c4 = (idx & 15) * 4;
    int b = batch[n];
    float4 h = *(const float4*)&g_h[n * 64 + c4];
    red_add_v4(&g_pool[b * 64 + c4], h.x, h.y, h.z, h.w);
    if (c4 == 0) atomicAdd(&g_cnt[b], 1.0f);
}

__global__ void k_pred(const float* __restrict__ w, const float* __restrict__ b,
                       float* __restrict__ out)
{
    int g = blockIdx.x, lane = threadIdx.x;
    float p = g_pool[g * 64 + lane] * w[lane] + g_pool[g * 64 + 32 + lane] * w[32 + lane];
#pragma unroll
    for (int o = 16; o > 0; o >>= 1) p += __shfl_xor_sync(0xffffffffu, p, o);
    if (lane == 0) out[g] = p / fmaxf(g_cnt[g], 1.0f) + b[0];
}

// ---------------- launch ----------------
extern "C" void kernel_launch(void* const* d_in, const int* in_sizes, int n_in,
                              void* d_out, int out_size)
{
    const float* node_s    = (const float*)d_in[0];
    const float* node_type = (const float*)d_in[1];
    const float* pos       = (const float*)d_in[2];
    const int*   ei        = (const int*)d_in[3];
    const float* edge_s    = (const float*)d_in[4];
    const int*   batch     = (const int*)d_in[5];
    const float* lin_in_w  = (const float*)d_in[6];
    const float* lin_in_b  = (const float*)d_in[7];
    const float* msg_w1    = (const float*)d_in[8];
    const float* msg_b1    = (const float*)d_in[9];
    const float* msg_g1    = (const float*)d_in[10];
    const float* msg_be1   = (const float*)d_in[11];
    const float* msg_w2    = (const float*)d_in[12];
    const float* msg_b2    = (const float*)d_in[13];
    const float* msg_g2    = (const float*)d_in[14];
    const float* msg_be2   = (const float*)d_in[15];
    const float* updf_w1   = (const float*)d_in[16];
    const float* updf_b1   = (const float*)d_in[17];
    const float* updf_g1   = (const float*)d_in[18];
    const float* updf_be1  = (const float*)d_in[19];
    const float* updf_w2   = (const float*)d_in[20];
    const float* updf_b2   = (const float*)d_in[21];
    const float* updc_w1   = (const float*)d_in[22];
    const float* updc_b1   = (const float*)d_in[23];
    const float* updc_g1   = (const float*)d_in[24];
    const float* updc_be1  = (const float*)d_in[25];
    const float* updc_w2   = (const float*)d_in[26];
    const float* updc_b2   = (const float*)d_in[27];
    const float* lin_pred_w = (const float*)d_in[28];
    const float* lin_pred_b = (const float*)d_in[29];

    // order chosen so ncu's fixed capture window lands on k_edgeAmma
    k_init<<<(NN * 64 + 255) / 256, 256>>>(node_s, node_type, pos, lin_in_w, lin_in_b);
    k_wpack_all<<<(NL * 64 * 256 + 255) / 256, 256>>>(msg_w1, updc_w1);

    for (int l = 0; l < NL; l++) {
        const float* mw1 = msg_w1 + (size_t)l * 64 * 161;
        const float* mb1 = msg_b1 + l * 64;
        const float* mw2 = msg_w2 + (size_t)l * 64 * 64;
        const float* mb2 = msg_b2 + l * 64;
        const float* cw1 = updc_w1 + (size_t)l * 64 * 161;
        const float* cb1 = updc_b1 + l * 64;
        const float* cw2 = updc_w2 + (size_t)l * 64;
        const float* cb2 = updc_b2 + l;
        const float* uw1 = updf_w1 + (size_t)l * 64 * 128;
        const float* ub1 = updf_b1 + l * 64;
        const float* uw2 = updf_w2 + (size_t)l * 64 * 64;
        const float* ub2 = updf_b2 + l * 64;

        k_hpre<<<592, 256>>>(l);
        k_edgeAmma<<<888, 128>>>(ei, edge_s, mw1, mb1, cw1, cb1);
        if (l == 0) {
            // CSR build — only needed before first edgeB/aggr; overlaps bn stall
            k_hist<<<(NE + 255) / 256, 256>>>(ei);
            k_scan<<<1, 1024>>>();
            k_fill<<<(NE + 255) / 256, 256>>>(ei);
        }
        k_bnfin<<<1, 128>>>(0, 128, 1.0 / NE,
                            msg_g1 + l * 64, msg_be1 + l * 64,
                            updc_g1 + l * 64, updc_be1 + l * 64);
        k_edgeBmma<<<888, 128>>>(mw2, mb2, cw2, cb2);
        k_bnfin<<<1, 64>>>(128, 64, 1.0 / NE,
                           msg_g2 + l * 64, msg_be2 + l * 64,
                           msg_g2 + l * 64, msg_be2 + l * 64);
        k_aggr<<<(NN * 32 + 255) / 256, 256>>>();
        k_node1<<<592, 256>>>(uw1, ub1);
        k_bnfin<<<1, 64>>>(192, 64, 1.0 / NN,
                           updf_g1 + l * 64, updf_be1 + l * 64,
                           updf_g1 + l * 64, updf_be1 + l * 64);
        k_node2<<<592, 256>>>(uw2, ub2);
    }

    k_pool<<<(NN * 16 + 255) / 256, 256>>>(batch);
    k_pred<<<NG, 32>>>(lin_pred_w, lin_pred_b, (float*)d_out);
}

// round 9
// speedup vs baseline: 1.7387x; 1.1382x over previous
#include <cuda_runtime.h>
#include <math.h>
#include <stdint.h>

#define NN 50000
#define NE 800000
#define NL 4
#define NG 64
#define EPS 1e-5f

// ---------------- static device scratch ----------------
__device__ __align__(16) float g_h[NN * 64];
__device__ __align__(16) float g_u[NN * 128];      // [h | aggr_h]
__device__ __align__(16) float g_un[NN * 64];
__device__ __align__(16) float g_pos[NN * 3];
__device__ __align__(16) float g_aggr_p[NN * 3];
__device__ __align__(16) float g_Hpre[(size_t)NN * 256];
__device__ __align__(16) float g_wpack4[NL][64 * 256];  // k-major [k][op]
__device__ __align__(16) float g_t1[(size_t)NE * 64];   // CSR-ordered
__device__ __align__(16) float g_t2[(size_t)NE * 64];   // CSR-ordered
__device__ __align__(16) float g_mlin[(size_t)NE * 64]; // CSR-ordered
__device__ __align__(16) float g_sc[NE];                // CSR-ordered
__device__ int g_deg[NN];
__device__ int g_rowstart[NN + 1];
__device__ int g_cursor[NN];
__device__ int g_csrsrc[NE];   // CSR position -> src node
__device__ int g_csrdst[NE];   // CSR position -> dst node
__device__ int g_csre[NE];     // CSR position -> original edge id
__device__ double g_sum[256];
__device__ double g_sumsq[256];
__device__ __align__(16) float g_bnA[256];
__device__ __align__(16) float g_bnB[256];
__device__ __align__(16) float g_pool[NG * 64];
__device__ float g_cnt[NG];

__device__ __forceinline__ float silu_f(float y) {
    return y * (1.0f / (1.0f + __expf(-y)));
}

__device__ __forceinline__ void red_add_v4(float* p, float a, float b, float c, float d) {
    asm volatile("red.global.add.v4.f32 [%0], {%1,%2,%3,%4};"
                 :: "l"(p), "f"(a), "f"(b), "f"(c), "f"(d) : "memory");
}

__device__ __forceinline__ uint32_t f2tf32(float f) {
    uint32_t u;
    asm("cvt.rna.tf32.f32 %0, %1;" : "=r"(u) : "f"(f));
    return u;
}

__device__ __forceinline__ void mma_tf32(float* c, uint32_t a0, uint32_t a1, uint32_t a2, uint32_t a3,
                                         uint32_t b0, uint32_t b1) {
    asm volatile("mma.sync.aligned.m16n8k8.row.col.f32.tf32.tf32.f32 "
                 "{%0,%1,%2,%3}, {%4,%5,%6,%7}, {%8,%9}, {%0,%1,%2,%3};"
                 : "+f"(c[0]), "+f"(c[1]), "+f"(c[2]), "+f"(c[3])
                 : "r"(a0), "r"(a1), "r"(a2), "r"(a3), "r"(b0), "r"(b1));
}

// ---------------- init ----------------
__global__ void k_init(const float* __restrict__ ns, const float* __restrict__ nt,
                       const float* __restrict__ pos, const float* __restrict__ w,
                       const float* __restrict__ b)
{
    int idx = blockIdx.x * blockDim.x + threadIdx.x;
    if (idx < NG * 64) g_pool[idx] = 0.f;
    if (idx < NG) g_cnt[idx] = 0.f;
    if (idx < 256) { g_sum[idx] = 0.0; g_sumsq[idx] = 0.0; }
    if (idx < NN) g_deg[idx] = 0;
    if (idx >= NN * 64) return;
    int n = idx >> 6, o = idx & 63;
    const float* wr = w + o * 8;
    const float* s = ns + n * 6;
    float acc = b[o];
#pragma unroll
    for (int i = 0; i < 6; i++) acc = fmaf(s[i], wr[i], acc);
    acc = fmaf(nt[n * 2 + 0], wr[6], acc);
    acc = fmaf(nt[n * 2 + 1], wr[7], acc);
    g_h[idx] = acc;
    g_u[(size_t)n * 128 + o] = acc;
    if (o < 3) g_pos[n * 3 + o] = pos[n * 3 + o];
}

// ---------------- CSR build ----------------
__global__ void k_hist(const int* __restrict__ ei)
{
    int e = blockIdx.x * blockDim.x + threadIdx.x;
    if (e < NE) atomicAdd(&g_deg[ei[NE + e]], 1);
}

__global__ __launch_bounds__(1024) void k_scan()
{
    __shared__ int ssum[1024];
    int t = threadIdx.x;
    const int C = 49;
    int begin = t * C;
    int end = begin + C; if (end > NN) end = NN;
    if (begin > NN) begin = NN;
    int s = 0;
    for (int i = begin; i < end; i++) s += g_deg[i];
    ssum[t] = s;
    __syncthreads();
    for (int off = 1; off < 1024; off <<= 1) {
        int v = (t >= off) ? ssum[t - off] : 0;
        __syncthreads();
        ssum[t] += v;
        __syncthreads();
    }
    int run = ssum[t] - s;
    for (int i = begin; i < end; i++) {
        g_rowstart[i] = run;
        g_cursor[i] = run;
        run += g_deg[i];
    }
    if (t == 1023) g_rowstart[NN] = ssum[1023];
}

__global__ void k_fill(const int* __restrict__ ei)
{
    int e = blockIdx.x * blockDim.x + threadIdx.x;
    if (e >= NE) return;
    int s = ei[e], d = ei[NE + e];
    int p = atomicAdd(&g_cursor[d], 1);
    g_csrsrc[p] = s;
    g_csrdst[p] = d;
    g_csre[p] = e;
}

// ---------------- pack h-columns of msg_w1/updc_w1 for ALL layers ----------------
__global__ void k_wpack_all(const float* __restrict__ mw1a, const float* __restrict__ cw1a)
{
    int idx = blockIdx.x * blockDim.x + threadIdx.x;
    if (idx >= NL * 64 * 256) return;
    int l = idx >> 14;
    int r = idx & 16383;
    int k = r >> 8, op = r & 255, o = op & 63;
    const float* mw1 = mw1a + (size_t)l * 64 * 161;
    const float* cw1 = cw1a + (size_t)l * 64 * 161;
    float v;
    if (op < 64)       v = mw1[o * 161 + k];
    else if (op < 128) v = mw1[o * 161 + 64 + k];
    else if (op < 192) v = cw1[o * 161 + k];
    else               v = cw1[o * 161 + 64 + k];
    g_wpack4[l][k * 256 + op] = v;
}

// ---------------- Hpre: tiled GEMM 64n x 128o (2 phases), K=64 ----------------
__global__ __launch_bounds__(256) void k_hpre(int layer)
{
    const float* wpack = g_wpack4[layer];
    __shared__ __align__(16) float sA[64][64];
    __shared__ __align__(16) float sB[64][128];
    int tid = threadIdx.x, tx = tid & 15, ty = tid >> 4;
    int ntiles = (NN + 63) >> 6;
    for (int t = blockIdx.x; t < ntiles; t += gridDim.x) {
        int n0 = t << 6;
        __syncthreads();
        {
            int nn = tid >> 2, k0 = (tid & 3) << 4;
            int n = n0 + nn;
#pragma unroll
            for (int m = 0; m < 4; m++) {
                float4 v = (n < NN) ? *(const float4*)&g_h[n * 64 + k0 + 4 * m]
                                    : make_float4(0.f, 0.f, 0.f, 0.f);
                sA[k0 + 4 * m + 0][nn] = v.x;
                sA[k0 + 4 * m + 1][nn] = v.y;
                sA[k0 + 4 * m + 2][nn] = v.z;
                sA[k0 + 4 * m + 3][nn] = v.w;
            }
        }
        for (int ph = 0; ph < 2; ph++) {
            __syncthreads();
#pragma unroll
            for (int r = 0; r < 8; r++) {
                int i = tid + r * 256;
                int k = i >> 5, o4 = (i & 31) << 2;
                *(float4*)&sB[k][o4] = *(const float4*)&wpack[k * 256 + ph * 128 + o4];
            }
            __syncthreads();
            float acc[4][8];
#pragma unroll
            for (int i = 0; i < 4; i++)
#pragma unroll
                for (int j = 0; j < 8; j++) acc[i][j] = 0.f;
#pragma unroll 4
            for (int k = 0; k < 64; k++) {
                float4 a = *(const float4*)&sA[k][tx << 2];
                float4 b0 = *(const float4*)&sB[k][ty << 3];
                float4 b1 = *(const float4*)&sB[k][(ty << 3) + 4];
                float av[4] = {a.x, a.y, a.z, a.w};
                float bv[8] = {b0.x, b0.y, b0.z, b0.w, b1.x, b1.y, b1.z, b1.w};
#pragma unroll
                for (int i = 0; i < 4; i++)
#pragma unroll
                    for (int j = 0; j < 8; j++) acc[i][j] = fmaf(av[i], bv[j], acc[i][j]);
            }
#pragma unroll
            for (int i = 0; i < 4; i++) {
                int n = n0 + (tx << 2) + i;
                if (n < NN) {
                    float* out = &g_Hpre[(size_t)n * 256 + ph * 128 + (ty << 3)];
                    *(float4*)out = make_float4(acc[i][0], acc[i][1], acc[i][2], acc[i][3]);
                    *(float4*)(out + 4) = make_float4(acc[i][4], acc[i][5], acc[i][6], acc[i][7]);
                }
            }
        }
    }
}

// ---------------- edge A (tf32 MMA, CSR order): t1/t2 = Hpre gather + r*wr + es@Wes^T + b ----------------
// 256 threads, 8 warps; tile = 64 CSR positions x 128 ch. Warp w covers ch [16w, 16w+16).
__global__ __launch_bounds__(256) void k_edgeAmma(const float* __restrict__ es,
                                                  const float* __restrict__ mw1, const float* __restrict__ mb1,
                                                  const float* __restrict__ cw1, const float* __restrict__ cb1)
{
    __shared__ __align__(16) uint32_t sBuf[64 * 132];      // 33.8KB (staging | output)
    uint32_t (*sBh)[36] = (uint32_t(*)[36])sBuf;
    uint32_t (*sBl)[36] = (uint32_t(*)[36])(sBuf + 64 * 36);
    float (*sOut)[132] = (float(*)[132])sBuf;
    __shared__ float sR[64];
    __shared__ int sSrc[64], sDst[64];
    __shared__ float sS[128], sQ[128];

    int tid = threadIdx.x;
    int warp = tid >> 5, lane = tid & 31;
    int gid = lane >> 2, tig = lane & 3;

    if (tid < 128) { sS[tid] = 0.f; sQ[tid] = 0.f; }

    // one m16 tile per warp: rows r0 = warp*16 + gid, r1 = r0+8 (ch idx)
    uint32_t ah[4][4], al[4][4];
    {
        int r0 = warp * 16 + gid;
        int r1 = r0 + 8;
        const float* w0 = (r0 < 64) ? &mw1[r0 * 161 + 129] : &cw1[(r0 - 64) * 161 + 129];
        const float* w1 = (r1 < 64) ? &mw1[r1 * 161 + 129] : &cw1[(r1 - 64) * 161 + 129];
#pragma unroll
        for (int kb = 0; kb < 4; kb++) {
            float f[4];
            f[0] = w0[kb * 8 + tig];     f[1] = w1[kb * 8 + tig];
            f[2] = w0[kb * 8 + tig + 4]; f[3] = w1[kb * 8 + tig + 4];
#pragma unroll
            for (int j = 0; j < 4; j++) {
                uint32_t h = f2tf32(f[j]);
                ah[kb][j] = h;
                al[kb][j] = f2tf32(f[j] - __uint_as_float(h));
            }
        }
    }
    // epilogue: warp handles edges [warp*8, warp*8+8); lane has 4 fixed channels
    int ch0 = lane << 2;
    float wr4[4], bb4[4];
#pragma unroll
    for (int j = 0; j < 4; j++) {
        int ch = ch0 + j;
        wr4[j] = (ch < 64) ? mw1[ch * 161 + 128] : cw1[(ch - 64) * 161 + 128];
        bb4[j] = (ch < 64) ? mb1[ch] : cb1[ch - 64];
    }
    int hd_off = (ch0 < 64) ? ch0 : 64 + ch0;
    int hs_off = (ch0 < 64) ? 64 + ch0 : 128 + ch0;
    float st[4] = {0.f, 0.f, 0.f, 0.f}, sq[4] = {0.f, 0.f, 0.f, 0.f};

    for (int t = blockIdx.x; t < NE / 64; t += gridDim.x) {
        int p0 = t << 6;
        __syncthreads();
        if (tid < 64) {
            int p = p0 + tid;
            int s = g_csrsrc[p], d = g_csrdst[p];
            sSrc[tid] = s; sDst[tid] = d;
            float dx = g_pos[d * 3] - g_pos[s * 3];
            float dy = g_pos[d * 3 + 1] - g_pos[s * 3 + 1];
            float dz = g_pos[d * 3 + 2] - g_pos[s * 3 + 2];
            sR[tid] = sqrtf(dx * dx + dy * dy + dz * dz);
        }
        // stage es hi/lo [edge][k] — gathered by original edge id
        {
            int el = tid >> 2, koff = (tid & 3) << 3;
            int eid = g_csre[p0 + el];
            const float4* ep = (const float4*)&es[(size_t)eid * 32 + koff];
            float4 v0 = ep[0];
            float4 v1 = ep[1];
            uint32_t h;
            h = f2tf32(v0.x); sBh[el][koff + 0] = h; sBl[el][koff + 0] = f2tf32(v0.x - __uint_as_float(h));
            h = f2tf32(v0.y); sBh[el][koff + 1] = h; sBl[el][koff + 1] = f2tf32(v0.y - __uint_as_float(h));
            h = f2tf32(v0.z); sBh[el][koff + 2] = h; sBl[el][koff + 2] = f2tf32(v0.z - __uint_as_float(h));
            h = f2tf32(v0.w); sBh[el][koff + 3] = h; sBl[el][koff + 3] = f2tf32(v0.w - __uint_as_float(h));
            h = f2tf32(v1.x); sBh[el][koff + 4] = h; sBl[el][koff + 4] = f2tf32(v1.x - __uint_as_float(h));
            h = f2tf32(v1.y); sBh[el][koff + 5] = h; sBl[el][koff + 5] = f2tf32(v1.y - __uint_as_float(h));
            h = f2tf32(v1.z); sBh[el][koff + 6] = h; sBl[el][koff + 6] = f2tf32(v1.z - __uint_as_float(h));
            h = f2tf32(v1.w); sBh[el][koff + 7] = h; sBl[el][koff + 7] = f2tf32(v1.w - __uint_as_float(h));
        }
        __syncthreads();
        // MMA: per warp C[16 ch][64 edges]
        float c[8][4];
#pragma unroll
        for (int nb = 0; nb < 8; nb++)
#pragma unroll
            for (int j = 0; j < 4; j++) c[nb][j] = 0.f;
#pragma unroll
        for (int kb = 0; kb < 4; kb++) {
#pragma unroll
            for (int nb = 0; nb < 8; nb++) {
                uint32_t bh0 = sBh[nb * 8 + gid][kb * 8 + tig];
                uint32_t bh1 = sBh[nb * 8 + gid][kb * 8 + tig + 4];
                uint32_t bl0 = sBl[nb * 8 + gid][kb * 8 + tig];
                uint32_t bl1 = sBl[nb * 8 + gid][kb * 8 + tig + 4];
                mma_tf32(c[nb], ah[kb][0], ah[kb][1], ah[kb][2], ah[kb][3], bh0, bh1);
                mma_tf32(c[nb], ah[kb][0], ah[kb][1], ah[kb][2], ah[kb][3], bl0, bl1);
                mma_tf32(c[nb], al[kb][0], al[kb][1], al[kb][2], al[kb][3], bh0, bh1);
            }
        }
        __syncthreads();
        // transpose C into sOut[edge][ch]
        {
            int ch = warp * 16 + gid;
#pragma unroll
            for (int nb = 0; nb < 8; nb++) {
                int e = nb * 8 + 2 * tig;
                sOut[e][ch] = c[nb][0];
                sOut[e + 1][ch] = c[nb][1];
                sOut[e][ch + 8] = c[nb][2];
                sOut[e + 1][ch + 8] = c[nb][3];
            }
        }
        __syncthreads();
        // epilogue
#pragma unroll 2
        for (int ee = 0; ee < 8; ee++) {
            int e = warp * 8 + ee;
            int d = sDst[e], s = sSrc[e];
            float r = sR[e];
            float4 hd = *(const float4*)&g_Hpre[(size_t)d * 256 + hd_off];
            float4 hs = *(const float4*)&g_Hpre[(size_t)s * 256 + hs_off];
            float4 o = *(const float4*)&sOut[e][ch0];
            float y0 = o.x + hd.x + hs.x + fmaf(r, wr4[0], bb4[0]);
            float y1 = o.y + hd.y + hs.y + fmaf(r, wr4[1], bb4[1]);
            float y2 = o.z + hd.z + hs.z + fmaf(r, wr4[2], bb4[2]);
            float y3 = o.w + hd.w + hs.w + fmaf(r, wr4[3], bb4[3]);
            int p = p0 + e;
            float* out = (ch0 < 64) ? &g_t1[(size_t)p * 64 + ch0]
                                    : &g_t2[(size_t)p * 64 + ch0 - 64];
            *(float4*)out = make_float4(y0, y1, y2, y3);
            st[0] += y0; sq[0] += y0 * y0; st[1] += y1; sq[1] += y1 * y1;
            st[2] += y2; sq[2] += y2 * y2; st[3] += y3; sq[3] += y3 * y3;
        }
    }
    __syncthreads();
#pragma unroll
    for (int j = 0; j < 4; j++) { atomicAdd(&sS[ch0 + j], st[j]); atomicAdd(&sQ[ch0 + j], sq[j]); }
    __syncthreads();
    if (tid < 128) {
        atomicAdd(&g_sum[tid], (double)sS[tid]);
        atomicAdd(&g_sumsq[tid], (double)sQ[tid]);
    }
}

// ---------------- BN finalize (self-resetting stats) ----------------
__global__ void k_bnfin(int off, int n, double inv,
                        const float* __restrict__ g0, const float* __restrict__ b0,
                        const float* __restrict__ g1, const float* __restrict__ b1)
{
    int c = threadIdx.x;
    if (c >= n) return;
    double m = g_sum[off + c] * inv;
    double v = g_sumsq[off + c] * inv - m * m;
    g_sum[off + c] = 0.0;
    g_sumsq[off + c] = 0.0;
    float gg = (c < 64) ? g0[c] : g1[c - 64];
    float bb = (c < 64) ? b0[c] : b1[c - 64];
    float A = gg * rsqrtf((float)v + EPS);
    g_bnA[off + c] = A;
    g_bnB[off + c] = bb - (float)m * A;
}

// ---------------- edge B (tf32 MMA, CSR order): mlin = silu(bn(t1)) @ msg_w2^T + b ----------------
__global__ __launch_bounds__(128) void k_edgeBmma(const float* __restrict__ mw2, const float* __restrict__ mb2,
                                                  const float* __restrict__ cw2, const float* __restrict__ cb2)
{
    __shared__ uint32_t sXh[64][68];
    __shared__ uint32_t sXl[64][68];
    __shared__ float sS[64], sQ[64];
    __shared__ float sCA[64], sCB[64], sDA[64], sDB[64], sWc2[64];

    int tid = threadIdx.x;
    int warp = tid >> 5, lane = tid & 31;
    int gid = lane >> 2, tig = lane & 3;
    int m0 = warp << 4;

    if (tid < 64) {
        sS[tid] = 0.f; sQ[tid] = 0.f;
        sCA[tid] = g_bnA[tid];        sCB[tid] = g_bnB[tid];
        sDA[tid] = g_bnA[64 + tid];   sDB[tid] = g_bnB[64 + tid];
        sWc2[tid] = cw2[tid];
    }

    uint32_t ah[8][4], al[8][4];
    {
        const float* w0 = mw2 + (size_t)(m0 + gid) * 64;
        const float* w1 = mw2 + (size_t)(m0 + gid + 8) * 64;
#pragma unroll
        for (int kb = 0; kb < 8; kb++) {
            float f[4];
            f[0] = w0[kb * 8 + tig];     f[1] = w1[kb * 8 + tig];
            f[2] = w0[kb * 8 + tig + 4]; f[3] = w1[kb * 8 + tig + 4];
#pragma unroll
            for (int j = 0; j < 4; j++) {
                uint32_t h = f2tf32(f[j]);
                ah[kb][j] = h;
                al[kb][j] = f2tf32(f[j] - __uint_as_float(h));
            }
        }
    }
    float bias0 = mb2[m0 + gid], bias1 = mb2[m0 + gid + 8];
    float cbias = cb2[0];
    float s0 = 0.f, q0 = 0.f, s1 = 0.f, q1 = 0.f;

    int el = tid >> 1, half = tid & 1;

    for (int t = blockIdx.x; t < NE / 64; t += gridDim.x) {
        int e0 = t << 6;
        __syncthreads();
        {
            const float4* tb = (const float4*)&g_t1[(size_t)(e0 + el) * 64 + half * 32];
#pragma unroll
            for (int m = 0; m < 8; m++) {
                float4 v = tb[m];
                int c = half * 32 + 4 * m;
                float x0 = silu_f(fmaf(v.x, sCA[c], sCB[c]));
                float x1 = silu_f(fmaf(v.y, sCA[c + 1], sCB[c + 1]));
                float x2 = silu_f(fmaf(v.z, sCA[c + 2], sCB[c + 2]));
                float x3 = silu_f(fmaf(v.w, sCA[c + 3], sCB[c + 3]));
                uint32_t h0 = f2tf32(x0), h1 = f2tf32(x1), h2 = f2tf32(x2), h3 = f2tf32(x3);
                *(uint4*)&sXh[el][c] = make_uint4(h0, h1, h2, h3);
                *(uint4*)&sXl[el][c] = make_uint4(
                    f2tf32(x0 - __uint_as_float(h0)), f2tf32(x1 - __uint_as_float(h1)),
                    f2tf32(x2 - __uint_as_float(h2)), f2tf32(x3 - __uint_as_float(h3)));
            }
        }
        {
            const float4* tb = (const float4*)&g_t2[(size_t)(e0 + el) * 64 + half * 32];
            float part = 0.f;
#pragma unroll
            for (int m = 0; m < 8; m++) {
                float4 v = tb[m];
                int c = half * 32 + 4 * m;
                part += silu_f(fmaf(v.x, sDA[c], sDB[c])) * sWc2[c];
                part += silu_f(fmaf(v.y, sDA[c + 1], sDB[c + 1])) * sWc2[c + 1];
                part += silu_f(fmaf(v.z, sDA[c + 2], sDB[c + 2])) * sWc2[c + 2];
                part += silu_f(fmaf(v.w, sDA[c + 3], sDB[c + 3])) * sWc2[c + 3];
            }
            part += __shfl_xor_sync(0xffffffffu, part, 1);
            if (half == 0) g_sc[e0 + el] = part + cbias;
        }
        __syncthreads();
        float c[8][4];
#pragma unroll
        for (int nb = 0; nb < 8; nb++)
#pragma unroll
            for (int j = 0; j < 4; j++) c[nb][j] = 0.f;
#pragma unroll
        for (int kb = 0; kb < 8; kb++) {
#pragma unroll
            for (int nb = 0; nb < 8; nb++) {
                uint32_t bh0 = sXh[nb * 8 + gid][kb * 8 + tig];
                uint32_t bh1 = sXh[nb * 8 + gid][kb * 8 + tig + 4];
                uint32_t bl0 = sXl[nb * 8 + gid][kb * 8 + tig];
                uint32_t bl1 = sXl[nb * 8 + gid][kb * 8 + tig + 4];
                mma_tf32(c[nb], ah[kb][0], ah[kb][1], ah[kb][2], ah[kb][3], bh0, bh1);
                mma_tf32(c[nb], ah[kb][0], ah[kb][1], ah[kb][2], ah[kb][3], bl0, bl1);
                mma_tf32(c[nb], al[kb][0], al[kb][1], al[kb][2], al[kb][3], bh0, bh1);
            }
        }
        __syncthreads();
        float* sOut = (float*)&sXh[0][0];
#pragma unroll
        for (int nb = 0; nb < 8; nb++) {
            int e = nb * 8 + 2 * tig;
            float y00 = c[nb][0] + bias0;
            float y01 = c[nb][1] + bias0;
            float y10 = c[nb][2] + bias1;
            float y11 = c[nb][3] + bias1;
            sOut[e * 68 + m0 + gid] = y00;
            sOut[(e + 1) * 68 + m0 + gid] = y01;
            sOut[e * 68 + m0 + gid + 8] = y10;
            sOut[(e + 1) * 68 + m0 + gid + 8] = y11;
            s0 += y00 + y01; q0 += y00 * y00 + y01 * y01;
            s1 += y10 + y11; q1 += y10 * y10 + y11 * y11;
        }
        __syncthreads();
        {
            float* dst = &g_mlin[(size_t)(e0 + el) * 64 + half * 32];
            const float* src = &sOut[el * 68 + half * 32];
#pragma unroll
            for (int m = 0; m < 8; m++)
                *(float4*)(dst + 4 * m) = *(const float4*)(src + 4 * m);
        }
    }
    __syncthreads();
    atomicAdd(&sS[m0 + gid], s0); atomicAdd(&sQ[m0 + gid], q0);
    atomicAdd(&sS[m0 + gid + 8], s1); atomicAdd(&sQ[m0 + gid + 8], q1);
    __syncthreads();
    if (tid < 64) {
        atomicAdd(&g_sum[128 + tid], (double)sS[tid]);
        atomicAdd(&g_sumsq[128 + tid], (double)sQ[tid]);
    }
}

// ---------------- aggregation: warp per node, contiguous CSR rows ----------------
__global__ __launch_bounds__(256) void k_aggr()
{
    int gwarp = (blockIdx.x * blockDim.x + threadIdx.x) >> 5;
    int lane = threadIdx.x & 31;
    if (gwarp >= NN) return;
    int n = gwarp;
    int s0 = g_rowstart[n], s1 = g_rowstart[n + 1];
    float A0 = g_bnA[128 + lane], B0 = g_bnB[128 + lane];
    float A1 = g_bnA[160 + lane], B1 = g_bnB[160 + lane];
    float acc0 = 0.f, acc1 = 0.f;
    for (int i = s0; i < s1; i++) {
        float m0 = g_mlin[(size_t)i * 64 + lane];
        float m1 = g_mlin[(size_t)i * 64 + 32 + lane];
        acc0 += silu_f(fmaf(m0, A0, B0));
        acc1 += silu_f(fmaf(m1, A1, B1));
    }
    g_u[(size_t)n * 128 + 64 + lane] = acc0;
    g_u[(size_t)n * 128 + 96 + lane] = acc1;
    float px = g_pos[n * 3], py = g_pos[n * 3 + 1], pz = g_pos[n * 3 + 2];
    float cx = 0.f, cy = 0.f, cz = 0.f;
    for (int i = s0 + lane; i < s1; i += 32) {
        int src = g_csrsrc[i];
        float sc = g_sc[i];
        cx += sc * (px - g_pos[src * 3]);
        cy += sc * (py - g_pos[src * 3 + 1]);
        cz += sc * (pz - g_pos[src * 3 + 2]);
    }
#pragma unroll
    for (int o = 16; o > 0; o >>= 1) {
        cx += __shfl_xor_sync(0xffffffffu, cx, o);
        cy += __shfl_xor_sync(0xffffffffu, cy, o);
        cz += __shfl_xor_sync(0xffffffffu, cz, o);
    }
    if (lane == 0) {
        g_aggr_p[n * 3 + 0] = cx;
        g_aggr_p[n * 3 + 1] = cy;
        g_aggr_p[n * 3 + 2] = cz;
    }
}

// ---------------- node 1: tiled 64n x 64o, K=128 ----------------
__global__ __launch_bounds__(256) void k_node1(const float* __restrict__ uw1, const float* __restrict__ ub1)
{
    __shared__ __align__(16) float sW[64][64];
    __shared__ __align__(16) float sA[64][64];
    __shared__ float sS[64], sQ[64];
    int tid = threadIdx.x, tx = tid & 15, ty = tid >> 4;
    if (tid < 64) { sS[tid] = 0.f; sQ[tid] = 0.f; }
    float bb[4];
#pragma unroll
    for (int j = 0; j < 4; j++) bb[j] = ub1[(ty << 2) + j];
    float st[4] = {0.f, 0.f, 0.f, 0.f}, sq[4] = {0.f, 0.f, 0.f, 0.f};
    int ntiles = (NN + 63) >> 6;
    for (int t = blockIdx.x; t < ntiles; t += gridDim.x) {
        int n0 = t << 6;
        float acc[4][4];
#pragma unroll
        for (int i = 0; i < 4; i++)
#pragma unroll
            for (int j = 0; j < 4; j++) acc[i][j] = 0.f;
        for (int half = 0; half < 2; half++) {
            __syncthreads();
            for (int i = tid; i < 1024; i += 256) {
                int o = i & 63, k0 = (i >> 6) << 2;
                float4 v = *(const float4*)&uw1[o * 128 + half * 64 + k0];
                sW[k0 + 0][o] = v.x; sW[k0 + 1][o] = v.y;
                sW[k0 + 2][o] = v.z; sW[k0 + 3][o] = v.w;
            }
            {
                int nn = tid >> 2, k0 = (tid & 3) << 4;
                int n = n0 + nn;
#pragma unroll
                for (int m = 0; m < 4; m++) {
                    float4 v = (n < NN) ? *(const float4*)&g_u[(size_t)n * 128 + half * 64 + k0 + 4 * m]
                                        : make_float4(0.f, 0.f, 0.f, 0.f);
                    sA[k0 + 4 * m + 0][nn] = v.x;
                    sA[k0 + 4 * m + 1][nn] = v.y;
                    sA[k0 + 4 * m + 2][nn] = v.z;
                    sA[k0 + 4 * m + 3][nn] = v.w;
                }
            }
            __syncthreads();
#pragma unroll 4
            for (int k = 0; k < 64; k++) {
                float4 a = *(const float4*)&sA[k][tx << 2];
                float4 b = *(const float4*)&sW[k][ty << 2];
                float av[4] = {a.x, a.y, a.z, a.w};
                float bv[4] = {b.x, b.y, b.z, b.w};
#pragma unroll
                for (int i = 0; i < 4; i++)
#pragma unroll
                    for (int j = 0; j < 4; j++) acc[i][j] = fmaf(av[i], bv[j], acc[i][j]);
            }
        }
#pragma unroll
        for (int i = 0; i < 4; i++) {
            int n = n0 + (tx << 2) + i;
            if (n < NN) {
                float y0 = acc[i][0] + bb[0], y1 = acc[i][1] + bb[1];
                float y2 = acc[i][2] + bb[2], y3 = acc[i][3] + bb[3];
                *(float4*)&g_un[n * 64 + (ty << 2)] = make_float4(y0, y1, y2, y3);
                st[0] += y0; sq[0] += y0 * y0; st[1] += y1; sq[1] += y1 * y1;
                st[2] += y2; sq[2] += y2 * y2; st[3] += y3; sq[3] += y3 * y3;
            }
        }
    }
    __syncthreads();
#pragma unroll
    for (int j = 0; j < 4; j++) {
        atomicAdd(&sS[(ty << 2) + j], st[j]);
        atomicAdd(&sQ[(ty << 2) + j], sq[j]);
    }
    __syncthreads();
    if (tid < 64) {
        atomicAdd(&g_sum[192 + tid], (double)sS[tid]);
        atomicAdd(&g_sumsq[192 + tid], (double)sQ[tid]);
    }
}

// ---------------- node 2: tiled 64n x 64o, K=64; residual + pos update ----------------
__global__ __launch_bounds__(256) void k_node2(const float* __restrict__ uw2, const float* __restrict__ ub2)
{
    __shared__ __align__(16) float sW[64][64];
    __shared__ __align__(16) float sA[64][64];
    int tid = threadIdx.x, tx = tid & 15, ty = tid >> 4;
    for (int i = tid; i < 1024; i += 256) {
        int o = i & 63, k0 = (i >> 6) << 2;
        float4 v = *(const float4*)&uw2[o * 64 + k0];
        sW[k0 + 0][o] = v.x; sW[k0 + 1][o] = v.y;
        sW[k0 + 2][o] = v.z; sW[k0 + 3][o] = v.w;
    }
    int k0s = (tid & 3) << 4;
    float4 cA[4], cB[4];
#pragma unroll
    for (int m = 0; m < 4; m++) {
        cA[m] = *(const float4*)&g_bnA[192 + k0s + 4 * m];
        cB[m] = *(const float4*)&g_bnB[192 + k0s + 4 * m];
    }
    float bb[4];
#pragma unroll
    for (int j = 0; j < 4; j++) bb[j] = ub2[(ty << 2) + j];
    int ntiles = (NN + 63) >> 6;
    for (int t = blockIdx.x; t < ntiles; t += gridDim.x) {
        int n0 = t << 6;
        __syncthreads();
        {
            int nn = tid >> 2;
            int n = n0 + nn;
#pragma unroll
            for (int m = 0; m < 4; m++) {
                float4 v = (n < NN) ? *(const float4*)&g_un[(size_t)n * 64 + k0s + 4 * m]
                                    : make_float4(0.f, 0.f, 0.f, 0.f);
                sA[k0s + 4 * m + 0][nn] = silu_f(fmaf(v.x, cA[m].x, cB[m].x));
                sA[k0s + 4 * m + 1][nn] = silu_f(fmaf(v.y, cA[m].y, cB[m].y));
                sA[k0s + 4 * m + 2][nn] = silu_f(fmaf(v.z, cA[m].z, cB[m].z));
                sA[k0s + 4 * m + 3][nn] = silu_f(fmaf(v.w, cA[m].w, cB[m].w));
            }
        }
        __syncthreads();
        float acc[4][4];
#pragma unroll
        for (int i = 0; i < 4; i++)
#pragma unroll
            for (int j = 0; j < 4; j++) acc[i][j] = 0.f;
#pragma unroll 4
        for (int k = 0; k < 64; k++) {
            float4 a = *(const float4*)&sA[k][tx << 2];
            float4 b = *(const float4*)&sW[k][ty << 2];
            float av[4] = {a.x, a.y, a.z, a.w};
            float bv[4] = {b.x, b.y, b.z, b.w};
#pragma unroll
            for (int i = 0; i < 4; i++)
#pragma unroll
                for (int j = 0; j < 4; j++) acc[i][j] = fmaf(av[i], bv[j], acc[i][j]);
        }
#pragma unroll
        for (int i = 0; i < 4; i++) {
            int n = n0 + (tx << 2) + i;
            if (n < NN) {
                float4 hold = *(const float4*)&g_h[n * 64 + (ty << 2)];
                float h0 = hold.x + acc[i][0] + bb[0];
                float h1 = hold.y + acc[i][1] + bb[1];
                float h2 = hold.z + acc[i][2] + bb[2];
                float h3 = hold.w + acc[i][3] + bb[3];
                float4 hv = make_float4(h0, h1, h2, h3);
                *(float4*)&g_h[n * 64 + (ty << 2)] = hv;
                *(float4*)&g_u[(size_t)n * 128 + (ty << 2)] = hv;
            }
        }
        if (tid < 64) {
            int n = n0 + tid;
            if (n < NN) {
                g_pos[n * 3 + 0] += g_aggr_p[n * 3 + 0];
                g_pos[n * 3 + 1] += g_aggr_p[n * 3 + 1];
                g_pos[n * 3 + 2] += g_aggr_p[n * 3 + 2];
            }
        }
    }
}

// ---------------- pooling ----------------
__global__ void k_pool(const int* __restrict__ batch)
{
    int idx = blockIdx.x * blockDim.x + threadIdx.x;
    if (idx >= NN * 16) return;
    int n = idx >> 4, c4 = (idx & 15) * 4;
    int b = batch[n];
    float4 h = *(const float4*)&g_h[n * 64 + c4];
    red_add_v4(&g_pool[b * 64 + c4], h.x, h.y, h.z, h.w);
    if (c4 == 0) atomicAdd(&g_cnt[b], 1.0f);
}

__global__ void k_pred(const float* __restrict__ w, const float* __restrict__ b,
                       float* __restrict__ out)
{
    int g = blockIdx.x, lane = threadIdx.x;
    float p = g_pool[g * 64 + lane] * w[lane] + g_pool[g * 64 + 32 + lane] * w[32 + lane];
#pragma unroll
    for (int o = 16; o > 0; o >>= 1) p += __shfl_xor_sync(0xffffffffu, p, o);
    if (lane == 0) out[g] = p / fmaxf(g_cnt[g], 1.0f) + b[0];
}

// ---------------- launch ----------------
extern "C" void kernel_launch(void* const* d_in, const int* in_sizes, int n_in,
                              void* d_out, int out_size)
{
    const float* node_s    = (const float*)d_in[0];
    const float* node_type = (const float*)d_in[1];
    const float* pos       = (const float*)d_in[2];
    const int*   ei        = (const int*)d_in[3];
    const float* edge_s    = (const float*)d_in[4];
    const int*   batch     = (const int*)d_in[5];
    const float* lin_in_w  = (const float*)d_in[6];
    const float* lin_in_b  = (const float*)d_in[7];
    const float* msg_w1    = (const float*)d_in[8];
    const float* msg_b1    = (const float*)d_in[9];
    const float* msg_g1    = (const float*)d_in[10];
    const float* msg_be1   = (const float*)d_in[11];
    const float* msg_w2    = (const float*)d_in[12];
    const float* msg_b2    = (const float*)d_in[13];
    const float* msg_g2    = (const float*)d_in[14];
    const float* msg_be2   = (const float*)d_in[15];
    const float* updf_w1   = (const float*)d_in[16];
    const float* updf_b1   = (const float*)d_in[17];
    const float* updf_g1   = (const float*)d_in[18];
    const float* updf_be1  = (const float*)d_in[19];
    const float* updf_w2   = (const float*)d_in[20];
    const float* updf_b2   = (const float*)d_in[21];
    const float* updc_w1   = (const float*)d_in[22];
    const float* updc_b1   = (const float*)d_in[23];
    const float* updc_g1   = (const float*)d_in[24];
    const float* updc_be1  = (const float*)d_in[25];
    const float* updc_w2   = (const float*)d_in[26];
    const float* updc_b2   = (const float*)d_in[27];
    const float* lin_pred_w = (const float*)d_in[28];
    const float* lin_pred_b = (const float*)d_in[29];

    k_init<<<(NN * 64 + 255) / 256, 256>>>(node_s, node_type, pos, lin_in_w, lin_in_b);
    k_hist<<<(NE + 255) / 256, 256>>>(ei);
    k_scan<<<1, 1024>>>();
    k_fill<<<(NE + 255) / 256, 256>>>(ei);
    k_wpack_all<<<(NL * 64 * 256 + 255) / 256, 256>>>(msg_w1, updc_w1);

    for (int l = 0; l < NL; l++) {
        const float* mw1 = msg_w1 + (size_t)l * 64 * 161;
        const float* mb1 = msg_b1 + l * 64;
        const float* mw2 = msg_w2 + (size_t)l * 64 * 64;
        const float* mb2 = msg_b2 + l * 64;
        const float* cw1 = updc_w1 + (size_t)l * 64 * 161;
        const float* cb1 = updc_b1 + l * 64;
        const float* cw2 = updc_w2 + (size_t)l * 64;
        const float* cb2 = updc_b2 + l;
        const float* uw1 = updf_w1 + (size_t)l * 64 * 128;
        const float* ub1 = updf_b1 + l * 64;
        const float* uw2 = updf_w2 + (size_t)l * 64 * 64;
        const float* ub2 = updf_b2 + l * 64;

        k_hpre<<<592, 256>>>(l);
        k_edgeAmma<<<592, 256>>>(edge_s, mw1, mb1, cw1, cb1);
        k_bnfin<<<1, 128>>>(0, 128, 1.0 / NE,
                            msg_g1 + l * 64, msg_be1 + l * 64,
                            updc_g1 + l * 64, updc_be1 + l * 64);
        k_edgeBmma<<<888, 128>>>(mw2, mb2, cw2, cb2);
        k_bnfin<<<1, 64>>>(128, 64, 1.0 / NE,
                           msg_g2 + l * 64, msg_be2 + l * 64,
                           msg_g2 + l * 64, msg_be2 + l * 64);
        k_aggr<<<(NN * 32 + 255) / 256, 256>>>();
        k_node1<<<592, 256>>>(uw1, ub1);
        k_bnfin<<<1, 64>>>(192, 64, 1.0 / NN,
                           updf_g1 + l * 64, updf_be1 + l * 64,
                           updf_g1 + l * 64, updf_be1 + l * 64);
        k_node2<<<592, 256>>>(uw2, ub2);
    }

    k_pool<<<(NN * 16 + 255) / 256, 256>>>(batch);
    k_pred<<<NG, 32>>>(lin_pred_w, lin_pred_b, (float*)d_out);
}

// round 10
// speedup vs baseline: 2.0946x; 1.2047x over previous
#include <cuda_runtime.h>
#include <cuda_fp16.h>
#include <math.h>
#include <stdint.h>

#define NN 50000
#define NE 800000
#define NL 4
#define NG 64
#define EPS 1e-5f

// ---------------- static device scratch ----------------
__device__ __align__(16) float g_h[NN * 64];
__device__ __align__(16) float g_u[NN * 128];      // [h | aggr_h]
__device__ __align__(16) float g_un[NN * 64];
__device__ __align__(16) float g_pos[NN * 3];
__device__ __align__(16) float g_aggr_p[NN * 3];
__device__ __align__(16) __half g_HpreH[(size_t)NN * 256];   // fp16, 25.6MB (L2-resident)
__device__ __align__(16) float g_wpack4[NL][64 * 256];       // k-major [k][op]
__device__ __align__(16) __half g_t1h[(size_t)NE * 64];      // CSR-ordered, fp16
__device__ __align__(16) __half g_t2h[(size_t)NE * 64];      // CSR-ordered, fp16
__device__ __align__(16) __half g_mlinh[(size_t)NE * 64];    // CSR-ordered, fp16
__device__ __align__(16) float g_sc[NE];                     // CSR-ordered
__device__ int g_deg[NN];
__device__ int g_rowstart[NN + 1];
__device__ int g_cursor[NN];
__device__ int g_csrsrc[NE];
__device__ int g_csrdst[NE];
__device__ int g_csre[NE];
__device__ double g_sum[256];
__device__ double g_sumsq[256];
__device__ __align__(16) float g_bnA[256];
__device__ __align__(16) float g_bnB[256];
__device__ __align__(16) float g_pool[NG * 64];
__device__ float g_cnt[NG];

__device__ __forceinline__ float silu_f(float y) {
    return y * (1.0f / (1.0f + __expf(-y)));
}

__device__ __forceinline__ void red_add_v4(float* p, float a, float b, float c, float d) {
    asm volatile("red.global.add.v4.f32 [%0], {%1,%2,%3,%4};"
                 :: "l"(p), "f"(a), "f"(b), "f"(c), "f"(d) : "memory");
}

__device__ __forceinline__ uint32_t f2tf32(float f) {
    uint32_t u;
    asm("cvt.rna.tf32.f32 %0, %1;" : "=r"(u) : "f"(f));
    return u;
}

__device__ __forceinline__ void mma_tf32(float* c, uint32_t a0, uint32_t a1, uint32_t a2, uint32_t a3,
                                         uint32_t b0, uint32_t b1) {
    asm volatile("mma.sync.aligned.m16n8k8.row.col.f32.tf32.tf32.f32 "
                 "{%0,%1,%2,%3}, {%4,%5,%6,%7}, {%8,%9}, {%0,%1,%2,%3};"
                 : "+f"(c[0]), "+f"(c[1]), "+f"(c[2]), "+f"(c[3])
                 : "r"(a0), "r"(a1), "r"(a2), "r"(a3), "r"(b0), "r"(b1));
}

// ---------------- init ----------------
__global__ void k_init(const float* __restrict__ ns, const float* __restrict__ nt,
                       const float* __restrict__ pos, const float* __restrict__ w,
                       const float* __restrict__ b)
{
    int idx = blockIdx.x * blockDim.x + threadIdx.x;
    if (idx < NG * 64) g_pool[idx] = 0.f;
    if (idx < NG) g_cnt[idx] = 0.f;
    if (idx < 256) { g_sum[idx] = 0.0; g_sumsq[idx] = 0.0; }
    if (idx < NN) g_deg[idx] = 0;
    if (idx >= NN * 64) return;
    int n = idx >> 6, o = idx & 63;
    const float* wr = w + o * 8;
    const float* s = ns + n * 6;
    float acc = b[o];
#pragma unroll
    for (int i = 0; i < 6; i++) acc = fmaf(s[i], wr[i], acc);
    acc = fmaf(nt[n * 2 + 0], wr[6], acc);
    acc = fmaf(nt[n * 2 + 1], wr[7], acc);
    g_h[idx] = acc;
    g_u[(size_t)n * 128 + o] = acc;
    if (o < 3) g_pos[n * 3 + o] = pos[n * 3 + o];
}

// ---------------- CSR build ----------------
__global__ void k_hist(const int* __restrict__ ei)
{
    int e = blockIdx.x * blockDim.x + threadIdx.x;
    if (e < NE) atomicAdd(&g_deg[ei[NE + e]], 1);
}

__global__ __launch_bounds__(1024) void k_scan()
{
    __shared__ int ssum[1024];
    int t = threadIdx.x;
    const int C = 49;
    int begin = t * C;
    int end = begin + C; if (end > NN) end = NN;
    if (begin > NN) begin = NN;
    int s = 0;
    for (int i = begin; i < end; i++) s += g_deg[i];
    ssum[t] = s;
    __syncthreads();
    for (int off = 1; off < 1024; off <<= 1) {
        int v = (t >= off) ? ssum[t - off] : 0;
        __syncthreads();
        ssum[t] += v;
        __syncthreads();
    }
    int run = ssum[t] - s;
    for (int i = begin; i < end; i++) {
        g_rowstart[i] = run;
        g_cursor[i] = run;
        run += g_deg[i];
    }
    if (t == 1023) g_rowstart[NN] = ssum[1023];
}

__global__ void k_fill(const int* __restrict__ ei)
{
    int e = blockIdx.x * blockDim.x + threadIdx.x;
    if (e >= NE) return;
    int s = ei[e], d = ei[NE + e];
    int p = atomicAdd(&g_cursor[d], 1);
    g_csrsrc[p] = s;
    g_csrdst[p] = d;
    g_csre[p] = e;
}

// ---------------- pack h-columns of msg_w1/updc_w1 for ALL layers ----------------
__global__ void k_wpack_all(const float* __restrict__ mw1a, const float* __restrict__ cw1a)
{
    int idx = blockIdx.x * blockDim.x + threadIdx.x;
    if (idx >= NL * 64 * 256) return;
    int l = idx >> 14;
    int r = idx & 16383;
    int k = r >> 8, op = r & 255, o = op & 63;
    const float* mw1 = mw1a + (size_t)l * 64 * 161;
    const float* cw1 = cw1a + (size_t)l * 64 * 161;
    float v;
    if (op < 64)       v = mw1[o * 161 + k];
    else if (op < 128) v = mw1[o * 161 + 64 + k];
    else if (op < 192) v = cw1[o * 161 + k];
    else               v = cw1[o * 161 + 64 + k];
    g_wpack4[l][k * 256 + op] = v;
}

// ---------------- Hpre: tiled GEMM 64n x 128o (2 phases), K=64; fp16 output ----------------
__global__ __launch_bounds__(256) void k_hpre(int layer)
{
    const float* wpack = g_wpack4[layer];
    __shared__ __align__(16) float sA[64][64];
    __shared__ __align__(16) float sB[64][128];
    int tid = threadIdx.x, tx = tid & 15, ty = tid >> 4;
    int ntiles = (NN + 63) >> 6;
    for (int t = blockIdx.x; t < ntiles; t += gridDim.x) {
        int n0 = t << 6;
        __syncthreads();
        {
            int nn = tid >> 2, k0 = (tid & 3) << 4;
            int n = n0 + nn;
#pragma unroll
            for (int m = 0; m < 4; m++) {
                float4 v = (n < NN) ? *(const float4*)&g_h[n * 64 + k0 + 4 * m]
                                    : make_float4(0.f, 0.f, 0.f, 0.f);
                sA[k0 + 4 * m + 0][nn] = v.x;
                sA[k0 + 4 * m + 1][nn] = v.y;
                sA[k0 + 4 * m + 2][nn] = v.z;
                sA[k0 + 4 * m + 3][nn] = v.w;
            }
        }
        for (int ph = 0; ph < 2; ph++) {
            __syncthreads();
#pragma unroll
            for (int r = 0; r < 8; r++) {
                int i = tid + r * 256;
                int k = i >> 5, o4 = (i & 31) << 2;
                *(float4*)&sB[k][o4] = *(const float4*)&wpack[k * 256 + ph * 128 + o4];
            }
            __syncthreads();
            float acc[4][8];
#pragma unroll
            for (int i = 0; i < 4; i++)
#pragma unroll
                for (int j = 0; j < 8; j++) acc[i][j] = 0.f;
#pragma unroll 4
            for (int k = 0; k < 64; k++) {
                float4 a = *(const float4*)&sA[k][tx << 2];
                float4 b0 = *(const float4*)&sB[k][ty << 3];
                float4 b1 = *(const float4*)&sB[k][(ty << 3) + 4];
                float av[4] = {a.x, a.y, a.z, a.w};
                float bv[8] = {b0.x, b0.y, b0.z, b0.w, b1.x, b1.y, b1.z, b1.w};
#pragma unroll
                for (int i = 0; i < 4; i++)
#pragma unroll
                    for (int j = 0; j < 8; j++) acc[i][j] = fmaf(av[i], bv[j], acc[i][j]);
            }
#pragma unroll
            for (int i = 0; i < 4; i++) {
                int n = n0 + (tx << 2) + i;
                if (n < NN) {
                    __half hv[8];
#pragma unroll
                    for (int j = 0; j < 8; j++) hv[j] = __float2half_rn(acc[i][j]);
                    *(uint4*)&g_HpreH[(size_t)n * 256 + ph * 128 + (ty << 3)] = *(uint4*)hv;
                }
            }
        }
    }
}

// ---------------- edge A (tf32 MMA, CSR order, fp16 scratch) ----------------
// 256 threads, 8 warps; tile = 64 CSR positions x 128 ch. Warp w covers ch [16w, 16w+16).
__global__ __launch_bounds__(256) void k_edgeAmma(const float* __restrict__ es,
                                                  const float* __restrict__ mw1, const float* __restrict__ mb1,
                                                  const float* __restrict__ cw1, const float* __restrict__ cb1)
{
    __shared__ __align__(16) uint32_t sBuf[64 * 132];      // 33.8KB (staging | output)
    uint32_t (*sBh)[36] = (uint32_t(*)[36])sBuf;
    uint32_t (*sBl)[36] = (uint32_t(*)[36])(sBuf + 64 * 36);
    float (*sOut)[132] = (float(*)[132])sBuf;
    __shared__ float sR[64];
    __shared__ int sSrc[64], sDst[64];
    __shared__ float sS[128], sQ[128];

    int tid = threadIdx.x;
    int warp = tid >> 5, lane = tid & 31;
    int gid = lane >> 2, tig = lane & 3;

    if (tid < 128) { sS[tid] = 0.f; sQ[tid] = 0.f; }

    uint32_t ah[4][4], al[4][4];
    {
        int r0 = warp * 16 + gid;
        int r1 = r0 + 8;
        const float* w0 = (r0 < 64) ? &mw1[r0 * 161 + 129] : &cw1[(r0 - 64) * 161 + 129];
        const float* w1 = (r1 < 64) ? &mw1[r1 * 161 + 129] : &cw1[(r1 - 64) * 161 + 129];
#pragma unroll
        for (int kb = 0; kb < 4; kb++) {
            float f[4];
            f[0] = w0[kb * 8 + tig];     f[1] = w1[kb * 8 + tig];
            f[2] = w0[kb * 8 + tig + 4]; f[3] = w1[kb * 8 + tig + 4];
#pragma unroll
            for (int j = 0; j < 4; j++) {
                uint32_t h = f2tf32(f[j]);
                ah[kb][j] = h;
                al[kb][j] = f2tf32(f[j] - __uint_as_float(h));
            }
        }
    }
    int ch0 = lane << 2;
    float wr4[4], bb4[4];
#pragma unroll
    for (int j = 0; j < 4; j++) {
        int ch = ch0 + j;
        wr4[j] = (ch < 64) ? mw1[ch * 161 + 128] : cw1[(ch - 64) * 161 + 128];
        bb4[j] = (ch < 64) ? mb1[ch] : cb1[ch - 64];
    }
    int hd_off = (ch0 < 64) ? ch0 : 64 + ch0;
    int hs_off = (ch0 < 64) ? 64 + ch0 : 128 + ch0;
    float st[4] = {0.f, 0.f, 0.f, 0.f}, sq[4] = {0.f, 0.f, 0.f, 0.f};

    for (int t = blockIdx.x; t < NE / 64; t += gridDim.x) {
        int p0 = t << 6;
        __syncthreads();
        if (tid < 64) {
            int p = p0 + tid;
            int s = g_csrsrc[p], d = g_csrdst[p];
            sSrc[tid] = s; sDst[tid] = d;
            float dx = g_pos[d * 3] - g_pos[s * 3];
            float dy = g_pos[d * 3 + 1] - g_pos[s * 3 + 1];
            float dz = g_pos[d * 3 + 2] - g_pos[s * 3 + 2];
            sR[tid] = sqrtf(dx * dx + dy * dy + dz * dz);
        }
        {
            int el = tid >> 2, koff = (tid & 3) << 3;
            int eid = g_csre[p0 + el];
            const float4* ep = (const float4*)&es[(size_t)eid * 32 + koff];
            float4 v0 = ep[0];
            float4 v1 = ep[1];
            uint32_t h;
            h = f2tf32(v0.x); sBh[el][koff + 0] = h; sBl[el][koff + 0] = f2tf32(v0.x - __uint_as_float(h));
            h = f2tf32(v0.y); sBh[el][koff + 1] = h; sBl[el][koff + 1] = f2tf32(v0.y - __uint_as_float(h));
            h = f2tf32(v0.z); sBh[el][koff + 2] = h; sBl[el][koff + 2] = f2tf32(v0.z - __uint_as_float(h));
            h = f2tf32(v0.w); sBh[el][koff + 3] = h; sBl[el][koff + 3] = f2tf32(v0.w - __uint_as_float(h));
            h = f2tf32(v1.x); sBh[el][koff + 4] = h; sBl[el][koff + 4] = f2tf32(v1.x - __uint_as_float(h));
            h = f2tf32(v1.y); sBh[el][koff + 5] = h; sBl[el][koff + 5] = f2tf32(v1.y - __uint_as_float(h));
            h = f2tf32(v1.z); sBh[el][koff + 6] = h; sBl[el][koff + 6] = f2tf32(v1.z - __uint_as_float(h));
            h = f2tf32(v1.w); sBh[el][koff + 7] = h; sBl[el][koff + 7] = f2tf32(v1.w - __uint_as_float(h));
        }
        __syncthreads();
        float c[8][4];
#pragma unroll
        for (int nb = 0; nb < 8; nb++)
#pragma unroll
            for (int j = 0; j < 4; j++) c[nb][j] = 0.f;
#pragma unroll
        for (int kb = 0; kb < 4; kb++) {
#pragma unroll
            for (int nb = 0; nb < 8; nb++) {
                uint32_t bh0 = sBh[nb * 8 + gid][kb * 8 + tig];
                uint32_t bh1 = sBh[nb * 8 + gid][kb * 8 + tig + 4];
                uint32_t bl0 = sBl[nb * 8 + gid][kb * 8 + tig];
                uint32_t bl1 = sBl[nb * 8 + gid][kb * 8 + tig + 4];
                mma_tf32(c[nb], ah[kb][0], ah[kb][1], ah[kb][2], ah[kb][3], bh0, bh1);
                mma_tf32(c[nb], ah[kb][0], ah[kb][1], ah[kb][2], ah[kb][3], bl0, bl1);
                mma_tf32(c[nb], al[kb][0], al[kb][1], al[kb][2], al[kb][3], bh0, bh1);
            }
        }
        __syncthreads();
        {
            int ch = warp * 16 + gid;
#pragma unroll
            for (int nb = 0; nb < 8; nb++) {
                int e = nb * 8 + 2 * tig;
                sOut[e][ch] = c[nb][0];
                sOut[e + 1][ch] = c[nb][1];
                sOut[e][ch + 8] = c[nb][2];
                sOut[e + 1][ch + 8] = c[nb][3];
            }
        }
        __syncthreads();
        // epilogue: fp16 Hpre gather, fp16 store, stats on rounded values
#pragma unroll 2
        for (int ee = 0; ee < 8; ee++) {
            int e = warp * 8 + ee;
            int d = sDst[e], s = sSrc[e];
            float r = sR[e];
            uint2 du = *(const uint2*)&g_HpreH[(size_t)d * 256 + hd_off];
            uint2 su = *(const uint2*)&g_HpreH[(size_t)s * 256 + hs_off];
            float2 d01 = __half22float2(*(__half2*)&du.x);
            float2 d23 = __half22float2(*(__half2*)&du.y);
            float2 s01 = __half22float2(*(__half2*)&su.x);
            float2 s23 = __half22float2(*(__half2*)&su.y);
            float4 o = *(const float4*)&sOut[e][ch0];
            __half hv[4];
            hv[0] = __float2half_rn(o.x + d01.x + s01.x + fmaf(r, wr4[0], bb4[0]));
            hv[1] = __float2half_rn(o.y + d01.y + s01.y + fmaf(r, wr4[1], bb4[1]));
            hv[2] = __float2half_rn(o.z + d23.x + s23.x + fmaf(r, wr4[2], bb4[2]));
            hv[3] = __float2half_rn(o.w + d23.y + s23.y + fmaf(r, wr4[3], bb4[3]));
            int p = p0 + e;
            __half* out = (ch0 < 64) ? &g_t1h[(size_t)p * 64 + ch0]
                                     : &g_t2h[(size_t)p * 64 + ch0 - 64];
            *(uint2*)out = *(uint2*)hv;
#pragma unroll
            for (int j = 0; j < 4; j++) {
                float yr = __half2float(hv[j]);
                st[j] += yr; sq[j] += yr * yr;
            }
        }
    }
    __syncthreads();
#pragma unroll
    for (int j = 0; j < 4; j++) { atomicAdd(&sS[ch0 + j], st[j]); atomicAdd(&sQ[ch0 + j], sq[j]); }
    __syncthreads();
    if (tid < 128) {
        atomicAdd(&g_sum[tid], (double)sS[tid]);
        atomicAdd(&g_sumsq[tid], (double)sQ[tid]);
    }
}

// ---------------- BN finalize (self-resetting stats) ----------------
__global__ void k_bnfin(int off, int n, double inv,
                        const float* __restrict__ g0, const float* __restrict__ b0,
                        const float* __restrict__ g1, const float* __restrict__ b1)
{
    int c = threadIdx.x;
    if (c >= n) return;
    double m = g_sum[off + c] * inv;
    double v = g_sumsq[off + c] * inv - m * m;
    g_sum[off + c] = 0.0;
    g_sumsq[off + c] = 0.0;
    float gg = (c < 64) ? g0[c] : g1[c - 64];
    float bb = (c < 64) ? b0[c] : b1[c - 64];
    float A = gg * rsqrtf((float)v + EPS);
    g_bnA[off + c] = A;
    g_bnB[off + c] = bb - (float)m * A;
}

// ---------------- edge B (tf32 MMA, 256 thr, fp16 scratch): mlin = silu(bn(t1)) @ msg_w2^T + b ----------------
// 8 warps: mwarp=warp&3 covers out rows [16m,16m+16); nwarp=warp>>2 covers edges [32n,32n+32)
__global__ __launch_bounds__(256) void k_edgeBmma(const float* __restrict__ mw2, const float* __restrict__ mb2,
                                                  const float* __restrict__ cw2, const float* __restrict__ cb2)
{
    __shared__ uint32_t sXh[64][68];
    __shared__ uint32_t sXl[64][68];
    __shared__ float sS[64], sQ[64];
    __shared__ float sCA[64], sCB[64], sDA[64], sDB[64], sWc2[64];

    int tid = threadIdx.x;
    int warp = tid >> 5, lane = tid & 31;
    int gid = lane >> 2, tig = lane & 3;
    int m0 = (warp & 3) << 4;
    int n0 = (warp >> 2) << 5;

    if (tid < 64) {
        sS[tid] = 0.f; sQ[tid] = 0.f;
        sCA[tid] = g_bnA[tid];        sCB[tid] = g_bnB[tid];
        sDA[tid] = g_bnA[64 + tid];   sDB[tid] = g_bnB[64 + tid];
        sWc2[tid] = cw2[tid];
    }

    uint32_t ah[8][4], al[8][4];
    {
        const float* w0 = mw2 + (size_t)(m0 + gid) * 64;
        const float* w1 = mw2 + (size_t)(m0 + gid + 8) * 64;
#pragma unroll
        for (int kb = 0; kb < 8; kb++) {
            float f[4];
            f[0] = w0[kb * 8 + tig];     f[1] = w1[kb * 8 + tig];
            f[2] = w0[kb * 8 + tig + 4]; f[3] = w1[kb * 8 + tig + 4];
#pragma unroll
            for (int j = 0; j < 4; j++) {
                uint32_t h = f2tf32(f[j]);
                ah[kb][j] = h;
                al[kb][j] = f2tf32(f[j] - __uint_as_float(h));
            }
        }
    }
    float bias0 = mb2[m0 + gid], bias1 = mb2[m0 + gid + 8];
    float cbias = cb2[0];
    float s0 = 0.f, q0 = 0.f, s1 = 0.f, q1 = 0.f;

    int el = tid >> 2, q = tid & 3;   // staging: edge el, channels [q*16, q*16+16)

    for (int t = blockIdx.x; t < NE / 64; t += gridDim.x) {
        int e0 = t << 6;
        __syncthreads();
        // stage X = silu(bn1(t1)) as tf32 hi/lo (fp16 source)
        {
            const uint4* tb = (const uint4*)&g_t1h[(size_t)(e0 + el) * 64 + q * 16];
            __half2 hbuf[8];
            *(uint4*)&hbuf[0] = tb[0];
            *(uint4*)&hbuf[4] = tb[1];
#pragma unroll
            for (int m = 0; m < 8; m++) {
                float2 f = __half22float2(hbuf[m]);
                int c = q * 16 + 2 * m;
                float x0 = silu_f(fmaf(f.x, sCA[c], sCB[c]));
                float x1 = silu_f(fmaf(f.y, sCA[c + 1], sCB[c + 1]));
                uint32_t h0 = f2tf32(x0), h1 = f2tf32(x1);
                sXh[el][c] = h0; sXh[el][c + 1] = h1;
                sXl[el][c] = f2tf32(x0 - __uint_as_float(h0));
                sXl[el][c + 1] = f2tf32(x1 - __uint_as_float(h1));
            }
        }
        // coord head: 4 threads per edge, 16 ch each -> g_sc
        {
            const uint4* tb = (const uint4*)&g_t2h[(size_t)(e0 + el) * 64 + q * 16];
            __half2 hbuf[8];
            *(uint4*)&hbuf[0] = tb[0];
            *(uint4*)&hbuf[4] = tb[1];
            float part = 0.f;
#pragma unroll
            for (int m = 0; m < 8; m++) {
                float2 f = __half22float2(hbuf[m]);
                int c = q * 16 + 2 * m;
                part += silu_f(fmaf(f.x, sDA[c], sDB[c])) * sWc2[c];
                part += silu_f(fmaf(f.y, sDA[c + 1], sDB[c + 1])) * sWc2[c + 1];
            }
            part += __shfl_xor_sync(0xffffffffu, part, 1);
            part += __shfl_xor_sync(0xffffffffu, part, 2);
            if (q == 0) g_sc[e0 + el] = part + cbias;
        }
        __syncthreads();
        // MMA: per warp C[16 out][32 edges]
        float c[4][4];
#pragma unroll
        for (int nb = 0; nb < 4; nb++)
#pragma unroll
            for (int j = 0; j < 4; j++) c[nb][j] = 0.f;
#pragma unroll
        for (int kb = 0; kb < 8; kb++) {
#pragma unroll
            for (int nb = 0; nb < 4; nb++) {
                int col = n0 + nb * 8 + gid;
                uint32_t bh0 = sXh[col][kb * 8 + tig];
                uint32_t bh1 = sXh[col][kb * 8 + tig + 4];
                uint32_t bl0 = sXl[col][kb * 8 + tig];
                uint32_t bl1 = sXl[col][kb * 8 + tig + 4];
                mma_tf32(c[nb], ah[kb][0], ah[kb][1], ah[kb][2], ah[kb][3], bh0, bh1);
                mma_tf32(c[nb], ah[kb][0], ah[kb][1], ah[kb][2], ah[kb][3], bl0, bl1);
                mma_tf32(c[nb], al[kb][0], al[kb][1], al[kb][2], al[kb][3], bh0, bh1);
            }
        }
        __syncthreads();
        // epilogue: bias + round-to-fp16 + stats, transpose through smem (reuse sXh)
        float* sOut = (float*)&sXh[0][0];
#pragma unroll
        for (int nb = 0; nb < 4; nb++) {
            int e = n0 + nb * 8 + 2 * tig;
            float yr00 = __half2float(__float2half_rn(c[nb][0] + bias0));
            float yr01 = __half2float(__float2half_rn(c[nb][1] + bias0));
            float yr10 = __half2float(__float2half_rn(c[nb][2] + bias1));
            float yr11 = __half2float(__float2half_rn(c[nb][3] + bias1));
            sOut[e * 68 + m0 + gid] = yr00;
            sOut[(e + 1) * 68 + m0 + gid] = yr01;
            sOut[e * 68 + m0 + gid + 8] = yr10;
            sOut[(e + 1) * 68 + m0 + gid + 8] = yr11;
            s0 += yr00 + yr01; q0 += yr00 * yr00 + yr01 * yr01;
            s1 += yr10 + yr11; q1 += yr10 * yr10 + yr11 * yr11;
        }
        __syncthreads();
        // coalesced fp16 store
        {
            const float* src = &sOut[el * 68 + q * 16];
            __half hv[16];
#pragma unroll
            for (int m = 0; m < 16; m++) hv[m] = __float2half_rn(src[m]);
            uint4* dst = (uint4*)&g_mlinh[(size_t)(e0 + el) * 64 + q * 16];
            dst[0] = *(uint4*)&hv[0];
            dst[1] = *(uint4*)&hv[8];
        }
    }
    __syncthreads();
    atomicAdd(&sS[m0 + gid], s0); atomicAdd(&sQ[m0 + gid], q0);
    atomicAdd(&sS[m0 + gid + 8], s1); atomicAdd(&sQ[m0 + gid + 8], q1);
    __syncthreads();
    if (tid < 64) {
        atomicAdd(&g_sum[128 + tid], (double)sS[tid]);
        atomicAdd(&g_sumsq[128 + tid], (double)sQ[tid]);
    }
}

// ---------------- aggregation: warp per node, contiguous CSR rows (fp16 mlin) ----------------
__global__ __launch_bounds__(256) void k_aggr()
{
    int gwarp = (blockIdx.x * blockDim.x + threadIdx.x) >> 5;
    int lane = threadIdx.x & 31;
    if (gwarp >= NN) return;
    int n = gwarp;
    int s0 = g_rowstart[n], s1 = g_rowstart[n + 1];
    float A0 = g_bnA[128 + lane], B0 = g_bnB[128 + lane];
    float A1 = g_bnA[160 + lane], B1 = g_bnB[160 + lane];
    float acc0 = 0.f, acc1 = 0.f;
    for (int i = s0; i < s1; i++) {
        float m0 = __half2float(g_mlinh[(size_t)i * 64 + lane]);
        float m1 = __half2float(g_mlinh[(size_t)i * 64 + 32 + lane]);
        acc0 += silu_f(fmaf(m0, A0, B0));
        acc1 += silu_f(fmaf(m1, A1, B1));
    }
    g_u[(size_t)n * 128 + 64 + lane] = acc0;
    g_u[(size_t)n * 128 + 96 + lane] = acc1;
    float px = g_pos[n * 3], py = g_pos[n * 3 + 1], pz = g_pos[n * 3 + 2];
    float cx = 0.f, cy = 0.f, cz = 0.f;
    for (int i = s0 + lane; i < s1; i += 32) {
        int src = g_csrsrc[i];
        float sc = g_sc[i];
        cx += sc * (px - g_pos[src * 3]);
        cy += sc * (py - g_pos[src * 3 + 1]);
        cz += sc * (pz - g_pos[src * 3 + 2]);
    }
#pragma unroll
    for (int o = 16; o > 0; o >>= 1) {
        cx += __shfl_xor_sync(0xffffffffu, cx, o);
        cy += __shfl_xor_sync(0xffffffffu, cy, o);
        cz += __shfl_xor_sync(0xffffffffu, cz, o);
    }
    if (lane == 0) {
        g_aggr_p[n * 3 + 0] = cx;
        g_aggr_p[n * 3 + 1] = cy;
        g_aggr_p[n * 3 + 2] = cz;
    }
}

// ---------------- node 1: tiled 64n x 64o, K=128 ----------------
__global__ __launch_bounds__(256) void k_node1(const float* __restrict__ uw1, const float* __restrict__ ub1)
{
    __shared__ __align__(16) float sW[64][64];
    __shared__ __align__(16) float sA[64][64];
    __shared__ float sS[64], sQ[64];
    int tid = threadIdx.x, tx = tid & 15, ty = tid >> 4;
    if (tid < 64) { sS[tid] = 0.f; sQ[tid] = 0.f; }
    float bb[4];
#pragma unroll
    for (int j = 0; j < 4; j++) bb[j] = ub1[(ty << 2) + j];
    float st[4] = {0.f, 0.f, 0.f, 0.f}, sq[4] = {0.f, 0.f, 0.f, 0.f};
    int ntiles = (NN + 63) >> 6;
    for (int t = blockIdx.x; t < ntiles; t += gridDim.x) {
        int n0 = t << 6;
        float acc[4][4];
#pragma unroll
        for (int i = 0; i < 4; i++)
#pragma unroll
            for (int j = 0; j < 4; j++) acc[i][j] = 0.f;
        for (int half = 0; half < 2; half++) {
            __syncthreads();
            for (int i = tid; i < 1024; i += 256) {
                int o = i & 63, k0 = (i >> 6) << 2;
                float4 v = *(const float4*)&uw1[o * 128 + half * 64 + k0];
                sW[k0 + 0][o] = v.x; sW[k0 + 1][o] = v.y;
                sW[k0 + 2][o] = v.z; sW[k0 + 3][o] = v.w;
            }
            {
                int nn = tid >> 2, k0 = (tid & 3) << 4;
                int n = n0 + nn;
#pragma unroll
                for (int m = 0; m < 4; m++) {
                    float4 v = (n < NN) ? *(const float4*)&g_u[(size_t)n * 128 + half * 64 + k0 + 4 * m]
                                        : make_float4(0.f, 0.f, 0.f, 0.f);
                    sA[k0 + 4 * m + 0][nn] = v.x;
                    sA[k0 + 4 * m + 1][nn] = v.y;
                    sA[k0 + 4 * m + 2][nn] = v.z;
                    sA[k0 + 4 * m + 3][nn] = v.w;
                }
            }
            __syncthreads();
#pragma unroll 4
            for (int k = 0; k < 64; k++) {
                float4 a = *(const float4*)&sA[k][tx << 2];
                float4 b = *(const float4*)&sW[k][ty << 2];
                float av[4] = {a.x, a.y, a.z, a.w};
                float bv[4] = {b.x, b.y, b.z, b.w};
#pragma unroll
                for (int i = 0; i < 4; i++)
#pragma unroll
                    for (int j = 0; j < 4; j++) acc[i][j] = fmaf(av[i], bv[j], acc[i][j]);
            }
        }
#pragma unroll
        for (int i = 0; i < 4; i++) {
            int n = n0 + (tx << 2) + i;
            if (n < NN) {
                float y0 = acc[i][0] + bb[0], y1 = acc[i][1] + bb[1];
                float y2 = acc[i][2] + bb[2], y3 = acc[i][3] + bb[3];
                *(float4*)&g_un[n * 64 + (ty << 2)] = make_float4(y0, y1, y2, y3);
                st[0] += y0; sq[0] += y0 * y0; st[1] += y1; sq[1] += y1 * y1;
                st[2] += y2; sq[2] += y2 * y2; st[3] += y3; sq[3] += y3 * y3;
            }
        }
    }
    __syncthreads();
#pragma unroll
    for (int j = 0; j < 4; j++) {
        atomicAdd(&sS[(ty << 2) + j], st[j]);
        atomicAdd(&sQ[(ty << 2) + j], sq[j]);
    }
    __syncthreads();
    if (tid < 64) {
        atomicAdd(&g_sum[192 + tid], (double)sS[tid]);
        atomicAdd(&g_sumsq[192 + tid], (double)sQ[tid]);
    }
}

// ---------------- node 2: tiled 64n x 64o, K=64; residual + pos update ----------------
__global__ __launch_bounds__(256) void k_node2(const float* __restrict__ uw2, const float* __restrict__ ub2)
{
    __shared__ __align__(16) float sW[64][64];
    __shared__ __align__(16) float sA[64][64];
    int tid = threadIdx.x, tx = tid & 15, ty = tid >> 4;
    for (int i = tid; i < 1024; i += 256) {
        int o = i & 63, k0 = (i >> 6) << 2;
        float4 v = *(const float4*)&uw2[o * 64 + k0];
        sW[k0 + 0][o] = v.x; sW[k0 + 1][o] = v.y;
        sW[k0 + 2][o] = v.z; sW[k0 + 3][o] = v.w;
    }
    int k0s = (tid & 3) << 4;
    float4 cA[4], cB[4];
#pragma unroll
    for (int m = 0; m < 4; m++) {
        cA[m] = *(const float4*)&g_bnA[192 + k0s + 4 * m];
        cB[m] = *(const float4*)&g_bnB[192 + k0s + 4 * m];
    }
    float bb[4];
#pragma unroll
    for (int j = 0; j < 4; j++) bb[j] = ub2[(ty << 2) + j];
    int ntiles = (NN + 63) >> 6;
    for (int t = blockIdx.x; t < ntiles; t += gridDim.x) {
        int n0 = t << 6;
        __syncthreads();
        {
            int nn = tid >> 2;
            int n = n0 + nn;
#pragma unroll
            for (int m = 0; m < 4; m++) {
                float4 v = (n < NN) ? *(const float4*)&g_un[(size_t)n * 64 + k0s + 4 * m]
                                    : make_float4(0.f, 0.f, 0.f, 0.f);
                sA[k0s + 4 * m + 0][nn] = silu_f(fmaf(v.x, cA[m].x, cB[m].x));
                sA[k0s + 4 * m + 1][nn] = silu_f(fmaf(v.y, cA[m].y, cB[m].y));
                sA[k0s + 4 * m + 2][nn] = silu_f(fmaf(v.z, cA[m].z, cB[m].z));
                sA[k0s + 4 * m + 3][nn] = silu_f(fmaf(v.w, cA[m].w, cB[m].w));
            }
        }
        __syncthreads();
        float acc[4][4];
#pragma unroll
        for (int i = 0; i < 4; i++)
#pragma unroll
            for (int j = 0; j < 4; j++) acc[i][j] = 0.f;
#pragma unroll 4
        for (int k = 0; k < 64; k++) {
            float4 a = *(const float4*)&sA[k][tx << 2];
            float4 b = *(const float4*)&sW[k][ty << 2];
            float av[4] = {a.x, a.y, a.z, a.w};
            float bv[4] = {b.x, b.y, b.z, b.w};
#pragma unroll
            for (int i = 0; i < 4; i++)
#pragma unroll
                for (int j = 0; j < 4; j++) acc[i][j] = fmaf(av[i], bv[j], acc[i][j]);
        }
#pragma unroll
        for (int i = 0; i < 4; i++) {
            int n = n0 + (tx << 2) + i;
            if (n < NN) {
                float4 hold = *(const float4*)&g_h[n * 64 + (ty << 2)];
                float h0 = hold.x + acc[i][0] + bb[0];
                float h1 = hold.y + acc[i][1] + bb[1];
                float h2 = hold.z + acc[i][2] + bb[2];
                float h3 = hold.w + acc[i][3] + bb[3];
                float4 hv = make_float4(h0, h1, h2, h3);
                *(float4*)&g_h[n * 64 + (ty << 2)] = hv;
                *(float4*)&g_u[(size_t)n * 128 + (ty << 2)] = hv;
            }
        }
        if (tid < 64) {
            int n = n0 + tid;
            if (n < NN) {
                g_pos[n * 3 + 0] += g_aggr_p[n * 3 + 0];
                g_pos[n * 3 + 1] += g_aggr_p[n * 3 + 1];
                g_pos[n * 3 + 2] += g_aggr_p[n * 3 + 2];
            }
        }
    }
}

// ---------------- pooling ----------------
__global__ void k_pool(const int* __restrict__ batch)
{
    int idx = blockIdx.x * blockDim.x + threadIdx.x;
    if (idx >= NN * 16) return;
    int n = idx >> 4, c4 = (idx & 15) * 4;
    int b = batch[n];
    float4 h = *(const float4*)&g_h[n * 64 + c4];
    red_add_v4(&g_pool[b * 64 + c4], h.x, h.y, h.z, h.w);
    if (c4 == 0) atomicAdd(&g_cnt[b], 1.0f);
}

__global__ void k_pred(const float* __restrict__ w, const float* __restrict__ b,
                       float* __restrict__ out)
{
    int g = blockIdx.x, lane = threadIdx.x;
    float p = g_pool[g * 64 + lane] * w[lane] + g_pool[g * 64 + 32 + lane] * w[32 + lane];
#pragma unroll
    for (int o = 16; o > 0; o >>= 1) p += __shfl_xor_sync(0xffffffffu, p, o);
    if (lane == 0) out[g] = p / fmaxf(g_cnt[g], 1.0f) + b[0];
}

// ---------------- launch ----------------
extern "C" void kernel_launch(void* const* d_in, const int* in_sizes, int n_in,
                              void* d_out, int out_size)
{
    const float* node_s    = (const float*)d_in[0];
    const float* node_type = (const float*)d_in[1];
    const float* pos       = (const float*)d_in[2];
    const int*   ei        = (const int*)d_in[3];
    const float* edge_s    = (const float*)d_in[4];
    const int*   batch     = (const int*)d_in[5];
    const float* lin_in_w  = (const float*)d_in[6];
    const float* lin_in_b  = (const float*)d_in[7];
    const float* msg_w1    = (const float*)d_in[8];
    const float* msg_b1    = (const float*)d_in[9];
    const float* msg_g1    = (const float*)d_in[10];
    const float* msg_be1   = (const float*)d_in[11];
    const float* msg_w2    = (const float*)d_in[12];
    const float* msg_b2    = (const float*)d_in[13];
    const float* msg_g2    = (const float*)d_in[14];
    const float* msg_be2   = (const float*)d_in[15];
    const float* updf_w1   = (const float*)d_in[16];
    const float* updf_b1   = (const float*)d_in[17];
    const float* updf_g1   = (const float*)d_in[18];
    const float* updf_be1  = (const float*)d_in[19];
    const float* updf_w2   = (const float*)d_in[20];
    const float* updf_b2   = (const float*)d_in[21];
    const float* updc_w1   = (const float*)d_in[22];
    const float* updc_b1   = (const float*)d_in[23];
    const float* updc_g1   = (const float*)d_in[24];
    const float* updc_be1  = (const float*)d_in[25];
    const float* updc_w2   = (const float*)d_in[26];
    const float* updc_b2   = (const float*)d_in[27];
    const float* lin_pred_w = (const float*)d_in[28];
    const float* lin_pred_b = (const float*)d_in[29];

    k_init<<<(NN * 64 + 255) / 256, 256>>>(node_s, node_type, pos, lin_in_w, lin_in_b);
    k_hist<<<(NE + 255) / 256, 256>>>(ei);
    k_scan<<<1, 1024>>>();
    k_fill<<<(NE + 255) / 256, 256>>>(ei);
    k_wpack_all<<<(NL * 64 * 256 + 255) / 256, 256>>>(msg_w1, updc_w1);

    for (int l = 0; l < NL; l++) {
        const float* mw1 = msg_w1 + (size_t)l * 64 * 161;
        const float* mb1 = msg_b1 + l * 64;
        const float* mw2 = msg_w2 + (size_t)l * 64 * 64;
        const float* mb2 = msg_b2 + l * 64;
        const float* cw1 = updc_w1 + (size_t)l * 64 * 161;
        const float* cb1 = updc_b1 + l * 64;
        const float* cw2 = updc_w2 + (size_t)l * 64;
        const float* cb2 = updc_b2 + l;
        const float* uw1 = updf_w1 + (size_t)l * 64 * 128;
        const float* ub1 = updf_b1 + l * 64;
        const float* uw2 = updf_w2 + (size_t)l * 64 * 64;
        const float* ub2 = updf_b2 + l * 64;

        k_hpre<<<592, 256>>>(l);
        k_edgeAmma<<<592, 256>>>(edge_s, mw1, mb1, cw1, cb1);
        k_bnfin<<<1, 128>>>(0, 128, 1.0 / NE,
                            msg_g1 + l * 64, msg_be1 + l * 64,
                            updc_g1 + l * 64, updc_be1 + l * 64);
        k_edgeBmma<<<592, 256>>>(mw2, mb2, cw2, cb2);
        k_bnfin<<<1, 64>>>(128, 64, 1.0 / NE,
                           msg_g2 + l * 64, msg_be2 + l * 64,
                           msg_g2 + l * 64, msg_be2 + l * 64);
        k_aggr<<<(NN * 32 + 255) / 256, 256>>>();
        k_node1<<<592, 256>>>(uw1, ub1);
        k_bnfin<<<1, 64>>>(192, 64, 1.0 / NN,
                           updf_g1 + l * 64, updf_be1 + l * 64,
                           updf_g1 + l * 64, updf_be1 + l * 64);
        k_node2<<<592, 256>>>(uw2, ub2);
    }

    k_pool<<<(NN * 16 + 255) / 256, 256>>>(batch);
    k_pred<<<NG, 32>>>(lin_pred_w, lin_pred_b, (float*)d_out);
}

// round 11
// speedup vs baseline: 2.3301x; 1.1124x over previous
#include <cuda_runtime.h>
#include <cuda_fp16.h>
#include <math.h>
#include <stdint.h>

#define NN 50000
#define NE 800000
#define NL 4
#define NG 64
#define EPS 1e-5f

// ---------------- static device scratch ----------------
__device__ __align__(16) float g_h[NN * 64];
__device__ __align__(16) float g_u[NN * 128];      // [h | aggr_h]
__device__ __align__(16) float g_un[NN * 64];
__device__ __align__(16) float g_pos[NN * 3];
__device__ __align__(16) float g_aggr_p[NN * 3];
__device__ __align__(16) __half g_HpreH[(size_t)NN * 256];   // fp16, 25.6MB (L2-resident)
__device__ __align__(16) float g_wpack4[NL][64 * 256];       // k-major [k][op]
__device__ __align__(16) __half g_t1h[(size_t)NE * 64];      // CSR-ordered, fp16
__device__ __align__(16) __half g_t2h[(size_t)NE * 64];      // CSR-ordered, fp16
__device__ __align__(16) __half g_mlinh[(size_t)NE * 64];    // CSR-ordered, fp16
__device__ __align__(16) float g_sc[NE];                     // CSR-ordered
__device__ int g_deg[NN];
__device__ int g_rowstart[NN + 1];
__device__ int g_cursor[NN];
__device__ int g_csrsrc[NE];
__device__ int g_csrdst[NE];
__device__ int g_csre[NE];
__device__ double g_sum[256];
__device__ double g_sumsq[256];
__device__ __align__(16) float g_bnA[256];
__device__ __align__(16) float g_bnB[256];
__device__ __align__(16) float g_pool[NG * 64];
__device__ float g_cnt[NG];

__device__ __forceinline__ float silu_f(float y) {
    return y * (1.0f / (1.0f + __expf(-y)));
}

__device__ __forceinline__ void red_add_v4(float* p, float a, float b, float c, float d) {
    asm volatile("red.global.add.v4.f32 [%0], {%1,%2,%3,%4};"
                 :: "l"(p), "f"(a), "f"(b), "f"(c), "f"(d) : "memory");
}

// fp16 m16n8k16 MMA, fp32 accumulate
__device__ __forceinline__ void mma_f16(float* c, uint32_t a0, uint32_t a1, uint32_t a2, uint32_t a3,
                                        uint32_t b0, uint32_t b1) {
    asm volatile("mma.sync.aligned.m16n8k16.row.col.f32.f16.f16.f32 "
                 "{%0,%1,%2,%3}, {%4,%5,%6,%7}, {%8,%9}, {%0,%1,%2,%3};"
                 : "+f"(c[0]), "+f"(c[1]), "+f"(c[2]), "+f"(c[3])
                 : "r"(a0), "r"(a1), "r"(a2), "r"(a3), "r"(b0), "r"(b1));
}

// split (x,y) into packed fp16 hi + residual-lo pairs
__device__ __forceinline__ void packsplit(float x, float y, uint32_t& h, uint32_t& l) {
    __half hx = __float2half_rn(x), hy = __float2half_rn(y);
    __half lx = __float2half_rn(x - __half2float(hx));
    __half ly = __float2half_rn(y - __half2float(hy));
    __half2 hh = __halves2half2(hx, hy), ll = __halves2half2(lx, ly);
    h = *(uint32_t*)&hh; l = *(uint32_t*)&ll;
}

// ---------------- init ----------------
__global__ void k_init(const float* __restrict__ ns, const float* __restrict__ nt,
                       const float* __restrict__ pos, const float* __restrict__ w,
                       const float* __restrict__ b)
{
    int idx = blockIdx.x * blockDim.x + threadIdx.x;
    if (idx < NG * 64) g_pool[idx] = 0.f;
    if (idx < NG) g_cnt[idx] = 0.f;
    if (idx < 256) { g_sum[idx] = 0.0; g_sumsq[idx] = 0.0; }
    if (idx < NN) g_deg[idx] = 0;
    if (idx >= NN * 64) return;
    int n = idx >> 6, o = idx & 63;
    const float* wr = w + o * 8;
    const float* s = ns + n * 6;
    float acc = b[o];
#pragma unroll
    for (int i = 0; i < 6; i++) acc = fmaf(s[i], wr[i], acc);
    acc = fmaf(nt[n * 2 + 0], wr[6], acc);
    acc = fmaf(nt[n * 2 + 1], wr[7], acc);
    g_h[idx] = acc;
    g_u[(size_t)n * 128 + o] = acc;
    if (o < 3) g_pos[n * 3 + o] = pos[n * 3 + o];
}

// ---------------- CSR build ----------------
__global__ void k_hist(const int* __restrict__ ei)
{
    int e = blockIdx.x * blockDim.x + threadIdx.x;
    if (e < NE) atomicAdd(&g_deg[ei[NE + e]], 1);
}

__global__ __launch_bounds__(1024) void k_scan()
{
    __shared__ int ssum[1024];
    int t = threadIdx.x;
    const int C = 49;
    int begin = t * C;
    int end = begin + C; if (end > NN) end = NN;
    if (begin > NN) begin = NN;
    int s = 0;
    for (int i = begin; i < end; i++) s += g_deg[i];
    ssum[t] = s;
    __syncthreads();
    for (int off = 1; off < 1024; off <<= 1) {
        int v = (t >= off) ? ssum[t - off] : 0;
        __syncthreads();
        ssum[t] += v;
        __syncthreads();
    }
    int run = ssum[t] - s;
    for (int i = begin; i < end; i++) {
        g_rowstart[i] = run;
        g_cursor[i] = run;
        run += g_deg[i];
    }
    if (t == 1023) g_rowstart[NN] = ssum[1023];
}

__global__ void k_fill(const int* __restrict__ ei)
{
    int e = blockIdx.x * blockDim.x + threadIdx.x;
    if (e >= NE) return;
    int s = ei[e], d = ei[NE + e];
    int p = atomicAdd(&g_cursor[d], 1);
    g_csrsrc[p] = s;
    g_csrdst[p] = d;
    g_csre[p] = e;
}

// ---------------- pack h-columns of msg_w1/updc_w1 for ALL layers ----------------
__global__ void k_wpack_all(const float* __restrict__ mw1a, const float* __restrict__ cw1a)
{
    int idx = blockIdx.x * blockDim.x + threadIdx.x;
    if (idx >= NL * 64 * 256) return;
    int l = idx >> 14;
    int r = idx & 16383;
    int k = r >> 8, op = r & 255, o = op & 63;
    const float* mw1 = mw1a + (size_t)l * 64 * 161;
    const float* cw1 = cw1a + (size_t)l * 64 * 161;
    float v;
    if (op < 64)       v = mw1[o * 161 + k];
    else if (op < 128) v = mw1[o * 161 + 64 + k];
    else if (op < 192) v = cw1[o * 161 + k];
    else               v = cw1[o * 161 + 64 + k];
    g_wpack4[l][k * 256 + op] = v;
}

// ---------------- Hpre: tiled GEMM 64n x 128o (2 phases), K=64; fp16 output ----------------
__global__ __launch_bounds__(256) void k_hpre(int layer)
{
    const float* wpack = g_wpack4[layer];
    __shared__ __align__(16) float sA[64][64];
    __shared__ __align__(16) float sB[64][128];
    int tid = threadIdx.x, tx = tid & 15, ty = tid >> 4;
    int ntiles = (NN + 63) >> 6;
    for (int t = blockIdx.x; t < ntiles; t += gridDim.x) {
        int n0 = t << 6;
        __syncthreads();
        {
            int nn = tid >> 2, k0 = (tid & 3) << 4;
            int n = n0 + nn;
#pragma unroll
            for (int m = 0; m < 4; m++) {
                float4 v = (n < NN) ? *(const float4*)&g_h[n * 64 + k0 + 4 * m]
                                    : make_float4(0.f, 0.f, 0.f, 0.f);
                sA[k0 + 4 * m + 0][nn] = v.x;
                sA[k0 + 4 * m + 1][nn] = v.y;
                sA[k0 + 4 * m + 2][nn] = v.z;
                sA[k0 + 4 * m + 3][nn] = v.w;
            }
        }
        for (int ph = 0; ph < 2; ph++) {
            __syncthreads();
#pragma unroll
            for (int r = 0; r < 8; r++) {
                int i = tid + r * 256;
                int k = i >> 5, o4 = (i & 31) << 2;
                *(float4*)&sB[k][o4] = *(const float4*)&wpack[k * 256 + ph * 128 + o4];
            }
            __syncthreads();
            float acc[4][8];
#pragma unroll
            for (int i = 0; i < 4; i++)
#pragma unroll
                for (int j = 0; j < 8; j++) acc[i][j] = 0.f;
#pragma unroll 4
            for (int k = 0; k < 64; k++) {
                float4 a = *(const float4*)&sA[k][tx << 2];
                float4 b0 = *(const float4*)&sB[k][ty << 3];
                float4 b1 = *(const float4*)&sB[k][(ty << 3) + 4];
                float av[4] = {a.x, a.y, a.z, a.w};
                float bv[8] = {b0.x, b0.y, b0.z, b0.w, b1.x, b1.y, b1.z, b1.w};
#pragma unroll
                for (int i = 0; i < 4; i++)
#pragma unroll
                    for (int j = 0; j < 8; j++) acc[i][j] = fmaf(av[i], bv[j], acc[i][j]);
            }
#pragma unroll
            for (int i = 0; i < 4; i++) {
                int n = n0 + (tx << 2) + i;
                if (n < NN) {
                    __half hv[8];
#pragma unroll
                    for (int j = 0; j < 8; j++) hv[j] = __float2half_rn(acc[i][j]);
                    *(uint4*)&g_HpreH[(size_t)n * 256 + ph * 128 + (ty << 3)] = *(uint4*)hv;
                }
            }
        }
    }
}

// ---------------- edge A (fp16 MMA, CSR order): t1/t2 = Hpre gather + r*wr + es@Wes^T + b ----------------
// 256 threads, 8 warps; tile = 64 CSR positions x 128 ch. Warp w covers ch [16w, 16w+16). K=32 (2 k16 steps).
__global__ __launch_bounds__(256) void k_edgeAmma(const float* __restrict__ es,
                                                  const float* __restrict__ mw1, const float* __restrict__ mb1,
                                                  const float* __restrict__ cw1, const float* __restrict__ cb1)
{
    __shared__ __align__(16) char sBuf[64 * 132 * 4];   // union: sEs half[64][40] | sOut float[64][132]
    __half (*sEs)[40] = (__half(*)[40])sBuf;
    float (*sOut)[132] = (float(*)[132])sBuf;
    __shared__ float sR[64];
    __shared__ int sSrc[64], sDst[64];
    __shared__ float sS[128], sQ[128];

    int tid = threadIdx.x;
    int warp = tid >> 5, lane = tid & 31;
    int gid = lane >> 2, tig = lane & 3;

    if (tid < 128) { sS[tid] = 0.f; sQ[tid] = 0.f; }

    // weight A fragments (16 ch x 32 k per warp), fp16 hi/lo split
    uint32_t ah[2][4], al[2][4];
    {
        int r0 = warp * 16 + gid;
        int r1 = r0 + 8;
        const float* w0 = (r0 < 64) ? &mw1[r0 * 161 + 129] : &cw1[(r0 - 64) * 161 + 129];
        const float* w1 = (r1 < 64) ? &mw1[r1 * 161 + 129] : &cw1[(r1 - 64) * 161 + 129];
#pragma unroll
        for (int kb = 0; kb < 2; kb++) {
            int k0 = kb * 16 + 2 * tig;
            packsplit(w0[k0], w0[k0 + 1], ah[kb][0], al[kb][0]);
            packsplit(w1[k0], w1[k0 + 1], ah[kb][1], al[kb][1]);
            packsplit(w0[k0 + 8], w0[k0 + 9], ah[kb][2], al[kb][2]);
            packsplit(w1[k0 + 8], w1[k0 + 9], ah[kb][3], al[kb][3]);
        }
    }
    int ch0 = lane << 2;
    float wr4[4], bb4[4];
#pragma unroll
    for (int j = 0; j < 4; j++) {
        int ch = ch0 + j;
        wr4[j] = (ch < 64) ? mw1[ch * 161 + 128] : cw1[(ch - 64) * 161 + 128];
        bb4[j] = (ch < 64) ? mb1[ch] : cb1[ch - 64];
    }
    int hd_off = (ch0 < 64) ? ch0 : 64 + ch0;
    int hs_off = (ch0 < 64) ? 64 + ch0 : 128 + ch0;
    float st[4] = {0.f, 0.f, 0.f, 0.f}, sq[4] = {0.f, 0.f, 0.f, 0.f};

    for (int t = blockIdx.x; t < NE / 64; t += gridDim.x) {
        int p0 = t << 6;
        __syncthreads();
        if (tid < 64) {
            int p = p0 + tid;
            int s = g_csrsrc[p], d = g_csrdst[p];
            sSrc[tid] = s; sDst[tid] = d;
            float dx = g_pos[d * 3] - g_pos[s * 3];
            float dy = g_pos[d * 3 + 1] - g_pos[s * 3 + 1];
            float dz = g_pos[d * 3 + 2] - g_pos[s * 3 + 2];
            sR[tid] = sqrtf(dx * dx + dy * dy + dz * dz);
        }
        // stage es as fp16 [edge][k]
        {
            int el = tid >> 2, q = tid & 3;
            int eid = g_csre[p0 + el];
            const float4* ep = (const float4*)&es[(size_t)eid * 32 + q * 8];
            float4 v0 = ep[0];
            float4 v1 = ep[1];
            __half hv[8];
            hv[0] = __float2half_rn(v0.x); hv[1] = __float2half_rn(v0.y);
            hv[2] = __float2half_rn(v0.z); hv[3] = __float2half_rn(v0.w);
            hv[4] = __float2half_rn(v1.x); hv[5] = __float2half_rn(v1.y);
            hv[6] = __float2half_rn(v1.z); hv[7] = __float2half_rn(v1.w);
            *(uint4*)&sEs[el][q * 8] = *(uint4*)hv;
        }
        __syncthreads();
        // MMA: per warp C[16 ch][64 edges], 2 kb x 8 nb x 2 (hi/lo)
        float c[8][4];
#pragma unroll
        for (int nb = 0; nb < 8; nb++)
#pragma unroll
            for (int j = 0; j < 4; j++) c[nb][j] = 0.f;
#pragma unroll
        for (int kb = 0; kb < 2; kb++) {
#pragma unroll
            for (int nb = 0; nb < 8; nb++) {
                int col = nb * 8 + gid;
                uint32_t b0 = *(const uint32_t*)&sEs[col][kb * 16 + 2 * tig];
                uint32_t b1 = *(const uint32_t*)&sEs[col][kb * 16 + 2 * tig + 8];
                mma_f16(c[nb], ah[kb][0], ah[kb][1], ah[kb][2], ah[kb][3], b0, b1);
                mma_f16(c[nb], al[kb][0], al[kb][1], al[kb][2], al[kb][3], b0, b1);
            }
        }
        __syncthreads();
        // transpose C into sOut[edge][ch]
        {
            int ch = warp * 16 + gid;
#pragma unroll
            for (int nb = 0; nb < 8; nb++) {
                int e = nb * 8 + 2 * tig;
                sOut[e][ch] = c[nb][0];
                sOut[e + 1][ch] = c[nb][1];
                sOut[e][ch + 8] = c[nb][2];
                sOut[e + 1][ch + 8] = c[nb][3];
            }
        }
        __syncthreads();
        // epilogue: fp16 Hpre gather, fp16 store, stats on rounded values
#pragma unroll 2
        for (int ee = 0; ee < 8; ee++) {
            int e = warp * 8 + ee;
            int d = sDst[e], s = sSrc[e];
            float r = sR[e];
            uint2 du = *(const uint2*)&g_HpreH[(size_t)d * 256 + hd_off];
            uint2 su = *(const uint2*)&g_HpreH[(size_t)s * 256 + hs_off];
            float2 d01 = __half22float2(*(__half2*)&du.x);
            float2 d23 = __half22float2(*(__half2*)&du.y);
            float2 s01 = __half22float2(*(__half2*)&su.x);
            float2 s23 = __half22float2(*(__half2*)&su.y);
            float4 o = *(const float4*)&sOut[e][ch0];
            __half hv[4];
            hv[0] = __float2half_rn(o.x + d01.x + s01.x + fmaf(r, wr4[0], bb4[0]));
            hv[1] = __float2half_rn(o.y + d01.y + s01.y + fmaf(r, wr4[1], bb4[1]));
            hv[2] = __float2half_rn(o.z + d23.x + s23.x + fmaf(r, wr4[2], bb4[2]));
            hv[3] = __float2half_rn(o.w + d23.y + s23.y + fmaf(r, wr4[3], bb4[3]));
            int p = p0 + e;
            __half* out = (ch0 < 64) ? &g_t1h[(size_t)p * 64 + ch0]
                                     : &g_t2h[(size_t)p * 64 + ch0 - 64];
            *(uint2*)out = *(uint2*)hv;
#pragma unroll
            for (int j = 0; j < 4; j++) {
                float yr = __half2float(hv[j]);
                st[j] += yr; sq[j] += yr * yr;
            }
        }
    }
    __syncthreads();
#pragma unroll
    for (int j = 0; j < 4; j++) { atomicAdd(&sS[ch0 + j], st[j]); atomicAdd(&sQ[ch0 + j], sq[j]); }
    __syncthreads();
    if (tid < 128) {
        atomicAdd(&g_sum[tid], (double)sS[tid]);
        atomicAdd(&g_sumsq[tid], (double)sQ[tid]);
    }
}

// ---------------- BN finalize (self-resetting stats) ----------------
__global__ void k_bnfin(int off, int n, double inv,
                        const float* __restrict__ g0, const float* __restrict__ b0,
                        const float* __restrict__ g1, const float* __restrict__ b1)
{
    int c = threadIdx.x;
    if (c >= n) return;
    double m = g_sum[off + c] * inv;
    double v = g_sumsq[off + c] * inv - m * m;
    g_sum[off + c] = 0.0;
    g_sumsq[off + c] = 0.0;
    float gg = (c < 64) ? g0[c] : g1[c - 64];
    float bb = (c < 64) ? b0[c] : b1[c - 64];
    float A = gg * rsqrtf((float)v + EPS);
    g_bnA[off + c] = A;
    g_bnB[off + c] = bb - (float)m * A;
}

// ---------------- edge B (fp16 MMA, 256 thr): mlin = silu(bn(t1)) @ msg_w2^T + b ----------------
// 8 warps: m0=(warp&3)*16 out rows; n0=(warp>>2)*32 edges. K=64 (4 k16 steps).
__global__ __launch_bounds__(256) void k_edgeBmma(const float* __restrict__ mw2, const float* __restrict__ mb2,
                                                  const float* __restrict__ cw2, const float* __restrict__ cb2)
{
    __shared__ __align__(16) char sBuf[64 * 68 * 4];    // union: sX half[64][72]=9216B | sOut float[64][68]=17408B
    __half (*sX)[72] = (__half(*)[72])sBuf;
    float* sOut = (float*)sBuf;
    __shared__ float sS[64], sQ[64];
    __shared__ float sCA[64], sCB[64], sDA[64], sDB[64], sWc2[64];

    int tid = threadIdx.x;
    int warp = tid >> 5, lane = tid & 31;
    int gid = lane >> 2, tig = lane & 3;
    int m0 = (warp & 3) << 4;
    int n0 = (warp >> 2) << 5;

    if (tid < 64) {
        sS[tid] = 0.f; sQ[tid] = 0.f;
        sCA[tid] = g_bnA[tid];        sCB[tid] = g_bnB[tid];
        sDA[tid] = g_bnA[64 + tid];   sDB[tid] = g_bnB[64 + tid];
        sWc2[tid] = cw2[tid];
    }

    // weight A fragments (16 out x 64 k), fp16 hi/lo split
    uint32_t ah[4][4], al[4][4];
    {
        const float* w0 = mw2 + (size_t)(m0 + gid) * 64;
        const float* w1 = mw2 + (size_t)(m0 + gid + 8) * 64;
#pragma unroll
        for (int kb = 0; kb < 4; kb++) {
            int k0 = kb * 16 + 2 * tig;
            packsplit(w0[k0], w0[k0 + 1], ah[kb][0], al[kb][0]);
            packsplit(w1[k0], w1[k0 + 1], ah[kb][1], al[kb][1]);
            packsplit(w0[k0 + 8], w0[k0 + 9], ah[kb][2], al[kb][2]);
            packsplit(w1[k0 + 8], w1[k0 + 9], ah[kb][3], al[kb][3]);
        }
    }
    float bias0 = mb2[m0 + gid], bias1 = mb2[m0 + gid + 8];
    float cbias = cb2[0];
    float s0 = 0.f, q0 = 0.f, s1 = 0.f, q1 = 0.f;

    int el = tid >> 2, q = tid & 3;   // staging: edge el, channels [q*16, q*16+16)

    for (int t = blockIdx.x; t < NE / 64; t += gridDim.x) {
        int e0 = t << 6;
        __syncthreads();
        // stage X = silu(bn1(t1)) as fp16 (fp16 source)
        {
            const uint4* tb = (const uint4*)&g_t1h[(size_t)(e0 + el) * 64 + q * 16];
            __half2 hbuf[8];
            *(uint4*)&hbuf[0] = tb[0];
            *(uint4*)&hbuf[4] = tb[1];
            __half xv[16];
#pragma unroll
            for (int m = 0; m < 8; m++) {
                float2 f = __half22float2(hbuf[m]);
                int c = q * 16 + 2 * m;
                xv[2 * m]     = __float2half_rn(silu_f(fmaf(f.x, sCA[c], sCB[c])));
                xv[2 * m + 1] = __float2half_rn(silu_f(fmaf(f.y, sCA[c + 1], sCB[c + 1])));
            }
            *(uint4*)&sX[el][q * 16] = *(uint4*)&xv[0];
            *(uint4*)&sX[el][q * 16 + 8] = *(uint4*)&xv[8];
        }
        // coord head: 4 threads per edge, 16 ch each -> g_sc
        {
            const uint4* tb = (const uint4*)&g_t2h[(size_t)(e0 + el) * 64 + q * 16];
            __half2 hbuf[8];
            *(uint4*)&hbuf[0] = tb[0];
            *(uint4*)&hbuf[4] = tb[1];
            float part = 0.f;
#pragma unroll
            for (int m = 0; m < 8; m++) {
                float2 f = __half22float2(hbuf[m]);
                int c = q * 16 + 2 * m;
                part += silu_f(fmaf(f.x, sDA[c], sDB[c])) * sWc2[c];
                part += silu_f(fmaf(f.y, sDA[c + 1], sDB[c + 1])) * sWc2[c + 1];
            }
            part += __shfl_xor_sync(0xffffffffu, part, 1);
            part += __shfl_xor_sync(0xffffffffu, part, 2);
            if (q == 0) g_sc[e0 + el] = part + cbias;
        }
        __syncthreads();
        // MMA: per warp C[16 out][32 edges], 4 kb x 4 nb x 2 (hi/lo)
        float c[4][4];
#pragma unroll
        for (int nb = 0; nb < 4; nb++)
#pragma unroll
            for (int j = 0; j < 4; j++) c[nb][j] = 0.f;
#pragma unroll
        for (int kb = 0; kb < 4; kb++) {
#pragma unroll
            for (int nb = 0; nb < 4; nb++) {
                int col = n0 + nb * 8 + gid;
                uint32_t b0 = *(const uint32_t*)&sX[col][kb * 16 + 2 * tig];
                uint32_t b1 = *(const uint32_t*)&sX[col][kb * 16 + 2 * tig + 8];
                mma_f16(c[nb], ah[kb][0], ah[kb][1], ah[kb][2], ah[kb][3], b0, b1);
                mma_f16(c[nb], al[kb][0], al[kb][1], al[kb][2], al[kb][3], b0, b1);
            }
        }
        __syncthreads();
        // epilogue: bias + round-to-fp16 + stats, transpose through smem (union buffer)
#pragma unroll
        for (int nb = 0; nb < 4; nb++) {
            int e = n0 + nb * 8 + 2 * tig;
            float yr00 = __half2float(__float2half_rn(c[nb][0] + bias0));
            float yr01 = __half2float(__float2half_rn(c[nb][1] + bias0));
            float yr10 = __half2float(__float2half_rn(c[nb][2] + bias1));
            float yr11 = __half2float(__float2half_rn(c[nb][3] + bias1));
            sOut[e * 68 + m0 + gid] = yr00;
            sOut[(e + 1) * 68 + m0 + gid] = yr01;
            sOut[e * 68 + m0 + gid + 8] = yr10;
            sOut[(e + 1) * 68 + m0 + gid + 8] = yr11;
            s0 += yr00 + yr01; q0 += yr00 * yr00 + yr01 * yr01;
            s1 += yr10 + yr11; q1 += yr10 * yr10 + yr11 * yr11;
        }
        __syncthreads();
        // coalesced fp16 store
        {
            const float* src = &sOut[el * 68 + q * 16];
            __half hv[16];
#pragma unroll
            for (int m = 0; m < 16; m++) hv[m] = __float2half_rn(src[m]);
            uint4* dst = (uint4*)&g_mlinh[(size_t)(e0 + el) * 64 + q * 16];
            dst[0] = *(uint4*)&hv[0];
            dst[1] = *(uint4*)&hv[8];
        }
    }
    __syncthreads();
    atomicAdd(&sS[m0 + gid], s0); atomicAdd(&sQ[m0 + gid], q0);
    atomicAdd(&sS[m0 + gid + 8], s1); atomicAdd(&sQ[m0 + gid + 8], q1);
    __syncthreads();
    if (tid < 64) {
        atomicAdd(&g_sum[128 + tid], (double)sS[tid]);
        atomicAdd(&g_sumsq[128 + tid], (double)sQ[tid]);
    }
}

// ---------------- aggregation: warp per node, contiguous CSR rows (fp16 mlin) ----------------
__global__ __launch_bounds__(256) void k_aggr()
{
    int gwarp = (blockIdx.x * blockDim.x + threadIdx.x) >> 5;
    int lane = threadIdx.x & 31;
    if (gwarp >= NN) return;
    int n = gwarp;
    int s0 = g_rowstart[n], s1 = g_rowstart[n + 1];
    float A0 = g_bnA[128 + lane], B0 = g_bnB[128 + lane];
    float A1 = g_bnA[160 + lane], B1 = g_bnB[160 + lane];
    float acc0 = 0.f, acc1 = 0.f;
    for (int i = s0; i < s1; i++) {
        float m0 = __half2float(g_mlinh[(size_t)i * 64 + lane]);
        float m1 = __half2float(g_mlinh[(size_t)i * 64 + 32 + lane]);
        acc0 += silu_f(fmaf(m0, A0, B0));
        acc1 += silu_f(fmaf(m1, A1, B1));
    }
    g_u[(size_t)n * 128 + 64 + lane] = acc0;
    g_u[(size_t)n * 128 + 96 + lane] = acc1;
    float px = g_pos[n * 3], py = g_pos[n * 3 + 1], pz = g_pos[n * 3 + 2];
    float cx = 0.f, cy = 0.f, cz = 0.f;
    for (int i = s0 + lane; i < s1; i += 32) {
        int src = g_csrsrc[i];
        float sc = g_sc[i];
        cx += sc * (px - g_pos[src * 3]);
        cy += sc * (py - g_pos[src * 3 + 1]);
        cz += sc * (pz - g_pos[src * 3 + 2]);
    }
#pragma unroll
    for (int o = 16; o > 0; o >>= 1) {
        cx += __shfl_xor_sync(0xffffffffu, cx, o);
        cy += __shfl_xor_sync(0xffffffffu, cy, o);
        cz += __shfl_xor_sync(0xffffffffu, cz, o);
    }
    if (lane == 0) {
        g_aggr_p[n * 3 + 0] = cx;
        g_aggr_p[n * 3 + 1] = cy;
        g_aggr_p[n * 3 + 2] = cz;
    }
}

// ---------------- node 1: tiled 64n x 64o, K=128 ----------------
__global__ __launch_bounds__(256) void k_node1(const float* __restrict__ uw1, const float* __restrict__ ub1)
{
    __shared__ __align__(16) float sW[64][64];
    __shared__ __align__(16) float sA[64][64];
    __shared__ float sS[64], sQ[64];
    int tid = threadIdx.x, tx = tid & 15, ty = tid >> 4;
    if (tid < 64) { sS[tid] = 0.f; sQ[tid] = 0.f; }
    float bb[4];
#pragma unroll
    for (int j = 0; j < 4; j++) bb[j] = ub1[(ty << 2) + j];
    float st[4] = {0.f, 0.f, 0.f, 0.f}, sq[4] = {0.f, 0.f, 0.f, 0.f};
    int ntiles = (NN + 63) >> 6;
    for (int t = blockIdx.x; t < ntiles; t += gridDim.x) {
        int n0 = t << 6;
        float acc[4][4];
#pragma unroll
        for (int i = 0; i < 4; i++)
#pragma unroll
            for (int j = 0; j < 4; j++) acc[i][j] = 0.f;
        for (int half = 0; half < 2; half++) {
            __syncthreads();
            for (int i = tid; i < 1024; i += 256) {
                int o = i & 63, k0 = (i >> 6) << 2;
                float4 v = *(const float4*)&uw1[o * 128 + half * 64 + k0];
                sW[k0 + 0][o] = v.x; sW[k0 + 1][o] = v.y;
                sW[k0 + 2][o] = v.z; sW[k0 + 3][o] = v.w;
            }
            {
                int nn = tid >> 2, k0 = (tid & 3) << 4;
                int n = n0 + nn;
#pragma unroll
                for (int m = 0; m < 4; m++) {
                    float4 v = (n < NN) ? *(const float4*)&g_u[(size_t)n * 128 + half * 64 + k0 + 4 * m]
                                        : make_float4(0.f, 0.f, 0.f, 0.f);
                    sA[k0 + 4 * m + 0][nn] = v.x;
                    sA[k0 + 4 * m + 1][nn] = v.y;
                    sA[k0 + 4 * m + 2][nn] = v.z;
                    sA[k0 + 4 * m + 3][nn] = v.w;
                }
            }
            __syncthreads();
#pragma unroll 4
            for (int k = 0; k < 64; k++) {
                float4 a = *(const float4*)&sA[k][tx << 2];
                float4 b = *(const float4*)&sW[k][ty << 2];
                float av[4] = {a.x, a.y, a.z, a.w};
                float bv[4] = {b.x, b.y, b.z, b.w};
#pragma unroll
                for (int i = 0; i < 4; i++)
#pragma unroll
                    for (int j = 0; j < 4; j++) acc[i][j] = fmaf(av[i], bv[j], acc[i][j]);
            }
        }
#pragma unroll
        for (int i = 0; i < 4; i++) {
            int n = n0 + (tx << 2) + i;
            if (n < NN) {
                float y0 = acc[i][0] + bb[0], y1 = acc[i][1] + bb[1];
                float y2 = acc[i][2] + bb[2], y3 = acc[i][3] + bb[3];
                *(float4*)&g_un[n * 64 + (ty << 2)] = make_float4(y0, y1, y2, y3);
                st[0] += y0; sq[0] += y0 * y0; st[1] += y1; sq[1] += y1 * y1;
                st[2] += y2; sq[2] += y2 * y2; st[3] += y3; sq[3] += y3 * y3;
            }
        }
    }
    __syncthreads();
#pragma unroll
    for (int j = 0; j < 4; j++) {
        atomicAdd(&sS[(ty << 2) + j], st[j]);
        atomicAdd(&sQ[(ty << 2) + j], sq[j]);
    }
    __syncthreads();
    if (tid < 64) {
        atomicAdd(&g_sum[192 + tid], (double)sS[tid]);
        atomicAdd(&g_sumsq[192 + tid], (double)sQ[tid]);
    }
}

// ---------------- node 2: tiled 64n x 64o, K=64; residual + pos update ----------------
__global__ __launch_bounds__(256) void k_node2(const float* __restrict__ uw2, const float* __restrict__ ub2)
{
    __shared__ __align__(16) float sW[64][64];
    __shared__ __align__(16) float sA[64][64];
    int tid = threadIdx.x, tx = tid & 15, ty = tid >> 4;
    for (int i = tid; i < 1024; i += 256) {
        int o = i & 63, k0 = (i >> 6) << 2;
        float4 v = *(const float4*)&uw2[o * 64 + k0];
        sW[k0 + 0][o] = v.x; sW[k0 + 1][o] = v.y;
        sW[k0 + 2][o] = v.z; sW[k0 + 3][o] = v.w;
    }
    int k0s = (tid & 3) << 4;
    float4 cA[4], cB[4];
#pragma unroll
    for (int m = 0; m < 4; m++) {
        cA[m] = *(const float4*)&g_bnA[192 + k0s + 4 * m];
        cB[m] = *(const float4*)&g_bnB[192 + k0s + 4 * m];
    }
    float bb[4];
#pragma unroll
    for (int j = 0; j < 4; j++) bb[j] = ub2[(ty << 2) + j];
    int ntiles = (NN + 63) >> 6;
    for (int t = blockIdx.x; t < ntiles; t += gridDim.x) {
        int n0 = t << 6;
        __syncthreads();
        {
            int nn = tid >> 2;
            int n = n0 + nn;
#pragma unroll
            for (int m = 0; m < 4; m++) {
                float4 v = (n < NN) ? *(const float4*)&g_un[(size_t)n * 64 + k0s + 4 * m]
                                    : make_float4(0.f, 0.f, 0.f, 0.f);
                sA[k0s + 4 * m + 0][nn] = silu_f(fmaf(v.x, cA[m].x, cB[m].x));
                sA[k0s + 4 * m + 1][nn] = silu_f(fmaf(v.y, cA[m].y, cB[m].y));
                sA[k0s + 4 * m + 2][nn] = silu_f(fmaf(v.z, cA[m].z, cB[m].z));
                sA[k0s + 4 * m + 3][nn] = silu_f(fmaf(v.w, cA[m].w, cB[m].w));
            }
        }
        __syncthreads();
        float acc[4][4];
#pragma unroll
        for (int i = 0; i < 4; i++)
#pragma unroll
            for (int j = 0; j < 4; j++) acc[i][j] = 0.f;
#pragma unroll 4
        for (int k = 0; k < 64; k++) {
            float4 a = *(const float4*)&sA[k][tx << 2];
            float4 b = *(const float4*)&sW[k][ty << 2];
            float av[4] = {a.x, a.y, a.z, a.w};
            float bv[4] = {b.x, b.y, b.z, b.w};
#pragma unroll
            for (int i = 0; i < 4; i++)
#pragma unroll
                for (int j = 0; j < 4; j++) acc[i][j] = fmaf(av[i], bv[j], acc[i][j]);
        }
#pragma unroll
        for (int i = 0; i < 4; i++) {
            int n = n0 + (tx << 2) + i;
            if (n < NN) {
                float4 hold = *(const float4*)&g_h[n * 64 + (ty << 2)];
                float h0 = hold.x + acc[i][0] + bb[0];
                float h1 = hold.y + acc[i][1] + bb[1];
                float h2 = hold.z + acc[i][2] + bb[2];
                float h3 = hold.w + acc[i][3] + bb[3];
                float4 hv = make_float4(h0, h1, h2, h3);
                *(float4*)&g_h[n * 64 + (ty << 2)] = hv;
                *(float4*)&g_u[(size_t)n * 128 + (ty << 2)] = hv;
            }
        }
        if (tid < 64) {
            int n = n0 + tid;
            if (n < NN) {
                g_pos[n * 3 + 0] += g_aggr_p[n * 3 + 0];
                g_pos[n * 3 + 1] += g_aggr_p[n * 3 + 1];
                g_pos[n * 3 + 2] += g_aggr_p[n * 3 + 2];
            }
        }
    }
}

// ---------------- pooling ----------------
__global__ void k_pool(const int* __restrict__ batch)
{
    int idx = blockIdx.x * blockDim.x + threadIdx.x;
    if (idx >= NN * 16) return;
    int n = idx >> 4, c4 = (idx & 15) * 4;
    int b = batch[n];
    float4 h = *(const float4*)&g_h[n * 64 + c4];
    red_add_v4(&g_pool[b * 64 + c4], h.x, h.y, h.z, h.w);
    if (c4 == 0) atomicAdd(&g_cnt[b], 1.0f);
}

__global__ void k_pred(const float* __restrict__ w, const float* __restrict__ b,
                       float* __restrict__ out)
{
    int g = blockIdx.x, lane = threadIdx.x;
    float p = g_pool[g * 64 + lane] * w[lane] + g_pool[g * 64 + 32 + lane] * w[32 + lane];
#pragma unroll
    for (int o = 16; o > 0; o >>= 1) p += __shfl_xor_sync(0xffffffffu, p, o);
    if (lane == 0) out[g] = p / fmaxf(g_cnt[g], 1.0f) + b[0];
}

// ---------------- launch ----------------
extern "C" void kernel_launch(void* const* d_in, const int* in_sizes, int n_in,
                              void* d_out, int out_size)
{
    const float* node_s    = (const float*)d_in[0];
    const float* node_type = (const float*)d_in[1];
    const float* pos       = (const float*)d_in[2];
    const int*   ei        = (const int*)d_in[3];
    const float* edge_s    = (const float*)d_in[4];
    const int*   batch     = (const int*)d_in[5];
    const float* lin_in_w  = (const float*)d_in[6];
    const float* lin_in_b  = (const float*)d_in[7];
    const float* msg_w1    = (const float*)d_in[8];
    const float* msg_b1    = (const float*)d_in[9];
    const float* msg_g1    = (const float*)d_in[10];
    const float* msg_be1   = (const float*)d_in[11];
    const float* msg_w2    = (const float*)d_in[12];
    const float* msg_b2    = (const float*)d_in[13];
    const float* msg_g2    = (const float*)d_in[14];
    const float* msg_be2   = (const float*)d_in[15];
    const float* updf_w1   = (const float*)d_in[16];
    const float* updf_b1   = (const float*)d_in[17];
    const float* updf_g1   = (const float*)d_in[18];
    const float* updf_be1  = (const float*)d_in[19];
    const float* updf_w2   = (const float*)d_in[20];
    const float* updf_b2   = (const float*)d_in[21];
    const float* updc_w1   = (const float*)d_in[22];
    const float* updc_b1   = (const float*)d_in[23];
    const float* updc_g1   = (const float*)d_in[24];
    const float* updc_be1  = (const float*)d_in[25];
    const float* updc_w2   = (const float*)d_in[26];
    const float* updc_b2   = (const float*)d_in[27];
    const float* lin_pred_w = (const float*)d_in[28];
    const float* lin_pred_b = (const float*)d_in[29];

    k_init<<<(NN * 64 + 255) / 256, 256>>>(node_s, node_type, pos, lin_in_w, lin_in_b);
    k_hist<<<(NE + 255) / 256, 256>>>(ei);
    k_scan<<<1, 1024>>>();
    k_fill<<<(NE + 255) / 256, 256>>>(ei);
    k_wpack_all<<<(NL * 64 * 256 + 255) / 256, 256>>>(msg_w1, updc_w1);

    for (int l = 0; l < NL; l++) {
        const float* mw1 = msg_w1 + (size_t)l * 64 * 161;
        const float* mb1 = msg_b1 + l * 64;
        const float* mw2 = msg_w2 + (size_t)l * 64 * 64;
        const float* mb2 = msg_b2 + l * 64;
        const float* cw1 = updc_w1 + (size_t)l * 64 * 161;
        const float* cb1 = updc_b1 + l * 64;
        const float* cw2 = updc_w2 + (size_t)l * 64;
        const float* cb2 = updc_b2 + l;
        const float* uw1 = updf_w1 + (size_t)l * 64 * 128;
        const float* ub1 = updf_b1 + l * 64;
        const float* uw2 = updf_w2 + (size_t)l * 64 * 64;
        const float* ub2 = updf_b2 + l * 64;

        k_hpre<<<592, 256>>>(l);
        k_edgeAmma<<<592, 256>>>(edge_s, mw1, mb1, cw1, cb1);
        k_bnfin<<<1, 128>>>(0, 128, 1.0 / NE,
                            msg_g1 + l * 64, msg_be1 + l * 64,
                            updc_g1 + l * 64, updc_be1 + l * 64);
        k_edgeBmma<<<592, 256>>>(mw2, mb2, cw2, cb2);
        k_bnfin<<<1, 64>>>(128, 64, 1.0 / NE,
                           msg_g2 + l * 64, msg_be2 + l * 64,
                           msg_g2 + l * 64, msg_be2 + l * 64);
        k_aggr<<<(NN * 32 + 255) / 256, 256>>>();
        k_node1<<<592, 256>>>(uw1, ub1);
        k_bnfin<<<1, 64>>>(192, 64, 1.0 / NN,
                           updf_g1 + l * 64, updf_be1 + l * 64,
                           updf_g1 + l * 64, updf_be1 + l * 64);
        k_node2<<<592, 256>>>(uw2, ub2);
    }

    k_pool<<<(NN * 16 + 255) / 256, 256>>>(batch);
    k_pred<<<NG, 32>>>(lin_pred_w, lin_pred_b, (float*)d_out);
}